// round 2
// baseline (speedup 1.0000x reference)
#include <cuda_runtime.h>
#include <cstdint>

#define B_ 8
#define N_ 2048
#define K_ 20
#define P_ (B_*N_)      // 16384
#define EPS 1e-5f

// ---------------- scratch (device globals; no runtime allocation) ----------------
__device__ float g_xt0 [P_*3];       // x transposed (B,N,3)
__device__ float g_xcat[P_*512];     // concat of 4 block outputs, point-major (p,512)
__device__ float g_cpart[P_*256];    // per-point ctr contribution (p,O)
__device__ float g_mx[P_*256];       // pre-BN max over valid k   (p,O)
__device__ float g_mn[P_*256];       // pre-BN min over valid k   (p,O)
__device__ float g_y1[P_*1024];      // tail activations, channel-major (o,p)
__device__ float g_y2[P_*512];
__device__ float g_y3[P_*128];
__device__ float g_wd[256*256];      // W[:, :C]
__device__ float g_w2[256*256];      // W[:, C:] - W[:, :C]
__device__ float g_sum[1024];
__device__ float g_sumsq[1024];
__device__ float g_a[1024];
__device__ float g_b2[1024];
__device__ int     g_cnt[P_];
__device__ uint8_t g_ok[P_];
__device__ int g_totvalid;
__device__ int g_okcnt;
__device__ int g_vmode;   // 0=int32, 1=uint8, 2=float32

// ---------------- valid dtype detection + accessor ----------------
__global__ void k_detect(const void* v) {
    // Scan first (B*N*K)/4 32-bit words — in-bounds for all candidate layouts.
    const int nwords = (P_ * K_) / 4;
    const unsigned int* w = (const unsigned int*)v;
    __shared__ int s_not01, s_f32;
    if (threadIdx.x == 0) { s_not01 = 0; s_f32 = 0; }
    __syncthreads();
    int not01 = 0, f32 = 0;
    for (int i = threadIdx.x; i < nwords; i += blockDim.x) {
        unsigned int u = w[i];
        if (u > 1u) not01 = 1;
        if (u == 0x3F800000u) f32 = 1;
    }
    if (not01) atomicOr(&s_not01, 1);
    if (f32)   atomicOr(&s_f32, 1);
    __syncthreads();
    if (threadIdx.x == 0) {
        g_vmode = (!s_not01) ? 0 : (s_f32 ? 2 : 1);
        g_totvalid = 0;
        g_okcnt = 0;
    }
}

__device__ __forceinline__ int valid_at(const void* v, int i) {
    int m = g_vmode;
    if (m == 0) return ((const int*)v)[i] != 0;
    if (m == 1) return ((const uint8_t*)v)[i] != 0;
    return ((const float*)v)[i] != 0.0f;
}

// ---------------- small utility kernels ----------------
__global__ void k_count(const void* __restrict__ valid) {
    int p = blockIdx.x * 256 + threadIdx.x;
    int c = 0;
    #pragma unroll
    for (int k = 0; k < K_; k++) c += valid_at(valid, p * K_ + k);
    g_cnt[p] = c;
    int okf = (c >= 1) ? 1 : 0;
    g_ok[p] = (uint8_t)okf;
    int tot = c, okc = okf;
    for (int d = 16; d; d >>= 1) {
        tot += __shfl_xor_sync(0xffffffffu, tot, d);
        okc += __shfl_xor_sync(0xffffffffu, okc, d);
    }
    if ((threadIdx.x & 31) == 0) {
        atomicAdd(&g_totvalid, tot);
        atomicAdd(&g_okcnt, okc);
    }
}

__global__ void k_transpose(const float* __restrict__ x) {
    int p = blockIdx.x * 256 + threadIdx.x;
    if (p >= P_) return;
    int b = p >> 11, n = p & (N_ - 1);
    #pragma unroll
    for (int c = 0; c < 3; c++)
        g_xt0[p * 3 + c] = x[(b * 3 + c) * N_ + n];
}

__global__ void k_prepw(const float* __restrict__ w, int O, int C) {
    int i = blockIdx.x * 256 + threadIdx.x;
    if (i >= O * C) return;
    int o = i / C, c = i - o * C;
    float wd = w[o * 2 * C + c];
    g_wd[i] = wd;
    g_w2[i] = w[o * 2 * C + C + c] - wd;
}

__global__ void k_zero_stats(int O) {
    int i = blockIdx.x * 256 + threadIdx.x;
    if (i < O) { g_sum[i] = 0.f; g_sumsq[i] = 0.f; }
}

__global__ void k_bn_param(int O, const float* __restrict__ gamma,
                           const float* __restrict__ beta, int use_ok) {
    int o = blockIdx.x * 256 + threadIdx.x;
    if (o >= O) return;
    float cnt = (float)(use_ok ? g_okcnt : g_totvalid);
    float n = fmaxf(cnt, 1.f);
    float s = g_sum[o];
    float mean = s / n;
    float var = (g_sumsq[o] - 2.f * mean * s + mean * mean * cnt) / n;
    float a = gamma[o] * rsqrtf(fmaxf(var, 0.f) + EPS);
    g_a[o] = a;
    g_b2[o] = beta[o] - mean * a;
}

// BN(+lrelu) using pre-BN max/min (monotonicity trick), gated by ok, write into concat slab
__global__ void k_edge_pass2(int O, int off) {
    int i = blockIdx.x * 256 + threadIdx.x;
    if (i >= P_ * O) return;
    int p = i / O, o = i - p * O;
    float a = g_a[o];
    float v = (a >= 0.f) ? g_mx[i] : g_mn[i];
    float h = a * v + g_b2[o];
    h = (h >= 0.f) ? h : 0.2f * h;
    if (g_cnt[p] < 1) h = 0.f;
    g_xcat[p * 512 + off + o] = h;
}

// in-place BN + lrelu on channel-major tensor (o*P_ + p)
__global__ void k_bn_apply(float* __restrict__ Y, int O) {
    int i = blockIdx.x * 256 + threadIdx.x;
    if (i >= P_ * O) return;
    int o = i >> 14;               // P_ = 2^14
    float y = g_a[o] * Y[i] + g_b2[o];
    Y[i] = (y >= 0.f) ? y : 0.2f * y;
}

// ---------------- unified dense GEMM over points ----------------
// Y[p,o] = sum_c W[o,c] * X[p,c] (+bias). 128(O) x 64(P) tile, 256 threads, 8x4 micro-tile.
// OUTM: 0 = point-major Y[p*O+o], 1 = channel-major Y[o*P_+p], 2 = (B,O,N) transposed out
template<bool IN_CH, int OUTM, bool STATS>
__global__ __launch_bounds__(256)
void gemm_pt(const float* __restrict__ X, int ldx, int xoff,
             const float* __restrict__ W, int O, int C,
             const float* __restrict__ bias, float* __restrict__ Y) {
    const int tid = threadIdx.x, tx = tid & 15, ty = tid >> 4;
    const int p0 = blockIdx.x * 64, o0 = blockIdx.y * 128;
    __shared__ float sW[128 * 17];
    __shared__ float sX[16 * 64];
    float acc[8][4];
    #pragma unroll
    for (int r = 0; r < 8; r++)
        #pragma unroll
        for (int j = 0; j < 4; j++) acc[r][j] = 0.f;

    for (int c0 = 0; c0 < C; c0 += 16) {
        #pragma unroll
        for (int e = tid; e < 128 * 16; e += 256) {
            int ol = e >> 4, cc = e & 15;
            int o = o0 + ol, c = c0 + cc;
            sW[ol * 17 + cc] = (o < O && c < C) ? W[o * C + c] : 0.f;
        }
        if (IN_CH) {
            #pragma unroll
            for (int e = tid; e < 16 * 64; e += 256) {
                int cc = e >> 6, col = e & 63;
                int c = c0 + cc;
                sX[cc * 64 + col] = (c < C) ? X[c * P_ + p0 + col] : 0.f;
            }
        } else {
            #pragma unroll
            for (int e = tid; e < 16 * 64; e += 256) {
                int col = e >> 4, cc = e & 15;
                int c = c0 + cc;
                sX[cc * 64 + col] = (c < C) ? X[(p0 + col) * ldx + xoff + c] : 0.f;
            }
        }
        __syncthreads();
        #pragma unroll
        for (int cc = 0; cc < 16; cc++) {
            float fv[4], wv[8];
            #pragma unroll
            for (int j = 0; j < 4; j++) fv[j] = sX[cc * 64 + tx + 16 * j];
            #pragma unroll
            for (int r = 0; r < 8; r++) wv[r] = sW[(ty + 16 * r) * 17 + cc];
            #pragma unroll
            for (int r = 0; r < 8; r++)
                #pragma unroll
                for (int j = 0; j < 4; j++) acc[r][j] += wv[r] * fv[j];
        }
        __syncthreads();
    }

    float bs[8];
    #pragma unroll
    for (int r = 0; r < 8; r++) {
        int o = o0 + ty + 16 * r;
        bs[r] = (bias != nullptr && o < O) ? bias[o] : 0.f;
    }
    bool okf[4];
    if (STATS) {
        #pragma unroll
        for (int j = 0; j < 4; j++) okf[j] = (g_ok[p0 + tx + 16 * j] != 0);
    }
    #pragma unroll
    for (int r = 0; r < 8; r++) {
        int o = o0 + ty + 16 * r;
        float s = 0.f, s2 = 0.f;
        #pragma unroll
        for (int j = 0; j < 4; j++) {
            int col = tx + 16 * j, p = p0 + col;
            float y = acc[r][j] + bs[r];
            if (STATS && okf[j]) { s += y; s2 += y * y; }
            if (o < O) {
                if (OUTM == 0) Y[p * O + o] = y;
                else if (OUTM == 1) Y[o * P_ + p] = y;
                else {
                    int b = p >> 11, n = p & (N_ - 1);
                    Y[(b * O + o) * N_ + n] = y;
                }
            }
        }
        if (STATS) {
            for (int d = 1; d < 16; d <<= 1) {
                s  += __shfl_xor_sync(0xffffffffu, s,  d);
                s2 += __shfl_xor_sync(0xffffffffu, s2, d);
            }
            if (tx == 0 && o < O) {
                atomicAdd(&g_sum[o], s);
                atomicAdd(&g_sumsq[o], s2);
            }
        }
    }
}

// ---------------- gather edge GEMM ----------------
// For 4 points x 20 neighbors (80 columns): h[o,col] = sum_c Wd[o,c]*X[src(col),c] + cpart[p,o]
// Epilogue reduces masked per-channel sum/sumsq and per-(o,point) max/min over valid k.
__global__ __launch_bounds__(256)
void edge_gemm(const float* __restrict__ Xin, int ldx, int xoff, int C, int O,
               const int* __restrict__ idx, const void* __restrict__ valid) {
    const int tid = threadIdx.x, tx = tid & 15, ty = tid >> 4;
    const int p0 = blockIdx.x * 4, o0 = blockIdx.y * 128;
    __shared__ float sW[128 * 17];
    __shared__ float sF[16 * 80];
    __shared__ int sSrc[80];
    __shared__ uint8_t sVal[80];
    __shared__ float sC[4 * 128];

    if (tid < 80) {
        int pt = tid / 20, k = tid - pt * 20;
        int p = p0 + pt, b = p >> 11;
        sSrc[tid] = (b << 11) + idx[p * K_ + k];
        sVal[tid] = (uint8_t)valid_at(valid, p * K_ + k);
    }
    for (int e = tid; e < 512; e += 256) {
        int pt = e >> 7, ol = e & 127;
        int o = o0 + ol;
        sC[e] = (o < O) ? g_cpart[(p0 + pt) * O + o] : 0.f;
    }
    __syncthreads();

    float acc[8][5];
    #pragma unroll
    for (int r = 0; r < 8; r++)
        #pragma unroll
        for (int j = 0; j < 5; j++) acc[r][j] = 0.f;

    for (int c0 = 0; c0 < C; c0 += 16) {
        #pragma unroll
        for (int e = tid; e < 128 * 16; e += 256) {
            int ol = e >> 4, cc = e & 15;
            int o = o0 + ol, c = c0 + cc;
            sW[ol * 17 + cc] = (o < O && c < C) ? g_wd[o * C + c] : 0.f;
        }
        #pragma unroll
        for (int e = tid; e < 16 * 80; e += 256) {
            int col = e >> 4, cc = e & 15;
            int c = c0 + cc;
            sF[cc * 80 + col] = (c < C) ? Xin[sSrc[col] * ldx + xoff + c] : 0.f;
        }
        __syncthreads();
        #pragma unroll
        for (int cc = 0; cc < 16; cc++) {
            float fv[5], wv[8];
            #pragma unroll
            for (int j = 0; j < 5; j++) fv[j] = sF[cc * 80 + tx * 5 + j];
            #pragma unroll
            for (int r = 0; r < 8; r++) wv[r] = sW[(ty + 16 * r) * 17 + cc];
            #pragma unroll
            for (int r = 0; r < 8; r++)
                #pragma unroll
                for (int j = 0; j < 5; j++) acc[r][j] += wv[r] * fv[j];
        }
        __syncthreads();
    }

    // epilogue: add cpart, masked stats + per-point max/min
    const int myPt = tx >> 2;          // tx*5..tx*5+4 all lie in point tx/4
    const int cbase = tx * 5;
    #pragma unroll
    for (int r = 0; r < 8; r++) {
        int ol = ty + 16 * r, o = o0 + ol;
        float cp = sC[myPt * 128 + ol];
        float s = 0.f, s2 = 0.f;
        float vmx = -INFINITY, vmn = INFINITY;
        #pragma unroll
        for (int j = 0; j < 5; j++) {
            int col = cbase + j;
            float h = acc[r][j] + cp;
            if (sVal[col]) {
                s += h; s2 += h * h;
                vmx = fmaxf(vmx, h);
                vmn = fminf(vmn, h);
            }
        }
        for (int d = 1; d < 16; d <<= 1) {
            s  += __shfl_xor_sync(0xffffffffu, s,  d);
            s2 += __shfl_xor_sync(0xffffffffu, s2, d);
        }
        for (int d = 1; d < 4; d <<= 1) {
            vmx = fmaxf(vmx, __shfl_xor_sync(0xffffffffu, vmx, d));
            vmn = fminf(vmn, __shfl_xor_sync(0xffffffffu, vmn, d));
        }
        if (o < O) {
            if (tx == 0) {
                atomicAdd(&g_sum[o], s);
                atomicAdd(&g_sumsq[o], s2);
            }
            if ((tx & 3) == 0) {
                int p = p0 + myPt;
                g_mx[p * O + o] = vmx;
                g_mn[p * O + o] = vmn;
            }
        }
    }
}

// ---------------- host orchestration ----------------
extern "C" void kernel_launch(void* const* d_in, const int* in_sizes, int n_in,
                              void* d_out, int out_size) {
    const float*   x      = (const float*)d_in[0];
    const int*     idx    = (const int*)d_in[1];
    const void*    valid  = (const void*)d_in[2];
    const float* enc_w[4] = {(const float*)d_in[3], (const float*)d_in[6],
                             (const float*)d_in[9], (const float*)d_in[12]};
    const float* enc_g[4] = {(const float*)d_in[4], (const float*)d_in[7],
                             (const float*)d_in[10], (const float*)d_in[13]};
    const float* enc_bb[4]= {(const float*)d_in[5], (const float*)d_in[8],
                             (const float*)d_in[11], (const float*)d_in[14]};
    const float* last_w   = (const float*)d_in[15];
    const float* last_g   = (const float*)d_in[16];
    const float* last_b   = (const float*)d_in[17];
    const float* emb_w1   = (const float*)d_in[18];
    const float* emb_bias1= (const float*)d_in[19];
    const float* emb_g1   = (const float*)d_in[20];
    const float* emb_b1   = (const float*)d_in[21];
    const float* emb_w2   = (const float*)d_in[22];
    const float* emb_bias2= (const float*)d_in[23];
    const float* emb_g2   = (const float*)d_in[24];
    const float* emb_b2   = (const float*)d_in[25];
    const float* out_w    = (const float*)d_in[26];
    const float* out_bias = (const float*)d_in[27];

    float *xt0p, *xcatp, *cpartp, *y1p, *y2p, *y3p;
    cudaGetSymbolAddress((void**)&xt0p,  g_xt0);
    cudaGetSymbolAddress((void**)&xcatp, g_xcat);
    cudaGetSymbolAddress((void**)&cpartp,g_cpart);
    cudaGetSymbolAddress((void**)&y1p,   g_y1);
    cudaGetSymbolAddress((void**)&y2p,   g_y2);
    cudaGetSymbolAddress((void**)&y3p,   g_y3);

    k_detect<<<1, 1024>>>(valid);
    k_count<<<P_ / 256, 256>>>(valid);
    k_transpose<<<P_ / 256, 256>>>(x);

    // edge blocks: (C_in, O, in_off, out_off)
    const int blkC[4]   = {3, 64, 64, 128};
    const int blkO[4]   = {64, 64, 128, 256};
    const int inOff[4]  = {0, 0, 64, 128};
    const int outOff[4] = {0, 64, 128, 256};

    for (int i = 0; i < 4; i++) {
        int C = blkC[i], O = blkO[i];
        const float* xin = (i == 0) ? xt0p : xcatp;
        int ldx = (i == 0) ? 3 : 512;
        int xoff = inOff[i];
        int otiles = (O + 127) / 128;

        k_prepw<<<(O * C + 255) / 256, 256>>>(enc_w[i], O, C);
        // cpart = (Wc - Wd) * ctr  (point-major output)
        {
            float* W2p; cudaGetSymbolAddress((void**)&W2p, g_w2);
            dim3 grid(P_ / 64, otiles);
            gemm_pt<false, 0, false><<<grid, 256>>>(xin, ldx, xoff, W2p, O, C,
                                                    nullptr, cpartp);
        }
        k_zero_stats<<<(O + 255) / 256, 256>>>(O);
        {
            dim3 grid(P_ / 4, otiles);
            edge_gemm<<<grid, 256>>>(xin, ldx, xoff, C, O, idx, valid);
        }
        k_bn_param<<<(O + 255) / 256, 256>>>(O, enc_g[i], enc_bb[i], 0);
        k_edge_pass2<<<(P_ * O + 255) / 256, 256>>>(O, outOff[i]);
    }

    // tail: last (512->1024), emb1 (1024->512), emb2 (512->128), out (128->32)
    k_zero_stats<<<4, 256>>>(1024);
    gemm_pt<false, 1, true><<<dim3(P_ / 64, 8), 256>>>(xcatp, 512, 0, last_w,
                                                       1024, 512, nullptr, y1p);
    k_bn_param<<<4, 256>>>(1024, last_g, last_b, 1);
    k_bn_apply<<<(P_ * 1024 + 255) / 256, 256>>>(y1p, 1024);

    k_zero_stats<<<2, 256>>>(512);
    gemm_pt<true, 1, true><<<dim3(P_ / 64, 4), 256>>>(y1p, 0, 0, emb_w1,
                                                      512, 1024, emb_bias1, y2p);
    k_bn_param<<<2, 256>>>(512, emb_g1, emb_b1, 1);
    k_bn_apply<<<(P_ * 512 + 255) / 256, 256>>>(y2p, 512);

    k_zero_stats<<<1, 256>>>(128);
    gemm_pt<true, 1, true><<<dim3(P_ / 64, 1), 256>>>(y2p, 0, 0, emb_w2,
                                                      128, 512, emb_bias2, y3p);
    k_bn_param<<<1, 256>>>(128, emb_g2, emb_b2, 1);
    k_bn_apply<<<(P_ * 128 + 255) / 256, 256>>>(y3p, 128);

    gemm_pt<true, 2, false><<<dim3(P_ / 64, 1), 256>>>(y3p, 0, 0, out_w,
                                                       32, 128, out_bias,
                                                       (float*)d_out);
}

// round 4
// speedup vs baseline: 1.9415x; 1.9415x over previous
#include <cuda_runtime.h>
#include <cuda_bf16.h>
#include <cstdint>

#define B_ 8
#define N_ 2048
#define K_ 20
#define P_ (B_*N_)      // 16384
#define EPS 1e-5f

// ---------------- scratch (device globals; no runtime allocation) ----------------
__device__ __align__(128) float g_xt0 [P_*3];
__device__ __align__(128) float g_xcat[P_*512];         // concat fp32, point-major
__device__ __align__(128) __nv_bfloat16 g_xch[P_*512];  // concat bf16 hi
__device__ __align__(128) __nv_bfloat16 g_xcl[P_*512];  // concat bf16 lo
__device__ __align__(128) float g_cpart[P_*256];
__device__ __align__(128) float g_mx[P_*256];
__device__ __align__(128) float g_mn[P_*256];
__device__ __align__(128) float g_y1[P_*1024];
__device__ __align__(128) float g_y2[P_*512];
__device__ __align__(128) float g_y3[P_*128];
__device__ __align__(128) float g_y3a[P_*128];
__device__ __align__(128) __nv_bfloat16 g_y1h[P_*1024];
__device__ __align__(128) __nv_bfloat16 g_y1l[P_*1024];
__device__ __align__(128) __nv_bfloat16 g_y2h[P_*512];
__device__ __align__(128) __nv_bfloat16 g_y2l[P_*512];
__device__ __align__(128) float g_wd[256*256];
__device__ __align__(128) float g_w2[256*256];
__device__ __align__(128) __nv_bfloat16 g_wth[1024*1024];
__device__ __align__(128) __nv_bfloat16 g_wtl[1024*1024];
__device__ float g_sum[1024];
__device__ float g_sumsq[1024];
__device__ float g_a[1024];
__device__ float g_b2[1024];
__device__ int     g_cnt[P_];
__device__ uint8_t g_ok[P_];
__device__ int g_totvalid;
__device__ int g_okcnt;
__device__ int g_vmode;   // 0=int32, 1=uint8, 2=float32

// ---------------- warp-MMA helpers (sm_80+ PTX, legal on plain sm_103) ----------------
#define SWZ(x) ((x) ^ (((x) >> 3) & 0x70))
__device__ __forceinline__ uint32_t s2u(const void* p) {
    uint32_t a;
    asm("{ .reg .u64 t; cvta.to.shared.u64 t, %1; cvt.u32.u64 %0, t; }" : "=r"(a) : "l"(p));
    return a;
}
__device__ __forceinline__ void ldsm4(uint32_t* r, uint32_t a) {
    asm volatile("ldmatrix.sync.aligned.m8n8.x4.shared.b16 {%0,%1,%2,%3}, [%4];"
                 : "=r"(r[0]), "=r"(r[1]), "=r"(r[2]), "=r"(r[3]) : "r"(a));
}
__device__ __forceinline__ void ldsm2(uint32_t* r, uint32_t a) {
    asm volatile("ldmatrix.sync.aligned.m8n8.x2.shared.b16 {%0,%1}, [%2];"
                 : "=r"(r[0]), "=r"(r[1]) : "r"(a));
}
__device__ __forceinline__ void mma16816(float* c, const uint32_t* a, const uint32_t* b) {
    asm volatile("mma.sync.aligned.m16n8k16.row.col.f32.bf16.bf16.f32 "
                 "{%0,%1,%2,%3},{%4,%5,%6,%7},{%8,%9},{%0,%1,%2,%3};"
                 : "+f"(c[0]), "+f"(c[1]), "+f"(c[2]), "+f"(c[3])
                 : "r"(a[0]), "r"(a[1]), "r"(a[2]), "r"(a[3]), "r"(b[0]), "r"(b[1]));
}

// ---------------- valid dtype detection + accessor ----------------
__global__ void k_detect(const void* v) {
    const int nwords = (P_ * K_) / 4;
    const unsigned int* w = (const unsigned int*)v;
    __shared__ int s_not01, s_f32;
    if (threadIdx.x == 0) { s_not01 = 0; s_f32 = 0; }
    __syncthreads();
    int not01 = 0, f32 = 0;
    for (int i = threadIdx.x; i < nwords; i += blockDim.x) {
        unsigned int u = w[i];
        if (u > 1u) not01 = 1;
        if (u == 0x3F800000u) f32 = 1;
    }
    if (not01) atomicOr(&s_not01, 1);
    if (f32)   atomicOr(&s_f32, 1);
    __syncthreads();
    if (threadIdx.x == 0) {
        g_vmode = (!s_not01) ? 0 : (s_f32 ? 2 : 1);
        g_totvalid = 0;
        g_okcnt = 0;
    }
}
__device__ __forceinline__ int valid_at(const void* v, int i) {
    int m = g_vmode;
    if (m == 0) return ((const int*)v)[i] != 0;
    if (m == 1) return ((const uint8_t*)v)[i] != 0;
    return ((const float*)v)[i] != 0.0f;
}

// ---------------- small utility kernels ----------------
__global__ void k_count(const void* __restrict__ valid) {
    int p = blockIdx.x * 256 + threadIdx.x;
    int c = 0;
    #pragma unroll
    for (int k = 0; k < K_; k++) c += valid_at(valid, p * K_ + k);
    g_cnt[p] = c;
    int okf = (c >= 1) ? 1 : 0;
    g_ok[p] = (uint8_t)okf;
    int tot = c, okc = okf;
    for (int d = 16; d; d >>= 1) {
        tot += __shfl_xor_sync(0xffffffffu, tot, d);
        okc += __shfl_xor_sync(0xffffffffu, okc, d);
    }
    if ((threadIdx.x & 31) == 0) {
        atomicAdd(&g_totvalid, tot);
        atomicAdd(&g_okcnt, okc);
    }
}

__global__ void k_transpose(const float* __restrict__ x) {
    int p = blockIdx.x * 256 + threadIdx.x;
    if (p >= P_) return;
    int b = p >> 11, n = p & (N_ - 1);
    #pragma unroll
    for (int c = 0; c < 3; c++)
        g_xt0[p * 3 + c] = x[(b * 3 + c) * N_ + n];
}

__global__ void k_prepw(const float* __restrict__ w, int O, int C) {
    int i = blockIdx.x * 256 + threadIdx.x;
    if (i >= O * C) return;
    int o = i / C, c = i - o * C;
    float wd = w[o * 2 * C + c];
    g_wd[i] = wd;
    g_w2[i] = w[o * 2 * C + C + c] - wd;
}

// split fp32 weights -> bf16 hi/lo, rows >= O zero-padded up to Opad
__global__ void k_prepw_bf16(const float* __restrict__ src, int O, int Opad, int C) {
    int i = blockIdx.x * 256 + threadIdx.x;
    if (i >= Opad * C) return;
    int o = i / C;
    float v = (o < O) ? src[i] : 0.f;
    __nv_bfloat16 h = __float2bfloat16(v);
    g_wth[i] = h;
    g_wtl[i] = __float2bfloat16(v - __bfloat162float(h));
}

__global__ void k_zero_stats(int O) {
    int i = blockIdx.x * 256 + threadIdx.x;
    if (i < O) { g_sum[i] = 0.f; g_sumsq[i] = 0.f; }
}

__global__ void k_bn_param(int O, const float* __restrict__ gamma,
                           const float* __restrict__ beta, int use_ok) {
    int o = blockIdx.x * 256 + threadIdx.x;
    if (o >= O) return;
    float cnt = (float)(use_ok ? g_okcnt : g_totvalid);
    float n = fmaxf(cnt, 1.f);
    float s = g_sum[o];
    float mean = s / n;
    float var = (g_sumsq[o] - 2.f * mean * s + mean * mean * cnt) / n;
    float a = gamma[o] * rsqrtf(fmaxf(var, 0.f) + EPS);
    g_a[o] = a;
    g_b2[o] = beta[o] - mean * a;
}

// BN(+lrelu) via pre-BN max/min, ok-gated; writes fp32 + bf16 hi/lo concat slabs
__global__ void k_edge_pass2(int O, int off) {
    int i = blockIdx.x * 256 + threadIdx.x;
    if (i >= P_ * O) return;
    int p = i / O, o = i - p * O;
    float a = g_a[o];
    float v = (a >= 0.f) ? g_mx[i] : g_mn[i];
    float h = a * v + g_b2[o];
    h = (h >= 0.f) ? h : 0.2f * h;
    if (g_cnt[p] < 1) h = 0.f;
    int di = p * 512 + off + o;
    g_xcat[di] = h;
    __nv_bfloat16 hh = __float2bfloat16(h);
    g_xch[di] = hh;
    g_xcl[di] = __float2bfloat16(h - __bfloat162float(hh));
}

// apply BN+lrelu to raw point-major fp32, emit bf16 hi/lo (+ optional fp32)
__global__ void k_convert(const float* __restrict__ Y, int O,
                          __nv_bfloat16* __restrict__ H, __nv_bfloat16* __restrict__ L,
                          float* __restrict__ F) {
    int i = blockIdx.x * 256 + threadIdx.x;
    if (i >= P_ * O) return;
    int o = i & (O - 1);
    float y = g_a[o] * Y[i] + g_b2[o];
    y = (y >= 0.f) ? y : 0.2f * y;
    __nv_bfloat16 h = __float2bfloat16(y);
    H[i] = h;
    L[i] = __float2bfloat16(y - __bfloat162float(h));
    if (F) F[i] = y;
}

// ---------------- scalar GEMM (cpart + final tiny layer) ----------------
template<int OUTM, bool STATS>
__global__ __launch_bounds__(256)
void gemm_pt(const float* __restrict__ X, int ldx, int xoff,
             const float* __restrict__ W, int O, int C,
             const float* __restrict__ bias, float* __restrict__ Y) {
    const int tid = threadIdx.x, tx = tid & 15, ty = tid >> 4;
    const int p0 = blockIdx.x * 64, o0 = blockIdx.y * 128;
    __shared__ float sW[128 * 17];
    __shared__ float sX[16 * 64];
    float acc[8][4];
    #pragma unroll
    for (int r = 0; r < 8; r++)
        #pragma unroll
        for (int j = 0; j < 4; j++) acc[r][j] = 0.f;

    for (int c0 = 0; c0 < C; c0 += 16) {
        #pragma unroll
        for (int e = tid; e < 128 * 16; e += 256) {
            int ol = e >> 4, cc = e & 15;
            int o = o0 + ol, c = c0 + cc;
            sW[ol * 17 + cc] = (o < O && c < C) ? W[o * C + c] : 0.f;
        }
        #pragma unroll
        for (int e = tid; e < 16 * 64; e += 256) {
            int col = e >> 4, cc = e & 15;
            int c = c0 + cc;
            sX[cc * 64 + col] = (c < C) ? X[(p0 + col) * ldx + xoff + c] : 0.f;
        }
        __syncthreads();
        #pragma unroll
        for (int cc = 0; cc < 16; cc++) {
            float fv[4], wv[8];
            #pragma unroll
            for (int j = 0; j < 4; j++) fv[j] = sX[cc * 64 + tx + 16 * j];
            #pragma unroll
            for (int r = 0; r < 8; r++) wv[r] = sW[(ty + 16 * r) * 17 + cc];
            #pragma unroll
            for (int r = 0; r < 8; r++)
                #pragma unroll
                for (int j = 0; j < 4; j++) acc[r][j] += wv[r] * fv[j];
        }
        __syncthreads();
    }

    float bs[8];
    #pragma unroll
    for (int r = 0; r < 8; r++) {
        int o = o0 + ty + 16 * r;
        bs[r] = (bias != nullptr && o < O) ? bias[o] : 0.f;
    }
    bool okf[4];
    if (STATS) {
        #pragma unroll
        for (int j = 0; j < 4; j++) okf[j] = (g_ok[p0 + tx + 16 * j] != 0);
    }
    #pragma unroll
    for (int r = 0; r < 8; r++) {
        int o = o0 + ty + 16 * r;
        float s = 0.f, s2 = 0.f;
        #pragma unroll
        for (int j = 0; j < 4; j++) {
            int col = tx + 16 * j, p = p0 + col;
            float y = acc[r][j] + bs[r];
            if (STATS && okf[j]) { s += y; s2 += y * y; }
            if (o < O) {
                if (OUTM == 0) Y[p * O + o] = y;
                else {
                    int b = p >> 11, n = p & (N_ - 1);
                    Y[(b * O + o) * N_ + n] = y;
                }
            }
        }
        if (STATS) {
            for (int d = 1; d < 16; d <<= 1) {
                s  += __shfl_xor_sync(0xffffffffu, s,  d);
                s2 += __shfl_xor_sync(0xffffffffu, s2, d);
            }
            if (tx == 0 && o < O) {
                atomicAdd(&g_sum[o], s);
                atomicAdd(&g_sumsq[o], s2);
            }
        }
    }
}

// ---------------- scalar gather edge GEMM (block 1, C=3) ----------------
__global__ __launch_bounds__(256)
void edge_gemm(const float* __restrict__ Xin, int ldx, int xoff, int C, int O,
               const int* __restrict__ idx, const void* __restrict__ valid) {
    const int tid = threadIdx.x, tx = tid & 15, ty = tid >> 4;
    const int p0 = blockIdx.x * 4, o0 = blockIdx.y * 128;
    __shared__ float sW[128 * 17];
    __shared__ float sF[16 * 80];
    __shared__ int sSrc[80];
    __shared__ uint8_t sVal[80];
    __shared__ float sC[4 * 128];

    if (tid < 80) {
        int pt = tid / 20, k = tid - pt * 20;
        int p = p0 + pt, b = p >> 11;
        sSrc[tid] = (b << 11) + idx[p * K_ + k];
        sVal[tid] = (uint8_t)valid_at(valid, p * K_ + k);
    }
    for (int e = tid; e < 512; e += 256) {
        int pt = e >> 7, ol = e & 127;
        int o = o0 + ol;
        sC[e] = (o < O) ? g_cpart[(p0 + pt) * O + o] : 0.f;
    }
    __syncthreads();

    float acc[8][5];
    #pragma unroll
    for (int r = 0; r < 8; r++)
        #pragma unroll
        for (int j = 0; j < 5; j++) acc[r][j] = 0.f;

    for (int c0 = 0; c0 < C; c0 += 16) {
        #pragma unroll
        for (int e = tid; e < 128 * 16; e += 256) {
            int ol = e >> 4, cc = e & 15;
            int o = o0 + ol, c = c0 + cc;
            sW[ol * 17 + cc] = (o < O && c < C) ? g_wd[o * C + c] : 0.f;
        }
        #pragma unroll
        for (int e = tid; e < 16 * 80; e += 256) {
            int col = e >> 4, cc = e & 15;
            int c = c0 + cc;
            sF[cc * 80 + col] = (c < C) ? Xin[sSrc[col] * ldx + xoff + c] : 0.f;
        }
        __syncthreads();
        #pragma unroll
        for (int cc = 0; cc < 16; cc++) {
            float fv[5], wv[8];
            #pragma unroll
            for (int j = 0; j < 5; j++) fv[j] = sF[cc * 80 + tx * 5 + j];
            #pragma unroll
            for (int r = 0; r < 8; r++) wv[r] = sW[(ty + 16 * r) * 17 + cc];
            #pragma unroll
            for (int r = 0; r < 8; r++)
                #pragma unroll
                for (int j = 0; j < 5; j++) acc[r][j] += wv[r] * fv[j];
        }
        __syncthreads();
    }

    const int myPt = tx >> 2;
    const int cbase = tx * 5;
    #pragma unroll
    for (int r = 0; r < 8; r++) {
        int ol = ty + 16 * r, o = o0 + ol;
        float cp = sC[myPt * 128 + ol];
        float s = 0.f, s2 = 0.f;
        float vmx = -INFINITY, vmn = INFINITY;
        #pragma unroll
        for (int j = 0; j < 5; j++) {
            int col = cbase + j;
            float h = acc[r][j] + cp;
            if (sVal[col]) {
                s += h; s2 += h * h;
                vmx = fmaxf(vmx, h);
                vmn = fminf(vmn, h);
            }
        }
        for (int d = 1; d < 16; d <<= 1) {
            s  += __shfl_xor_sync(0xffffffffu, s,  d);
            s2 += __shfl_xor_sync(0xffffffffu, s2, d);
        }
        for (int d = 1; d < 4; d <<= 1) {
            vmx = fmaxf(vmx, __shfl_xor_sync(0xffffffffu, vmx, d));
            vmn = fminf(vmn, __shfl_xor_sync(0xffffffffu, vmn, d));
        }
        if (o < O) {
            if (tx == 0) {
                atomicAdd(&g_sum[o], s);
                atomicAdd(&g_sumsq[o], s2);
            }
            if ((tx & 3) == 0) {
                int p = p0 + myPt;
                g_mx[p * O + o] = vmx;
                g_mn[p * O + o] = vmn;
            }
        }
    }
}

// ---------------- warp-MMA tail GEMM: block 128(o) x 128(p), bf16-split x3 ----------------
// smem regions: Ahi[0,16K) Alo[16K,32K) Bhi[32K,48K) Blo[48K,64K); epilogue fp32 [128p][132o]
__global__ __launch_bounds__(256, 1)
void tgemm_tail(const __nv_bfloat16* __restrict__ Xhi, const __nv_bfloat16* __restrict__ Xlo,
                int ldx, int O, int C, const float* __restrict__ bias,
                float* __restrict__ Y) {
    extern __shared__ __align__(1024) unsigned char dsm[];
    __shared__ uint8_t sOk[128];
    const int tid = threadIdx.x, lane = tid & 31, wid = tid >> 5;
    const int wm = wid >> 2, wn = wid & 3;
    const int p0 = blockIdx.x * 128, o0 = blockIdx.y * 128;
    const uint32_t sb = s2u(dsm);
    if (tid < 128) sOk[tid] = g_ok[p0 + tid];

    // per-lane ldmatrix base addresses
    const int lr = lane & 7, g = lane >> 3;
    const uint32_t xorv = (uint32_t)lr * 16;
    const uint32_t aRow = (uint32_t)(wm * 64 + (g & 1) * 8 + lr) * 128;
    const uint32_t aSeg = (uint32_t)(g >> 1) * 16;
    const uint32_t bRow = (uint32_t)(wn * 32 + lr) * 128;
    const uint32_t bSeg = (uint32_t)(g & 1) * 16;

    float acc[4][4][4];
    #pragma unroll
    for (int mi = 0; mi < 4; mi++)
        #pragma unroll
        for (int ni = 0; ni < 4; ni++)
            #pragma unroll
            for (int j = 0; j < 4; j++) acc[mi][ni][j] = 0.f;

    const int nch = C >> 6;
    for (int ch = 0; ch < nch; ch++) {
        const int c0 = ch << 6;
        #pragma unroll
        for (int e = tid; e < 1024; e += 256) {
            int row = e >> 3, q = e & 7;
            uint32_t dst = SWZ((uint32_t)(row * 128 + q * 16));
            *(uint4*)(dsm + dst)         = ((const uint4*)(g_wth + (size_t)(o0 + row) * C + c0))[q];
            *(uint4*)(dsm + 16384 + dst) = ((const uint4*)(g_wtl + (size_t)(o0 + row) * C + c0))[q];
            *(uint4*)(dsm + 32768 + dst) = ((const uint4*)(Xhi + (size_t)(p0 + row) * ldx + c0))[q];
            *(uint4*)(dsm + 49152 + dst) = ((const uint4*)(Xlo + (size_t)(p0 + row) * ldx + c0))[q];
        }
        __syncthreads();
        #pragma unroll
        for (int s = 0; s < 4; s++) {
            const uint32_t ofsA = ((uint32_t)(s * 32) + aSeg) ^ xorv;
            const uint32_t ofsB = ((uint32_t)(s * 32) + bSeg) ^ xorv;
            uint32_t ah[4][4], al[4][4], bh[4][2], bl[4][2];
            #pragma unroll
            for (int mi = 0; mi < 4; mi++) {
                ldsm4(ah[mi], sb + aRow + mi * 2048 + ofsA);
                ldsm4(al[mi], sb + 16384 + aRow + mi * 2048 + ofsA);
            }
            #pragma unroll
            for (int ni = 0; ni < 4; ni++) {
                ldsm2(bh[ni], sb + 32768 + bRow + ni * 1024 + ofsB);
                ldsm2(bl[ni], sb + 49152 + bRow + ni * 1024 + ofsB);
            }
            #pragma unroll
            for (int mi = 0; mi < 4; mi++)
                #pragma unroll
                for (int ni = 0; ni < 4; ni++) {
                    mma16816(acc[mi][ni], ah[mi], bh[ni]);
                    mma16816(acc[mi][ni], ah[mi], bl[ni]);
                    mma16816(acc[mi][ni], al[mi], bh[ni]);
                }
        }
        __syncthreads();
    }

    // epilogue: bias + masked stats + smem transpose + coalesced store
    const int lrow = lane >> 2, lcol2 = (lane & 3) * 2;
    float bias_r[4][2];
    #pragma unroll
    for (int mi = 0; mi < 4; mi++)
        #pragma unroll
        for (int h = 0; h < 2; h++) {
            int o = o0 + wm * 64 + mi * 16 + h * 8 + lrow;
            bias_r[mi][h] = (bias != nullptr) ? bias[o] : 0.f;
        }
    float st[4][2], st2[4][2];
    #pragma unroll
    for (int mi = 0; mi < 4; mi++)
        #pragma unroll
        for (int h = 0; h < 2; h++) { st[mi][h] = 0.f; st2[mi][h] = 0.f; }

    float* sT = (float*)dsm;   // [128][132]
    #pragma unroll
    for (int mi = 0; mi < 4; mi++) {
        const int ro = wm * 64 + mi * 16 + lrow;
        #pragma unroll
        for (int ni = 0; ni < 4; ni++) {
            const int cp0 = wn * 32 + ni * 8 + lcol2;
            float y00 = acc[mi][ni][0] + bias_r[mi][0];
            float y01 = acc[mi][ni][1] + bias_r[mi][0];
            float y10 = acc[mi][ni][2] + bias_r[mi][1];
            float y11 = acc[mi][ni][3] + bias_r[mi][1];
            if (sOk[cp0])     { st[mi][0] += y00; st2[mi][0] += y00 * y00;
                                st[mi][1] += y10; st2[mi][1] += y10 * y10; }
            if (sOk[cp0 + 1]) { st[mi][0] += y01; st2[mi][0] += y01 * y01;
                                st[mi][1] += y11; st2[mi][1] += y11 * y11; }
            sT[cp0 * 132 + ro]           = y00;
            sT[(cp0 + 1) * 132 + ro]     = y01;
            sT[cp0 * 132 + ro + 8]       = y10;
            sT[(cp0 + 1) * 132 + ro + 8] = y11;
        }
    }
    #pragma unroll
    for (int mi = 0; mi < 4; mi++)
        #pragma unroll
        for (int h = 0; h < 2; h++) {
            float v = st[mi][h], v2 = st2[mi][h];
            v  += __shfl_xor_sync(0xffffffffu, v, 1);
            v  += __shfl_xor_sync(0xffffffffu, v, 2);
            v2 += __shfl_xor_sync(0xffffffffu, v2, 1);
            v2 += __shfl_xor_sync(0xffffffffu, v2, 2);
            if ((lane & 3) == 0) {
                int o = o0 + wm * 64 + mi * 16 + h * 8 + lrow;
                atomicAdd(&g_sum[o], v);
                atomicAdd(&g_sumsq[o], v2);
            }
        }
    __syncthreads();
    {
        int p = tid >> 1, hf = tid & 1;
        const float4* src = (const float4*)(sT + p * 132 + hf * 64);
        float4* dst = (float4*)(Y + (size_t)(p0 + p) * O + o0 + hf * 64);
        #pragma unroll
        for (int i = 0; i < 16; i++) dst[i] = src[i];
    }
}

// ---------------- warp-MMA edge GEMM: block 128(o) x 160(8 pts x 20 k), gathered B ----------------
// smem: Ahi[0,16K) Alo[16K,32K) Bhi[32K,52K) Blo[52K,72K)
__global__ __launch_bounds__(256, 1)
void tgemm_edge(int xoff, int C, int O,
                const int* __restrict__ idx, const void* __restrict__ valid) {
    extern __shared__ __align__(1024) unsigned char dsm[];
    __shared__ int sSrc[160];
    __shared__ uint8_t sVal[160];
    const int tid = threadIdx.x, lane = tid & 31, wid = tid >> 5;
    const int wm = wid >> 2, wn = wid & 3;
    const int p0 = blockIdx.x * 8, o0 = blockIdx.y * 128;
    const uint32_t sb = s2u(dsm);

    if (tid < 160) {
        int p = p0 + tid / 20, k = tid % 20;
        int b = p >> 11;
        sSrc[tid] = (b << 11) + idx[p * K_ + k];
        sVal[tid] = (uint8_t)valid_at(valid, p * K_ + k);
    }
    __syncthreads();

    const int lr = lane & 7, g = lane >> 3;
    const uint32_t xorv = (uint32_t)lr * 16;
    const uint32_t aRow = (uint32_t)(wm * 64 + (g & 1) * 8 + lr) * 128;
    const uint32_t aSeg = (uint32_t)(g >> 1) * 16;
    const uint32_t bRow = (uint32_t)(wn * 40 + lr) * 128;
    const uint32_t bSeg = (uint32_t)(g & 1) * 16;

    float acc[4][5][4];
    #pragma unroll
    for (int mi = 0; mi < 4; mi++)
        #pragma unroll
        for (int ni = 0; ni < 5; ni++)
            #pragma unroll
            for (int j = 0; j < 4; j++) acc[mi][ni][j] = 0.f;

    const int nch = C >> 6;
    for (int ch = 0; ch < nch; ch++) {
        const int c0 = ch << 6;
        #pragma unroll
        for (int e = tid; e < 1024; e += 256) {
            int row = e >> 3, q = e & 7;
            uint32_t dst = SWZ((uint32_t)(row * 128 + q * 16));
            *(uint4*)(dsm + dst)         = ((const uint4*)(g_wth + (size_t)(o0 + row) * C + c0))[q];
            *(uint4*)(dsm + 16384 + dst) = ((const uint4*)(g_wtl + (size_t)(o0 + row) * C + c0))[q];
        }
        for (int e = tid; e < 1280; e += 256) {
            int row = e >> 3, q = e & 7;
            uint32_t dst = SWZ((uint32_t)(row * 128 + q * 16));
            size_t src = (size_t)sSrc[row] * 512 + xoff + c0;
            *(uint4*)(dsm + 32768 + dst) = ((const uint4*)(g_xch + src))[q];
            *(uint4*)(dsm + 53248 + dst) = ((const uint4*)(g_xcl + src))[q];
        }
        __syncthreads();
        #pragma unroll
        for (int s = 0; s < 4; s++) {
            const uint32_t ofsA = ((uint32_t)(s * 32) + aSeg) ^ xorv;
            const uint32_t ofsB = ((uint32_t)(s * 32) + bSeg) ^ xorv;
            uint32_t ah[4][4], al[4][4];
            #pragma unroll
            for (int mi = 0; mi < 4; mi++) {
                ldsm4(ah[mi], sb + aRow + mi * 2048 + ofsA);
                ldsm4(al[mi], sb + 16384 + aRow + mi * 2048 + ofsA);
            }
            #pragma unroll
            for (int ni = 0; ni < 5; ni++) {
                uint32_t bh[2], bl[2];
                ldsm2(bh, sb + 32768 + bRow + ni * 1024 + ofsB);
                ldsm2(bl, sb + 53248 + bRow + ni * 1024 + ofsB);
                #pragma unroll
                for (int mi = 0; mi < 4; mi++) {
                    mma16816(acc[mi][ni], ah[mi], bh);
                    mma16816(acc[mi][ni], ah[mi], bl);
                    mma16816(acc[mi][ni], al[mi], bh);
                }
            }
        }
        __syncthreads();
    }

    // epilogue: cpart add, masked stats, per-(o, point) max/min (register-level)
    const int lrow = lane >> 2, lcol2 = (lane & 3) * 2;
    float cp[4][2][2];
    #pragma unroll
    for (int mi = 0; mi < 4; mi++)
        #pragma unroll
        for (int h = 0; h < 2; h++)
            #pragma unroll
            for (int pt = 0; pt < 2; pt++) {
                int o = o0 + wm * 64 + mi * 16 + h * 8 + lrow;
                cp[mi][h][pt] = (o < O) ? g_cpart[(size_t)(p0 + wn * 2 + pt) * O + o] : 0.f;
            }
    float st[4][2], st2[4][2];
    float mxv[4][2][2], mnv[4][2][2];
    #pragma unroll
    for (int mi = 0; mi < 4; mi++)
        #pragma unroll
        for (int h = 0; h < 2; h++) {
            st[mi][h] = 0.f; st2[mi][h] = 0.f;
            #pragma unroll
            for (int pt = 0; pt < 2; pt++) { mxv[mi][h][pt] = -INFINITY; mnv[mi][h][pt] = INFINITY; }
        }
    #pragma unroll
    for (int ni = 0; ni < 5; ni++) {
        const int cl = ni * 8 + lcol2;
        const int pt = (cl >= 20) ? 1 : 0;
        const int col = wn * 40 + cl;
        const bool v0 = sVal[col] != 0, v1 = sVal[col + 1] != 0;
        #pragma unroll
        for (int mi = 0; mi < 4; mi++) {
            float h00 = acc[mi][ni][0] + cp[mi][0][pt];
            float h01 = acc[mi][ni][1] + cp[mi][0][pt];
            float h10 = acc[mi][ni][2] + cp[mi][1][pt];
            float h11 = acc[mi][ni][3] + cp[mi][1][pt];
            if (v0) {
                st[mi][0] += h00; st2[mi][0] += h00 * h00;
                st[mi][1] += h10; st2[mi][1] += h10 * h10;
                mxv[mi][0][pt] = fmaxf(mxv[mi][0][pt], h00);
                mnv[mi][0][pt] = fminf(mnv[mi][0][pt], h00);
                mxv[mi][1][pt] = fmaxf(mxv[mi][1][pt], h10);
                mnv[mi][1][pt] = fminf(mnv[mi][1][pt], h10);
            }
            if (v1) {
                st[mi][0] += h01; st2[mi][0] += h01 * h01;
                st[mi][1] += h11; st2[mi][1] += h11 * h11;
                mxv[mi][0][pt] = fmaxf(mxv[mi][0][pt], h01);
                mnv[mi][0][pt] = fminf(mnv[mi][0][pt], h01);
                mxv[mi][1][pt] = fmaxf(mxv[mi][1][pt], h11);
                mnv[mi][1][pt] = fminf(mnv[mi][1][pt], h11);
            }
        }
    }
    #pragma unroll
    for (int mi = 0; mi < 4; mi++)
        #pragma unroll
        for (int h = 0; h < 2; h++) {
            float v = st[mi][h], v2 = st2[mi][h];
            v  += __shfl_xor_sync(0xffffffffu, v, 1);
            v  += __shfl_xor_sync(0xffffffffu, v, 2);
            v2 += __shfl_xor_sync(0xffffffffu, v2, 1);
            v2 += __shfl_xor_sync(0xffffffffu, v2, 2);
            float mxr[2], mnr[2];
            #pragma unroll
            for (int pt = 0; pt < 2; pt++) {
                float a = mxv[mi][h][pt], b = mnv[mi][h][pt];
                a = fmaxf(a, __shfl_xor_sync(0xffffffffu, a, 1));
                a = fmaxf(a, __shfl_xor_sync(0xffffffffu, a, 2));
                b = fminf(b, __shfl_xor_sync(0xffffffffu, b, 1));
                b = fminf(b, __shfl_xor_sync(0xffffffffu, b, 2));
                mxr[pt] = a; mnr[pt] = b;
            }
            if ((lane & 3) == 0) {
                int o = o0 + wm * 64 + mi * 16 + h * 8 + lrow;
                if (o < O) {
                    atomicAdd(&g_sum[o], v);
                    atomicAdd(&g_sumsq[o], v2);
                    #pragma unroll
                    for (int pt = 0; pt < 2; pt++) {
                        int p = p0 + wn * 2 + pt;
                        g_mx[(size_t)p * O + o] = mxr[pt];
                        g_mn[(size_t)p * O + o] = mnr[pt];
                    }
                }
            }
        }
}

// ---------------- host orchestration ----------------
extern "C" void kernel_launch(void* const* d_in, const int* in_sizes, int n_in,
                              void* d_out, int out_size) {
    const float*   x      = (const float*)d_in[0];
    const int*     idx    = (const int*)d_in[1];
    const void*    valid  = (const void*)d_in[2];
    const float* enc_w[4] = {(const float*)d_in[3], (const float*)d_in[6],
                             (const float*)d_in[9], (const float*)d_in[12]};
    const float* enc_g[4] = {(const float*)d_in[4], (const float*)d_in[7],
                             (const float*)d_in[10], (const float*)d_in[13]};
    const float* enc_bb[4]= {(const float*)d_in[5], (const float*)d_in[8],
                             (const float*)d_in[11], (const float*)d_in[14]};
    const float* last_w   = (const float*)d_in[15];
    const float* last_g   = (const float*)d_in[16];
    const float* last_b   = (const float*)d_in[17];
    const float* emb_w1   = (const float*)d_in[18];
    const float* emb_bias1= (const float*)d_in[19];
    const float* emb_g1   = (const float*)d_in[20];
    const float* emb_b1   = (const float*)d_in[21];
    const float* emb_w2   = (const float*)d_in[22];
    const float* emb_bias2= (const float*)d_in[23];
    const float* emb_g2   = (const float*)d_in[24];
    const float* emb_b2   = (const float*)d_in[25];
    const float* out_w    = (const float*)d_in[26];
    const float* out_bias = (const float*)d_in[27];

    cudaFuncSetAttribute(tgemm_tail, cudaFuncAttributeMaxDynamicSharedMemorySize, 69632);
    cudaFuncSetAttribute(tgemm_edge, cudaFuncAttributeMaxDynamicSharedMemorySize, 73728);

    float *xt0p, *cpartp, *y1p, *y2p, *y3p, *y3ap, *wdp, *w2p;
    __nv_bfloat16 *xchp, *xclp, *y1hp, *y1lp, *y2hp, *y2lp;
    cudaGetSymbolAddress((void**)&xt0p,  g_xt0);
    cudaGetSymbolAddress((void**)&cpartp,g_cpart);
    cudaGetSymbolAddress((void**)&y1p,   g_y1);
    cudaGetSymbolAddress((void**)&y2p,   g_y2);
    cudaGetSymbolAddress((void**)&y3p,   g_y3);
    cudaGetSymbolAddress((void**)&y3ap,  g_y3a);
    cudaGetSymbolAddress((void**)&wdp,   g_wd);
    cudaGetSymbolAddress((void**)&w2p,   g_w2);
    cudaGetSymbolAddress((void**)&xchp,  g_xch);
    cudaGetSymbolAddress((void**)&xclp,  g_xcl);
    cudaGetSymbolAddress((void**)&y1hp,  g_y1h);
    cudaGetSymbolAddress((void**)&y1lp,  g_y1l);
    cudaGetSymbolAddress((void**)&y2hp,  g_y2h);
    cudaGetSymbolAddress((void**)&y2lp,  g_y2l);
    float* xcatp; cudaGetSymbolAddress((void**)&xcatp, g_xcat);

    k_detect<<<1, 1024>>>(valid);
    k_count<<<P_ / 256, 256>>>(valid);
    k_transpose<<<P_ / 256, 256>>>(x);

    const int blkC[4]   = {3, 64, 64, 128};
    const int blkO[4]   = {64, 64, 128, 256};
    const int inOff[4]  = {0, 0, 64, 128};
    const int outOff[4] = {0, 64, 128, 256};

    for (int i = 0; i < 4; i++) {
        int C = blkC[i], O = blkO[i];
        const float* xin = (i == 0) ? xt0p : xcatp;
        int ldx = (i == 0) ? 3 : 512;
        int xoff = inOff[i];

        k_prepw<<<(O * C + 255) / 256, 256>>>(enc_w[i], O, C);
        gemm_pt<0, false><<<dim3(P_ / 64, (O + 127) / 128), 256>>>(
            xin, ldx, xoff, w2p, O, C, nullptr, cpartp);
        k_zero_stats<<<(O + 255) / 256, 256>>>(O);
        if (i == 0) {
            edge_gemm<<<dim3(P_ / 4, 1), 256>>>(xin, ldx, xoff, C, O, idx, valid);
        } else {
            int Opad = (O + 127) & ~127;
            k_prepw_bf16<<<(Opad * C + 255) / 256, 256>>>(wdp, O, Opad, C);
            tgemm_edge<<<dim3(P_ / 8, Opad / 128), 256, 73728>>>(xoff, C, O, idx, valid);
        }
        k_bn_param<<<(O + 255) / 256, 256>>>(O, enc_g[i], enc_bb[i], 0);
        k_edge_pass2<<<(P_ * O + 255) / 256, 256>>>(O, outOff[i]);
    }

    // ---- tail (warp-MMA) ----
    k_prepw_bf16<<<(1024 * 512 + 255) / 256, 256>>>(last_w, 1024, 1024, 512);
    k_zero_stats<<<4, 256>>>(1024);
    tgemm_tail<<<dim3(P_ / 128, 8), 256, 69632>>>(xchp, xclp, 512, 1024, 512, nullptr, y1p);
    k_bn_param<<<4, 256>>>(1024, last_g, last_b, 1);
    k_convert<<<(P_ * 1024 + 255) / 256, 256>>>(y1p, 1024, y1hp, y1lp, nullptr);

    k_prepw_bf16<<<(512 * 1024 + 255) / 256, 256>>>(emb_w1, 512, 512, 1024);
    k_zero_stats<<<2, 256>>>(512);
    tgemm_tail<<<dim3(P_ / 128, 4), 256, 69632>>>(y1hp, y1lp, 1024, 512, 1024, emb_bias1, y2p);
    k_bn_param<<<2, 256>>>(512, emb_g1, emb_b1, 1);
    k_convert<<<(P_ * 512 + 255) / 256, 256>>>(y2p, 512, y2hp, y2lp, nullptr);

    k_prepw_bf16<<<(128 * 512 + 255) / 256, 256>>>(emb_w2, 128, 128, 512);
    k_zero_stats<<<1, 256>>>(128);
    tgemm_tail<<<dim3(P_ / 128, 1), 256, 69632>>>(y2hp, y2lp, 512, 128, 512, emb_bias2, y3p);
    k_bn_param<<<1, 256>>>(128, emb_g2, emb_b2, 1);
    k_convert<<<(P_ * 128 + 255) / 256, 256>>>(y3p, 128, y2hp, y2lp, y3ap);

    // out: 128 -> 32, scalar (tiny), transposed (B,32,N) output
    gemm_pt<1, false><<<dim3(P_ / 64, 1), 256>>>(y3ap, 128, 0, out_w, 32, 128,
                                                 out_bias, (float*)d_out);
}

// round 5
// speedup vs baseline: 2.3470x; 1.2089x over previous
#include <cuda_runtime.h>
#include <cuda_bf16.h>
#include <cstdint>

#define B_ 8
#define N_ 2048
#define K_ 20
#define P_ (B_*N_)      // 16384
#define EPS 1e-5f

// ---------------- scratch (device globals; no runtime allocation) ----------------
__device__ __align__(128) float g_xt0 [P_*3];
__device__ __align__(128) float g_xcat[P_*512];         // concat fp32, point-major
__device__ __align__(128) __nv_bfloat16 g_xch[P_*512];  // concat bf16 hi
__device__ __align__(128) __nv_bfloat16 g_xcl[P_*512];  // concat bf16 lo
__device__ __align__(128) float g_cpart[P_*256];        // stride 256 per point
__device__ __align__(128) float g_mx[P_*256];
__device__ __align__(128) float g_mn[P_*256];
__device__ __align__(128) float g_y1[P_*1024];
__device__ __align__(128) float g_y2[P_*512];
__device__ __align__(128) float g_y3[P_*128];
__device__ __align__(128) float g_y3a[P_*128];
__device__ __align__(128) __nv_bfloat16 g_y1h[P_*1024];
__device__ __align__(128) __nv_bfloat16 g_y1l[P_*1024];
__device__ __align__(128) __nv_bfloat16 g_y2h[P_*512];
__device__ __align__(128) __nv_bfloat16 g_y2l[P_*512];
__device__ __align__(128) float g_wd[256*256];
__device__ __align__(128) float g_w2[256*256];
__device__ __align__(128) __nv_bfloat16 g_wth[1024*1024];
__device__ __align__(128) __nv_bfloat16 g_wtl[1024*1024];
__device__ __align__(128) __nv_bfloat16 g_w2h[256*256];
__device__ __align__(128) __nv_bfloat16 g_w2l[256*256];
__device__ float g_sum[1024];
__device__ float g_sumsq[1024];
__device__ float g_a[1024];
__device__ float g_b2[1024];
__device__ int     g_cnt[P_];
__device__ uint8_t g_ok[P_];
__device__ int g_totvalid;
__device__ int g_okcnt;
__device__ int g_vmode;   // 0=int32, 1=uint8, 2=float32

// ---------------- warp-MMA + cp.async helpers (sm_80+ PTX, legal on plain sm_103) ----------------
#define SWZ(x) ((x) ^ (((x) >> 3) & 0x70))
__device__ __forceinline__ uint32_t s2u(const void* p) {
    uint32_t a;
    asm("{ .reg .u64 t; cvta.to.shared.u64 t, %1; cvt.u32.u64 %0, t; }" : "=r"(a) : "l"(p));
    return a;
}
__device__ __forceinline__ void ldsm4(uint32_t* r, uint32_t a) {
    asm volatile("ldmatrix.sync.aligned.m8n8.x4.shared.b16 {%0,%1,%2,%3}, [%4];"
                 : "=r"(r[0]), "=r"(r[1]), "=r"(r[2]), "=r"(r[3]) : "r"(a));
}
__device__ __forceinline__ void ldsm2(uint32_t* r, uint32_t a) {
    asm volatile("ldmatrix.sync.aligned.m8n8.x2.shared.b16 {%0,%1}, [%2];"
                 : "=r"(r[0]), "=r"(r[1]) : "r"(a));
}
__device__ __forceinline__ void mma16816(float* c, const uint32_t* a, const uint32_t* b) {
    asm volatile("mma.sync.aligned.m16n8k16.row.col.f32.bf16.bf16.f32 "
                 "{%0,%1,%2,%3},{%4,%5,%6,%7},{%8,%9},{%0,%1,%2,%3};"
                 : "+f"(c[0]), "+f"(c[1]), "+f"(c[2]), "+f"(c[3])
                 : "r"(a[0]), "r"(a[1]), "r"(a[2]), "r"(a[3]), "r"(b[0]), "r"(b[1]));
}
__device__ __forceinline__ void cpa16(uint32_t dst, const void* src) {
    asm volatile("cp.async.cg.shared.global [%0], [%1], 16;" :: "r"(dst), "l"(src));
}
#define CPA_COMMIT() asm volatile("cp.async.commit_group;" ::: "memory")
#define CPA_WAIT1()  asm volatile("cp.async.wait_group 1;" ::: "memory")
#define CPA_WAIT0()  asm volatile("cp.async.wait_group 0;" ::: "memory")

// ---------------- valid dtype detection + accessor ----------------
__global__ void k_detect(const void* v) {
    const int nwords = (P_ * K_) / 4;
    const unsigned int* w = (const unsigned int*)v;
    __shared__ int s_not01, s_f32;
    if (threadIdx.x == 0) { s_not01 = 0; s_f32 = 0; }
    __syncthreads();
    int not01 = 0, f32 = 0;
    for (int i = threadIdx.x; i < nwords; i += blockDim.x) {
        unsigned int u = w[i];
        if (u > 1u) not01 = 1;
        if (u == 0x3F800000u) f32 = 1;
    }
    if (not01) atomicOr(&s_not01, 1);
    if (f32)   atomicOr(&s_f32, 1);
    __syncthreads();
    if (threadIdx.x == 0) {
        g_vmode = (!s_not01) ? 0 : (s_f32 ? 2 : 1);
        g_totvalid = 0;
        g_okcnt = 0;
    }
}
__device__ __forceinline__ int valid_at(const void* v, int i) {
    int m = g_vmode;
    if (m == 0) return ((const int*)v)[i] != 0;
    if (m == 1) return ((const uint8_t*)v)[i] != 0;
    return ((const float*)v)[i] != 0.0f;
}

// ---------------- small utility kernels ----------------
__global__ void k_count(const void* __restrict__ valid) {
    int p = blockIdx.x * 256 + threadIdx.x;
    int c = 0;
    #pragma unroll
    for (int k = 0; k < K_; k++) c += valid_at(valid, p * K_ + k);
    g_cnt[p] = c;
    int okf = (c >= 1) ? 1 : 0;
    g_ok[p] = (uint8_t)okf;
    int tot = c, okc = okf;
    for (int d = 16; d; d >>= 1) {
        tot += __shfl_xor_sync(0xffffffffu, tot, d);
        okc += __shfl_xor_sync(0xffffffffu, okc, d);
    }
    if ((threadIdx.x & 31) == 0) {
        atomicAdd(&g_totvalid, tot);
        atomicAdd(&g_okcnt, okc);
    }
}

__global__ void k_transpose(const float* __restrict__ x) {
    int p = blockIdx.x * 256 + threadIdx.x;
    if (p >= P_) return;
    int b = p >> 11, n = p & (N_ - 1);
    #pragma unroll
    for (int c = 0; c < 3; c++)
        g_xt0[p * 3 + c] = x[(b * 3 + c) * N_ + n];
}

// edge-block weight prep: wd = W[:, :C], w2 = W[:, C:] - wd; fp32 + bf16 splits (rows >= O zero)
__global__ void k_prep_edge(const float* __restrict__ w, int O, int Opad, int C) {
    int i = blockIdx.x * 256 + threadIdx.x;
    if (i >= Opad * C) return;
    int o = i / C, c = i - o * C;
    float wd = 0.f, w2 = 0.f;
    if (o < O) {
        wd = w[o * 2 * C + c];
        w2 = w[o * 2 * C + C + c] - wd;
        g_wd[o * C + c] = wd;
        g_w2[o * C + c] = w2;
    }
    __nv_bfloat16 h = __float2bfloat16(wd);
    g_wth[i] = h;
    g_wtl[i] = __float2bfloat16(wd - __bfloat162float(h));
    __nv_bfloat16 h2 = __float2bfloat16(w2);
    g_w2h[i] = h2;
    g_w2l[i] = __float2bfloat16(w2 - __bfloat162float(h2));
}

// split fp32 weights -> bf16 hi/lo into g_wth/g_wtl (tail layers)
__global__ void k_prepw_bf16(const float* __restrict__ src, int O, int Opad, int C) {
    int i = blockIdx.x * 256 + threadIdx.x;
    if (i >= Opad * C) return;
    int o = i / C;
    float v = (o < O) ? src[i] : 0.f;
    __nv_bfloat16 h = __float2bfloat16(v);
    g_wth[i] = h;
    g_wtl[i] = __float2bfloat16(v - __bfloat162float(h));
}

__global__ void k_zero_stats(int O) {
    int i = blockIdx.x * 256 + threadIdx.x;
    if (i < O) { g_sum[i] = 0.f; g_sumsq[i] = 0.f; }
}

__global__ void k_bn_param(int O, const float* __restrict__ gamma,
                           const float* __restrict__ beta, int use_ok) {
    int o = blockIdx.x * 256 + threadIdx.x;
    if (o >= O) return;
    float cnt = (float)(use_ok ? g_okcnt : g_totvalid);
    float n = fmaxf(cnt, 1.f);
    float s = g_sum[o];
    float mean = s / n;
    float var = (g_sumsq[o] - 2.f * mean * s + mean * mean * cnt) / n;
    float a = gamma[o] * rsqrtf(fmaxf(var, 0.f) + EPS);
    g_a[o] = a;
    g_b2[o] = beta[o] - mean * a;
}

// BN(+lrelu) via pre-BN max/min, ok-gated; writes fp32 + bf16 hi/lo concat slabs
__global__ void k_edge_pass2(int O, int off) {
    int i = blockIdx.x * 256 + threadIdx.x;
    if (i >= P_ * O) return;
    int p = i / O, o = i - p * O;
    float a = g_a[o];
    float v = (a >= 0.f) ? g_mx[i] : g_mn[i];
    float h = a * v + g_b2[o];
    h = (h >= 0.f) ? h : 0.2f * h;
    if (g_cnt[p] < 1) h = 0.f;
    int di = p * 512 + off + o;
    g_xcat[di] = h;
    __nv_bfloat16 hh = __float2bfloat16(h);
    g_xch[di] = hh;
    g_xcl[di] = __float2bfloat16(h - __bfloat162float(hh));
}

// apply BN+lrelu to raw point-major fp32, emit bf16 hi/lo (+ optional fp32)
__global__ void k_convert(const float* __restrict__ Y, int O,
                          __nv_bfloat16* __restrict__ H, __nv_bfloat16* __restrict__ L,
                          float* __restrict__ F) {
    int i = blockIdx.x * 256 + threadIdx.x;
    if (i >= P_ * O) return;
    int o = i & (O - 1);
    float y = g_a[o] * Y[i] + g_b2[o];
    y = (y >= 0.f) ? y : 0.2f * y;
    __nv_bfloat16 h = __float2bfloat16(y);
    H[i] = h;
    L[i] = __float2bfloat16(y - __bfloat162float(h));
    if (F) F[i] = y;
}

// ---------------- scalar GEMM (block1 cpart + final tiny layer) ----------------
// OUTM: 0 -> Y[p*O+o], 1 -> (B,O,N) transposed, 3 -> Y[p*256+o]
template<int OUTM>
__global__ __launch_bounds__(256)
void gemm_pt(const float* __restrict__ X, int ldx, int xoff,
             const float* __restrict__ W, int O, int C,
             const float* __restrict__ bias, float* __restrict__ Y) {
    const int tid = threadIdx.x, tx = tid & 15, ty = tid >> 4;
    const int p0 = blockIdx.x * 64, o0 = blockIdx.y * 128;
    __shared__ float sW[128 * 17];
    __shared__ float sX[16 * 64];
    float acc[8][4];
    #pragma unroll
    for (int r = 0; r < 8; r++)
        #pragma unroll
        for (int j = 0; j < 4; j++) acc[r][j] = 0.f;

    for (int c0 = 0; c0 < C; c0 += 16) {
        #pragma unroll
        for (int e = tid; e < 128 * 16; e += 256) {
            int ol = e >> 4, cc = e & 15;
            int o = o0 + ol, c = c0 + cc;
            sW[ol * 17 + cc] = (o < O && c < C) ? W[o * C + c] : 0.f;
        }
        #pragma unroll
        for (int e = tid; e < 16 * 64; e += 256) {
            int col = e >> 4, cc = e & 15;
            int c = c0 + cc;
            sX[cc * 64 + col] = (c < C) ? X[(p0 + col) * ldx + xoff + c] : 0.f;
        }
        __syncthreads();
        #pragma unroll
        for (int cc = 0; cc < 16; cc++) {
            float fv[4], wv[8];
            #pragma unroll
            for (int j = 0; j < 4; j++) fv[j] = sX[cc * 64 + tx + 16 * j];
            #pragma unroll
            for (int r = 0; r < 8; r++) wv[r] = sW[(ty + 16 * r) * 17 + cc];
            #pragma unroll
            for (int r = 0; r < 8; r++)
                #pragma unroll
                for (int j = 0; j < 4; j++) acc[r][j] += wv[r] * fv[j];
        }
        __syncthreads();
    }

    #pragma unroll
    for (int r = 0; r < 8; r++) {
        int o = o0 + ty + 16 * r;
        float bs = (bias != nullptr && o < O) ? bias[o] : 0.f;
        #pragma unroll
        for (int j = 0; j < 4; j++) {
            int col = tx + 16 * j, p = p0 + col;
            float y = acc[r][j] + bs;
            if (o < O) {
                if (OUTM == 0) Y[p * O + o] = y;
                else if (OUTM == 3) Y[p * 256 + o] = y;
                else {
                    int b = p >> 11, n = p & (N_ - 1);
                    Y[(b * O + o) * N_ + n] = y;
                }
            }
        }
    }
}

// ---------------- scalar gather edge GEMM (block 1, C=3) ----------------
__global__ __launch_bounds__(256)
void edge_gemm(const float* __restrict__ Xin, int ldx, int xoff, int C, int O,
               const int* __restrict__ idx, const void* __restrict__ valid) {
    const int tid = threadIdx.x, tx = tid & 15, ty = tid >> 4;
    const int p0 = blockIdx.x * 4, o0 = blockIdx.y * 128;
    __shared__ float sW[128 * 17];
    __shared__ float sF[16 * 80];
    __shared__ int sSrc[80];
    __shared__ uint8_t sVal[80];
    __shared__ float sC[4 * 128];

    if (tid < 80) {
        int pt = tid / 20, k = tid - pt * 20;
        int p = p0 + pt, b = p >> 11;
        sSrc[tid] = (b << 11) + idx[p * K_ + k];
        sVal[tid] = (uint8_t)valid_at(valid, p * K_ + k);
    }
    for (int e = tid; e < 512; e += 256) {
        int pt = e >> 7, ol = e & 127;
        int o = o0 + ol;
        sC[e] = (o < O) ? g_cpart[(p0 + pt) * 256 + o] : 0.f;
    }
    __syncthreads();

    float acc[8][5];
    #pragma unroll
    for (int r = 0; r < 8; r++)
        #pragma unroll
        for (int j = 0; j < 5; j++) acc[r][j] = 0.f;

    for (int c0 = 0; c0 < C; c0 += 16) {
        #pragma unroll
        for (int e = tid; e < 128 * 16; e += 256) {
            int ol = e >> 4, cc = e & 15;
            int o = o0 + ol, c = c0 + cc;
            sW[ol * 17 + cc] = (o < O && c < C) ? g_wd[o * C + c] : 0.f;
        }
        #pragma unroll
        for (int e = tid; e < 16 * 80; e += 256) {
            int col = e >> 4, cc = e & 15;
            int c = c0 + cc;
            sF[cc * 80 + col] = (c < C) ? Xin[sSrc[col] * ldx + xoff + c] : 0.f;
        }
        __syncthreads();
        #pragma unroll
        for (int cc = 0; cc < 16; cc++) {
            float fv[5], wv[8];
            #pragma unroll
            for (int j = 0; j < 5; j++) fv[j] = sF[cc * 80 + tx * 5 + j];
            #pragma unroll
            for (int r = 0; r < 8; r++) wv[r] = sW[(ty + 16 * r) * 17 + cc];
            #pragma unroll
            for (int r = 0; r < 8; r++)
                #pragma unroll
                for (int j = 0; j < 5; j++) acc[r][j] += wv[r] * fv[j];
        }
        __syncthreads();
    }

    const int myPt = tx >> 2;
    const int cbase = tx * 5;
    #pragma unroll
    for (int r = 0; r < 8; r++) {
        int ol = ty + 16 * r, o = o0 + ol;
        float cp = sC[myPt * 128 + ol];
        float s = 0.f, s2 = 0.f;
        float vmx = -INFINITY, vmn = INFINITY;
        #pragma unroll
        for (int j = 0; j < 5; j++) {
            int col = cbase + j;
            float h = acc[r][j] + cp;
            if (sVal[col]) {
                s += h; s2 += h * h;
                vmx = fmaxf(vmx, h);
                vmn = fminf(vmn, h);
            }
        }
        for (int d = 1; d < 16; d <<= 1) {
            s  += __shfl_xor_sync(0xffffffffu, s,  d);
            s2 += __shfl_xor_sync(0xffffffffu, s2, d);
        }
        for (int d = 1; d < 4; d <<= 1) {
            vmx = fmaxf(vmx, __shfl_xor_sync(0xffffffffu, vmx, d));
            vmn = fminf(vmn, __shfl_xor_sync(0xffffffffu, vmn, d));
        }
        if (o < O) {
            if (tx == 0) {
                atomicAdd(&g_sum[o], s);
                atomicAdd(&g_sumsq[o], s2);
            }
            if ((tx & 3) == 0) {
                int p = p0 + myPt;
                g_mx[p * O + o] = vmx;
                g_mn[p * O + o] = vmn;
            }
        }
    }
}

// ---------------- warp-MMA dense GEMM: block 128(o) x 128(p), bf16-split x3 ----------------
// double-buffered cp.async; per buffer 64KB: Whi[0,16K) Wlo[16K,32K) Xhi[32K,48K) Xlo[48K,64K)
// output point-major at stride ldout; optional bias + masked stats
template<bool STATS>
__global__ __launch_bounds__(256, 1)
void tgemm_tail(const __nv_bfloat16* __restrict__ Xhi, const __nv_bfloat16* __restrict__ Xlo,
                const __nv_bfloat16* __restrict__ Wh, const __nv_bfloat16* __restrict__ Wl,
                int ldx, int xoff, int C, int ldout,
                const float* __restrict__ bias, float* __restrict__ Y) {
    extern __shared__ __align__(1024) unsigned char dsm[];
    __shared__ uint8_t sOk[128];
    const int tid = threadIdx.x, lane = tid & 31, wid = tid >> 5;
    const int wm = wid >> 2, wn = wid & 3;
    const int p0 = blockIdx.x * 128, o0 = blockIdx.y * 128;
    const uint32_t sb = s2u(dsm);
    if (STATS && tid < 128) sOk[tid] = g_ok[p0 + tid];

    const int lr = lane & 7, g = lane >> 3;
    const uint32_t xorv = (uint32_t)lr * 16;
    const uint32_t aRow = (uint32_t)(wm * 64 + (g & 1) * 8 + lr) * 128;
    const uint32_t aSeg = (uint32_t)(g >> 1) * 16;
    const uint32_t bRow = (uint32_t)(wn * 32 + lr) * 128;
    const uint32_t bSeg = (uint32_t)(g & 1) * 16;

    float acc[4][4][4];
    #pragma unroll
    for (int mi = 0; mi < 4; mi++)
        #pragma unroll
        for (int ni = 0; ni < 4; ni++)
            #pragma unroll
            for (int j = 0; j < 4; j++) acc[mi][ni][j] = 0.f;

    const int nch = C >> 6;
    // prefetch chunk 0
    {
        const int c0 = 0;
        #pragma unroll
        for (int e = tid; e < 1024; e += 256) {
            int row = e >> 3, q = e & 7;
            uint32_t dst = SWZ((uint32_t)(row * 128 + q * 16));
            cpa16(sb + dst,         Wh  + (size_t)(o0 + row) * C + c0 + q * 8);
            cpa16(sb + 16384 + dst, Wl  + (size_t)(o0 + row) * C + c0 + q * 8);
            cpa16(sb + 32768 + dst, Xhi + (size_t)(p0 + row) * ldx + xoff + c0 + q * 8);
            cpa16(sb + 49152 + dst, Xlo + (size_t)(p0 + row) * ldx + xoff + c0 + q * 8);
        }
        CPA_COMMIT();
    }
    for (int ch = 0; ch < nch; ch++) {
        if (ch + 1 < nch) {
            const int c0 = (ch + 1) << 6;
            const uint32_t bo = (uint32_t)((ch + 1) & 1) * 65536u;
            #pragma unroll
            for (int e = tid; e < 1024; e += 256) {
                int row = e >> 3, q = e & 7;
                uint32_t dst = bo + SWZ((uint32_t)(row * 128 + q * 16));
                cpa16(sb + dst,         Wh  + (size_t)(o0 + row) * C + c0 + q * 8);
                cpa16(sb + 16384 + dst, Wl  + (size_t)(o0 + row) * C + c0 + q * 8);
                cpa16(sb + 32768 + dst, Xhi + (size_t)(p0 + row) * ldx + xoff + c0 + q * 8);
                cpa16(sb + 49152 + dst, Xlo + (size_t)(p0 + row) * ldx + xoff + c0 + q * 8);
            }
            CPA_COMMIT();
            CPA_WAIT1();
        } else {
            CPA_WAIT0();
        }
        __syncthreads();
        const uint32_t bo = (uint32_t)(ch & 1) * 65536u;
        #pragma unroll
        for (int s = 0; s < 4; s++) {
            const uint32_t ofsA = bo + (((uint32_t)(s * 32) + aSeg) ^ xorv);
            const uint32_t ofsB = bo + (((uint32_t)(s * 32) + bSeg) ^ xorv);
            uint32_t ah[4][4], al[4][4], bh[4][2], bl[4][2];
            #pragma unroll
            for (int mi = 0; mi < 4; mi++) {
                ldsm4(ah[mi], sb + aRow + mi * 2048 + ofsA);
                ldsm4(al[mi], sb + 16384 + aRow + mi * 2048 + ofsA);
            }
            #pragma unroll
            for (int ni = 0; ni < 4; ni++) {
                ldsm2(bh[ni], sb + 32768 + bRow + ni * 1024 + ofsB);
                ldsm2(bl[ni], sb + 49152 + bRow + ni * 1024 + ofsB);
            }
            #pragma unroll
            for (int mi = 0; mi < 4; mi++)
                #pragma unroll
                for (int ni = 0; ni < 4; ni++) {
                    mma16816(acc[mi][ni], ah[mi], bh[ni]);
                    mma16816(acc[mi][ni], ah[mi], bl[ni]);
                    mma16816(acc[mi][ni], al[mi], bh[ni]);
                }
        }
        __syncthreads();
    }

    // epilogue: bias + (masked stats) + smem transpose + coalesced store
    const int lrow = lane >> 2, lcol2 = (lane & 3) * 2;
    float bias_r[4][2];
    #pragma unroll
    for (int mi = 0; mi < 4; mi++)
        #pragma unroll
        for (int h = 0; h < 2; h++) {
            int o = o0 + wm * 64 + mi * 16 + h * 8 + lrow;
            bias_r[mi][h] = (bias != nullptr) ? bias[o] : 0.f;
        }
    float st[4][2], st2[4][2];
    #pragma unroll
    for (int mi = 0; mi < 4; mi++)
        #pragma unroll
        for (int h = 0; h < 2; h++) { st[mi][h] = 0.f; st2[mi][h] = 0.f; }

    float* sT = (float*)dsm;   // [128][132] fp32, reuses buffers
    #pragma unroll
    for (int mi = 0; mi < 4; mi++) {
        const int ro = wm * 64 + mi * 16 + lrow;
        #pragma unroll
        for (int ni = 0; ni < 4; ni++) {
            const int cp0 = wn * 32 + ni * 8 + lcol2;
            float y00 = acc[mi][ni][0] + bias_r[mi][0];
            float y01 = acc[mi][ni][1] + bias_r[mi][0];
            float y10 = acc[mi][ni][2] + bias_r[mi][1];
            float y11 = acc[mi][ni][3] + bias_r[mi][1];
            if (STATS) {
                if (sOk[cp0])     { st[mi][0] += y00; st2[mi][0] += y00 * y00;
                                    st[mi][1] += y10; st2[mi][1] += y10 * y10; }
                if (sOk[cp0 + 1]) { st[mi][0] += y01; st2[mi][0] += y01 * y01;
                                    st[mi][1] += y11; st2[mi][1] += y11 * y11; }
            }
            sT[cp0 * 132 + ro]           = y00;
            sT[(cp0 + 1) * 132 + ro]     = y01;
            sT[cp0 * 132 + ro + 8]       = y10;
            sT[(cp0 + 1) * 132 + ro + 8] = y11;
        }
    }
    if (STATS) {
        #pragma unroll
        for (int mi = 0; mi < 4; mi++)
            #pragma unroll
            for (int h = 0; h < 2; h++) {
                float v = st[mi][h], v2 = st2[mi][h];
                v  += __shfl_xor_sync(0xffffffffu, v, 1);
                v  += __shfl_xor_sync(0xffffffffu, v, 2);
                v2 += __shfl_xor_sync(0xffffffffu, v2, 1);
                v2 += __shfl_xor_sync(0xffffffffu, v2, 2);
                if ((lane & 3) == 0) {
                    int o = o0 + wm * 64 + mi * 16 + h * 8 + lrow;
                    atomicAdd(&g_sum[o], v);
                    atomicAdd(&g_sumsq[o], v2);
                }
            }
    }
    __syncthreads();
    {
        int p = tid >> 1, hf = tid & 1;
        const float4* src = (const float4*)(sT + p * 132 + hf * 64);
        float4* dst = (float4*)(Y + (size_t)(p0 + p) * ldout + o0 + hf * 64);
        #pragma unroll
        for (int i = 0; i < 16; i++) dst[i] = src[i];
    }
}

// ---------------- warp-MMA edge GEMM: block 128(o) x 160(8 pts x 20 k), gathered B ----------------
// double-buffered cp.async; per buffer 72KB: Whi[0,16K) Wlo[16K,32K) Bhi[32K,52K) Blo[52K,72K)
__global__ __launch_bounds__(256, 1)
void tgemm_edge(int xoff, int C, int O,
                const int* __restrict__ idx, const void* __restrict__ valid) {
    extern __shared__ __align__(1024) unsigned char dsm[];
    __shared__ int sSrc[160];
    __shared__ uint8_t sVal[160];
    const int tid = threadIdx.x, lane = tid & 31, wid = tid >> 5;
    const int wm = wid >> 2, wn = wid & 3;
    const int p0 = blockIdx.x * 8, o0 = blockIdx.y * 128;
    const uint32_t sb = s2u(dsm);
    const uint32_t BUF = 73728u;

    if (tid < 160) {
        int p = p0 + tid / 20, k = tid % 20;
        int b = p >> 11;
        sSrc[tid] = (b << 11) + idx[p * K_ + k];
        sVal[tid] = (uint8_t)valid_at(valid, p * K_ + k);
    }
    __syncthreads();

    const int lr = lane & 7, g = lane >> 3;
    const uint32_t xorv = (uint32_t)lr * 16;
    const uint32_t aRow = (uint32_t)(wm * 64 + (g & 1) * 8 + lr) * 128;
    const uint32_t aSeg = (uint32_t)(g >> 1) * 16;
    const uint32_t bRow = (uint32_t)(wn * 40 + lr) * 128;
    const uint32_t bSeg = (uint32_t)(g & 1) * 16;

    float acc[4][5][4];
    #pragma unroll
    for (int mi = 0; mi < 4; mi++)
        #pragma unroll
        for (int ni = 0; ni < 5; ni++)
            #pragma unroll
            for (int j = 0; j < 4; j++) acc[mi][ni][j] = 0.f;

    const int nch = C >> 6;
    {
        const int c0 = 0;
        #pragma unroll
        for (int e = tid; e < 1024; e += 256) {
            int row = e >> 3, q = e & 7;
            uint32_t dst = SWZ((uint32_t)(row * 128 + q * 16));
            cpa16(sb + dst,         g_wth + (size_t)(o0 + row) * C + c0 + q * 8);
            cpa16(sb + 16384 + dst, g_wtl + (size_t)(o0 + row) * C + c0 + q * 8);
        }
        for (int e = tid; e < 1280; e += 256) {
            int row = e >> 3, q = e & 7;
            uint32_t dst = SWZ((uint32_t)(row * 128 + q * 16));
            size_t src = (size_t)sSrc[row] * 512 + xoff + c0 + q * 8;
            cpa16(sb + 32768 + dst, g_xch + src);
            cpa16(sb + 53248 + dst, g_xcl + src);
        }
        CPA_COMMIT();
    }
    for (int ch = 0; ch < nch; ch++) {
        if (ch + 1 < nch) {
            const int c0 = (ch + 1) << 6;
            const uint32_t bo = (uint32_t)((ch + 1) & 1) * BUF;
            #pragma unroll
            for (int e = tid; e < 1024; e += 256) {
                int row = e >> 3, q = e & 7;
                uint32_t dst = bo + SWZ((uint32_t)(row * 128 + q * 16));
                cpa16(sb + dst,         g_wth + (size_t)(o0 + row) * C + c0 + q * 8);
                cpa16(sb + 16384 + dst, g_wtl + (size_t)(o0 + row) * C + c0 + q * 8);
            }
            for (int e = tid; e < 1280; e += 256) {
                int row = e >> 3, q = e & 7;
                uint32_t dst = bo + SWZ((uint32_t)(row * 128 + q * 16));
                size_t src = (size_t)sSrc[row] * 512 + xoff + c0 + q * 8;
                cpa16(sb + 32768 + dst, g_xch + src);
                cpa16(sb + 53248 + dst, g_xcl + src);
            }
            CPA_COMMIT();
            CPA_WAIT1();
        } else {
            CPA_WAIT0();
        }
        __syncthreads();
        const uint32_t bo = (uint32_t)(ch & 1) * BUF;
        #pragma unroll
        for (int s = 0; s < 4; s++) {
            const uint32_t ofsA = bo + (((uint32_t)(s * 32) + aSeg) ^ xorv);
            const uint32_t ofsB = bo + (((uint32_t)(s * 32) + bSeg) ^ xorv);
            uint32_t ah[4][4], al[4][4];
            #pragma unroll
            for (int mi = 0; mi < 4; mi++) {
                ldsm4(ah[mi], sb + aRow + mi * 2048 + ofsA);
                ldsm4(al[mi], sb + 16384 + aRow + mi * 2048 + ofsA);
            }
            #pragma unroll
            for (int ni = 0; ni < 5; ni++) {
                uint32_t bh[2], bl[2];
                ldsm2(bh, sb + 32768 + bRow + ni * 1024 + ofsB);
                ldsm2(bl, sb + 53248 + bRow + ni * 1024 + ofsB);
                #pragma unroll
                for (int mi = 0; mi < 4; mi++) {
                    mma16816(acc[mi][ni], ah[mi], bh);
                    mma16816(acc[mi][ni], ah[mi], bl);
                    mma16816(acc[mi][ni], al[mi], bh);
                }
            }
        }
        __syncthreads();
    }

    // epilogue: cpart add, masked stats, per-(o, point) max/min
    const int lrow = lane >> 2, lcol2 = (lane & 3) * 2;
    float cp[4][2][2];
    #pragma unroll
    for (int mi = 0; mi < 4; mi++)
        #pragma unroll
        for (int h = 0; h < 2; h++)
            #pragma unroll
            for (int pt = 0; pt < 2; pt++) {
                int o = o0 + wm * 64 + mi * 16 + h * 8 + lrow;
                cp[mi][h][pt] = (o < O) ? g_cpart[(size_t)(p0 + wn * 2 + pt) * 256 + o] : 0.f;
            }
    float st[4][2], st2[4][2];
    float mxv[4][2][2], mnv[4][2][2];
    #pragma unroll
    for (int mi = 0; mi < 4; mi++)
        #pragma unroll
        for (int h = 0; h < 2; h++) {
            st[mi][h] = 0.f; st2[mi][h] = 0.f;
            #pragma unroll
            for (int pt = 0; pt < 2; pt++) { mxv[mi][h][pt] = -INFINITY; mnv[mi][h][pt] = INFINITY; }
        }
    #pragma unroll
    for (int ni = 0; ni < 5; ni++) {
        const int cl = ni * 8 + lcol2;
        const int pt = (cl >= 20) ? 1 : 0;
        const int col = wn * 40 + cl;
        const bool v0 = sVal[col] != 0, v1 = sVal[col + 1] != 0;
        #pragma unroll
        for (int mi = 0; mi < 4; mi++) {
            float h00 = acc[mi][ni][0] + cp[mi][0][pt];
            float h01 = acc[mi][ni][1] + cp[mi][0][pt];
            float h10 = acc[mi][ni][2] + cp[mi][1][pt];
            float h11 = acc[mi][ni][3] + cp[mi][1][pt];
            if (v0) {
                st[mi][0] += h00; st2[mi][0] += h00 * h00;
                st[mi][1] += h10; st2[mi][1] += h10 * h10;
                mxv[mi][0][pt] = fmaxf(mxv[mi][0][pt], h00);
                mnv[mi][0][pt] = fminf(mnv[mi][0][pt], h00);
                mxv[mi][1][pt] = fmaxf(mxv[mi][1][pt], h10);
                mnv[mi][1][pt] = fminf(mnv[mi][1][pt], h10);
            }
            if (v1) {
                st[mi][0] += h01; st2[mi][0] += h01 * h01;
                st[mi][1] += h11; st2[mi][1] += h11 * h11;
                mxv[mi][0][pt] = fmaxf(mxv[mi][0][pt], h01);
                mnv[mi][0][pt] = fminf(mnv[mi][0][pt], h01);
                mxv[mi][1][pt] = fmaxf(mxv[mi][1][pt], h11);
                mnv[mi][1][pt] = fminf(mnv[mi][1][pt], h11);
            }
        }
    }
    #pragma unroll
    for (int mi = 0; mi < 4; mi++)
        #pragma unroll
        for (int h = 0; h < 2; h++) {
            float v = st[mi][h], v2 = st2[mi][h];
            v  += __shfl_xor_sync(0xffffffffu, v, 1);
            v  += __shfl_xor_sync(0xffffffffu, v, 2);
            v2 += __shfl_xor_sync(0xffffffffu, v2, 1);
            v2 += __shfl_xor_sync(0xffffffffu, v2, 2);
            float mxr[2], mnr[2];
            #pragma unroll
            for (int pt = 0; pt < 2; pt++) {
                float a = mxv[mi][h][pt], b = mnv[mi][h][pt];
                a = fmaxf(a, __shfl_xor_sync(0xffffffffu, a, 1));
                a = fmaxf(a, __shfl_xor_sync(0xffffffffu, a, 2));
                b = fminf(b, __shfl_xor_sync(0xffffffffu, b, 1));
                b = fminf(b, __shfl_xor_sync(0xffffffffu, b, 2));
                mxr[pt] = a; mnr[pt] = b;
            }
            if ((lane & 3) == 0) {
                int o = o0 + wm * 64 + mi * 16 + h * 8 + lrow;
                if (o < O) {
                    atomicAdd(&g_sum[o], v);
                    atomicAdd(&g_sumsq[o], v2);
                    #pragma unroll
                    for (int pt = 0; pt < 2; pt++) {
                        int p = p0 + wn * 2 + pt;
                        g_mx[(size_t)p * O + o] = mxr[pt];
                        g_mn[(size_t)p * O + o] = mnr[pt];
                    }
                }
            }
        }
}

// ---------------- host orchestration ----------------
extern "C" void kernel_launch(void* const* d_in, const int* in_sizes, int n_in,
                              void* d_out, int out_size) {
    const float*   x      = (const float*)d_in[0];
    const int*     idx    = (const int*)d_in[1];
    const void*    valid  = (const void*)d_in[2];
    const float* enc_w[4] = {(const float*)d_in[3], (const float*)d_in[6],
                             (const float*)d_in[9], (const float*)d_in[12]};
    const float* enc_g[4] = {(const float*)d_in[4], (const float*)d_in[7],
                             (const float*)d_in[10], (const float*)d_in[13]};
    const float* enc_bb[4]= {(const float*)d_in[5], (const float*)d_in[8],
                             (const float*)d_in[11], (const float*)d_in[14]};
    const float* last_w   = (const float*)d_in[15];
    const float* last_g   = (const float*)d_in[16];
    const float* last_b   = (const float*)d_in[17];
    const float* emb_w1   = (const float*)d_in[18];
    const float* emb_bias1= (const float*)d_in[19];
    const float* emb_g1   = (const float*)d_in[20];
    const float* emb_b1   = (const float*)d_in[21];
    const float* emb_w2   = (const float*)d_in[22];
    const float* emb_bias2= (const float*)d_in[23];
    const float* emb_g2   = (const float*)d_in[24];
    const float* emb_b2   = (const float*)d_in[25];
    const float* out_w    = (const float*)d_in[26];
    const float* out_bias = (const float*)d_in[27];

    cudaFuncSetAttribute(tgemm_tail<true>,  cudaFuncAttributeMaxDynamicSharedMemorySize, 131072);
    cudaFuncSetAttribute(tgemm_tail<false>, cudaFuncAttributeMaxDynamicSharedMemorySize, 131072);
    cudaFuncSetAttribute(tgemm_edge, cudaFuncAttributeMaxDynamicSharedMemorySize, 147456);

    float *xt0p, *cpartp, *y1p, *y2p, *y3p, *y3ap, *w2p;
    __nv_bfloat16 *xchp, *xclp, *y1hp, *y1lp, *y2hp, *y2lp, *wthp, *wtlp, *w2hp, *w2lp;
    cudaGetSymbolAddress((void**)&xt0p,  g_xt0);
    cudaGetSymbolAddress((void**)&cpartp,g_cpart);
    cudaGetSymbolAddress((void**)&y1p,   g_y1);
    cudaGetSymbolAddress((void**)&y2p,   g_y2);
    cudaGetSymbolAddress((void**)&y3p,   g_y3);
    cudaGetSymbolAddress((void**)&y3ap,  g_y3a);
    cudaGetSymbolAddress((void**)&w2p,   g_w2);
    cudaGetSymbolAddress((void**)&xchp,  g_xch);
    cudaGetSymbolAddress((void**)&xclp,  g_xcl);
    cudaGetSymbolAddress((void**)&y1hp,  g_y1h);
    cudaGetSymbolAddress((void**)&y1lp,  g_y1l);
    cudaGetSymbolAddress((void**)&y2hp,  g_y2h);
    cudaGetSymbolAddress((void**)&y2lp,  g_y2l);
    cudaGetSymbolAddress((void**)&wthp,  g_wth);
    cudaGetSymbolAddress((void**)&wtlp,  g_wtl);
    cudaGetSymbolAddress((void**)&w2hp,  g_w2h);
    cudaGetSymbolAddress((void**)&w2lp,  g_w2l);
    float* xcatp; cudaGetSymbolAddress((void**)&xcatp, g_xcat);

    k_detect<<<1, 1024>>>(valid);
    k_count<<<P_ / 256, 256>>>(valid);
    k_transpose<<<P_ / 256, 256>>>(x);

    const int blkC[4]   = {3, 64, 64, 128};
    const int blkO[4]   = {64, 64, 128, 256};
    const int inOff[4]  = {0, 0, 64, 128};
    const int outOff[4] = {0, 64, 128, 256};

    for (int i = 0; i < 4; i++) {
        int C = blkC[i], O = blkO[i];
        int Opad = (O + 127) & ~127;
        int xoff = inOff[i];

        k_prep_edge<<<(Opad * C + 255) / 256, 256>>>(enc_w[i], O, Opad, C);
        k_zero_stats<<<(O + 255) / 256, 256>>>(O);
        if (i == 0) {
            // scalar cpart (stride-256 out) + scalar gather GEMM (C=3)
            gemm_pt<3><<<dim3(P_ / 64, 1), 256>>>(xt0p, 3, 0, w2p, O, C, nullptr, cpartp);
            edge_gemm<<<dim3(P_ / 4, 1), 256>>>(xt0p, 3, 0, C, O, idx, valid);
        } else {
            // tensor cpart: (Wc-Wd) @ ctr, point-major stride 256
            tgemm_tail<false><<<dim3(P_ / 128, Opad / 128), 256, 131072>>>(
                xchp, xclp, w2hp, w2lp, 512, xoff, C, 256, nullptr, cpartp);
            tgemm_edge<<<dim3(P_ / 8, Opad / 128), 256, 147456>>>(xoff, C, O, idx, valid);
        }
        k_bn_param<<<(O + 255) / 256, 256>>>(O, enc_g[i], enc_bb[i], 0);
        k_edge_pass2<<<(P_ * O + 255) / 256, 256>>>(O, outOff[i]);
    }

    // ---- tail (warp-MMA, double-buffered) ----
    k_prepw_bf16<<<(1024 * 512 + 255) / 256, 256>>>(last_w, 1024, 1024, 512);
    k_zero_stats<<<4, 256>>>(1024);
    tgemm_tail<true><<<dim3(P_ / 128, 8), 256, 131072>>>(
        xchp, xclp, wthp, wtlp, 512, 0, 512, 1024, nullptr, y1p);
    k_bn_param<<<4, 256>>>(1024, last_g, last_b, 1);
    k_convert<<<(P_ * 1024 + 255) / 256, 256>>>(y1p, 1024, y1hp, y1lp, nullptr);

    k_prepw_bf16<<<(512 * 1024 + 255) / 256, 256>>>(emb_w1, 512, 512, 1024);
    k_zero_stats<<<2, 256>>>(512);
    tgemm_tail<true><<<dim3(P_ / 128, 4), 256, 131072>>>(
        y1hp, y1lp, wthp, wtlp, 1024, 0, 1024, 512, emb_bias1, y2p);
    k_bn_param<<<2, 256>>>(512, emb_g1, emb_b1, 1);
    k_convert<<<(P_ * 512 + 255) / 256, 256>>>(y2p, 512, y2hp, y2lp, nullptr);

    k_prepw_bf16<<<(128 * 512 + 255) / 256, 256>>>(emb_w2, 128, 128, 512);
    k_zero_stats<<<1, 256>>>(128);
    tgemm_tail<true><<<dim3(P_ / 128, 1), 256, 131072>>>(
        y2hp, y2lp, wthp, wtlp, 512, 0, 512, 128, emb_bias2, y3p);
    k_bn_param<<<1, 256>>>(128, emb_g2, emb_b2, 1);
    k_convert<<<(P_ * 128 + 255) / 256, 256>>>(y3p, 128, y2hp, y2lp, y3ap);

    // out: 128 -> 32, scalar (tiny), transposed (B,32,N) output
    gemm_pt<1><<<dim3(P_ / 64, 1), 256>>>(y3ap, 128, 0, out_w, 32, 128,
                                          out_bias, (float*)d_out);
}

// round 6
// speedup vs baseline: 2.5503x; 1.0866x over previous
#include <cuda_runtime.h>
#include <cuda_bf16.h>
#include <cstdint>

#define B_ 8
#define N_ 2048
#define K_ 20
#define P_ (B_*N_)      // 16384
#define EPS 1e-5f

// ---------------- scratch (device globals; no runtime allocation) ----------------
__device__ __align__(128) float g_xt0 [P_*3];
__device__ __align__(128) float g_xcat[P_*512];
__device__ __align__(128) __nv_bfloat16 g_xch[P_*512];
__device__ __align__(128) __nv_bfloat16 g_xcl[P_*512];
__device__ __align__(128) float g_cpart[P_*256];        // stride 256 per point
__device__ __align__(128) float g_mx[P_*256];
__device__ __align__(128) float g_mn[P_*256];
__device__ __align__(128) float g_y1[P_*1024];
__device__ __align__(128) float g_y2[P_*512];
__device__ __align__(128) float g_y3[P_*128];
__device__ __align__(128) __nv_bfloat16 g_y1h[P_*1024];
__device__ __align__(128) __nv_bfloat16 g_y1l[P_*1024];
__device__ __align__(128) __nv_bfloat16 g_y2h[P_*512];
__device__ __align__(128) __nv_bfloat16 g_y2l[P_*512];
// weight arenas
#define EW1D 0
#define EW1C 4096
#define EW2D 8192
#define EW2C 16384
#define EW3D 24576
#define EW3C 57344
#define EW_TOT 90112
#define TL  0
#define TE1 524288
#define TE2 1048576
#define TW_TOT 1114112
__device__ __align__(128) __nv_bfloat16 g_ewh[EW_TOT];
__device__ __align__(128) __nv_bfloat16 g_ewl[EW_TOT];
__device__ __align__(128) __nv_bfloat16 g_twh[TW_TOT];
__device__ __align__(128) __nv_bfloat16 g_twl[TW_TOT];
__device__ float g_wd[192];     // blk0 fp32
__device__ float g_w2[192];
__device__ float g_sum[7168];
__device__ float g_sumsq[7168];
__device__ int     g_cnt[P_];
__device__ uint8_t g_ok[P_];
__device__ int g_totvalid;
__device__ int g_okcnt;
__device__ int g_vmode;   // 0=int32, 1=uint8, 2=float32

// ---------------- helpers ----------------
#define SWZ(x) ((x) ^ (((x) >> 3) & 0x70))
__device__ __forceinline__ uint32_t s2u(const void* p) {
    uint32_t a;
    asm("{ .reg .u64 t; cvta.to.shared.u64 t, %1; cvt.u32.u64 %0, t; }" : "=r"(a) : "l"(p));
    return a;
}
__device__ __forceinline__ void ldsm4(uint32_t* r, uint32_t a) {
    asm volatile("ldmatrix.sync.aligned.m8n8.x4.shared.b16 {%0,%1,%2,%3}, [%4];"
                 : "=r"(r[0]), "=r"(r[1]), "=r"(r[2]), "=r"(r[3]) : "r"(a));
}
__device__ __forceinline__ void ldsm2(uint32_t* r, uint32_t a) {
    asm volatile("ldmatrix.sync.aligned.m8n8.x2.shared.b16 {%0,%1}, [%2];"
                 : "=r"(r[0]), "=r"(r[1]) : "r"(a));
}
__device__ __forceinline__ void mma16816(float* c, const uint32_t* a, const uint32_t* b) {
    asm volatile("mma.sync.aligned.m16n8k16.row.col.f32.bf16.bf16.f32 "
                 "{%0,%1,%2,%3},{%4,%5,%6,%7},{%8,%9},{%0,%1,%2,%3};"
                 : "+f"(c[0]), "+f"(c[1]), "+f"(c[2]), "+f"(c[3])
                 : "r"(a[0]), "r"(a[1]), "r"(a[2]), "r"(a[3]), "r"(b[0]), "r"(b[1]));
}
__device__ __forceinline__ void cpa16(uint32_t dst, const void* src) {
    asm volatile("cp.async.cg.shared.global [%0], [%1], 16;" :: "r"(dst), "l"(src));
}
#define CPA_COMMIT() asm volatile("cp.async.commit_group;" ::: "memory")
#define CPA_WAIT1()  asm volatile("cp.async.wait_group 1;" ::: "memory")
#define CPA_WAIT0()  asm volatile("cp.async.wait_group 0;" ::: "memory")

// inline BN params from raw stats
__device__ __forceinline__ void bn_ab(int o, int base, float cnt,
                                      const float* __restrict__ gamma,
                                      const float* __restrict__ beta,
                                      float& a, float& b) {
    float n = fmaxf(cnt, 1.f);
    float s = g_sum[base + o];
    float mean = s / n;
    float var = (g_sumsq[base + o] - 2.f * mean * s + mean * mean * cnt) / n;
    a = gamma[o] * rsqrtf(fmaxf(var, 0.f) + EPS);
    b = beta[o] - mean * a;
}

// ---------------- mega-prep: all weight splits + stat zeroing in ONE launch ----------------
__global__ void k_megaprep(const float* __restrict__ w2_, const float* __restrict__ w3_,
                           const float* __restrict__ w4_, const float* __restrict__ lw,
                           const float* __restrict__ e1, const float* __restrict__ e2,
                           const float* __restrict__ w1_) {
    int i = blockIdx.x * 256 + threadIdx.x;
    if (i < EW_TOT) {
        float v;
        if (i < 4096)        { int o = i >> 6, c = i & 63; v = w2_[o * 128 + c]; }
        else if (i < 8192)   { int j = i - 4096, o = j >> 6, c = j & 63;
                               v = w2_[o * 128 + 64 + c] - w2_[o * 128 + c]; }
        else if (i < 16384)  { int j = i - 8192, o = j >> 6, c = j & 63; v = w3_[o * 128 + c]; }
        else if (i < 24576)  { int j = i - 16384, o = j >> 6, c = j & 63;
                               v = w3_[o * 128 + 64 + c] - w3_[o * 128 + c]; }
        else if (i < 57344)  { int j = i - 24576, o = j >> 7, c = j & 127; v = w4_[o * 256 + c]; }
        else                 { int j = i - 57344, o = j >> 7, c = j & 127;
                               v = w4_[o * 256 + 128 + c] - w4_[o * 256 + c]; }
        __nv_bfloat16 h = __float2bfloat16(v);
        g_ewh[i] = h;
        g_ewl[i] = __float2bfloat16(v - __bfloat162float(h));
        return;
    }
    i -= EW_TOT;
    if (i < TW_TOT) {
        float v = (i < TE1) ? lw[i] : ((i < TE2) ? e1[i - TE1] : e2[i - TE2]);
        __nv_bfloat16 h = __float2bfloat16(v);
        g_twh[i] = h;
        g_twl[i] = __float2bfloat16(v - __bfloat162float(h));
        return;
    }
    i -= TW_TOT;
    if (i < 192) {
        int o = i / 3, c = i - o * 3;
        float wd = w1_[o * 6 + c];
        g_wd[i] = wd;
        g_w2[i] = w1_[o * 6 + 3 + c] - wd;
        return;
    }
    i -= 192;
    if (i < 7168) { g_sum[i] = 0.f; g_sumsq[i] = 0.f; }
}
#define MEGAN (EW_TOT + TW_TOT + 192 + 7168)

// ---------------- valid dtype detection + accessor ----------------
__global__ void k_detect(const void* v) {
    const int nwords = (P_ * K_) / 4;
    const unsigned int* w = (const unsigned int*)v;
    __shared__ int s_not01, s_f32;
    if (threadIdx.x == 0) { s_not01 = 0; s_f32 = 0; }
    __syncthreads();
    int not01 = 0, f32 = 0;
    for (int i = threadIdx.x; i < nwords; i += blockDim.x) {
        unsigned int u = w[i];
        if (u > 1u) not01 = 1;
        if (u == 0x3F800000u) f32 = 1;
    }
    if (not01) atomicOr(&s_not01, 1);
    if (f32)   atomicOr(&s_f32, 1);
    __syncthreads();
    if (threadIdx.x == 0) {
        g_vmode = (!s_not01) ? 0 : (s_f32 ? 2 : 1);
        g_totvalid = 0;
        g_okcnt = 0;
    }
}
__device__ __forceinline__ int valid_at(const void* v, int i) {
    int m = g_vmode;
    if (m == 0) return ((const int*)v)[i] != 0;
    if (m == 1) return ((const uint8_t*)v)[i] != 0;
    return ((const float*)v)[i] != 0.0f;
}

__global__ void k_count(const void* __restrict__ valid) {
    int p = blockIdx.x * 256 + threadIdx.x;
    int c = 0;
    #pragma unroll
    for (int k = 0; k < K_; k++) c += valid_at(valid, p * K_ + k);
    g_cnt[p] = c;
    int okf = (c >= 1) ? 1 : 0;
    g_ok[p] = (uint8_t)okf;
    int tot = c, okc = okf;
    for (int d = 16; d; d >>= 1) {
        tot += __shfl_xor_sync(0xffffffffu, tot, d);
        okc += __shfl_xor_sync(0xffffffffu, okc, d);
    }
    if ((threadIdx.x & 31) == 0) {
        atomicAdd(&g_totvalid, tot);
        atomicAdd(&g_okcnt, okc);
    }
}

__global__ void k_transpose(const float* __restrict__ x) {
    int p = blockIdx.x * 256 + threadIdx.x;
    if (p >= P_) return;
    int b = p >> 11, n = p & (N_ - 1);
    #pragma unroll
    for (int c = 0; c < 3; c++)
        g_xt0[p * 3 + c] = x[(b * 3 + c) * N_ + n];
}

// BN(+lrelu) via pre-BN max/min, ok-gated, BN params inline; writes concat slabs
__global__ void k_edge_pass2(int O, int off, int base,
                             const float* __restrict__ gamma, const float* __restrict__ beta) {
    int i = blockIdx.x * 256 + threadIdx.x;
    if (i >= P_ * O) return;
    int p = i / O, o = i - p * O;
    float a, b;
    bn_ab(o, base, (float)g_totvalid, gamma, beta, a, b);
    float v = (a >= 0.f) ? g_mx[i] : g_mn[i];
    float h = a * v + b;
    h = (h >= 0.f) ? h : 0.2f * h;
    if (g_cnt[p] < 1) h = 0.f;
    int di = p * 512 + off + o;
    g_xcat[di] = h;
    __nv_bfloat16 hh = __float2bfloat16(h);
    g_xch[di] = hh;
    g_xcl[di] = __float2bfloat16(h - __bfloat162float(hh));
}

// BN+lrelu (params inline, ok-count) on point-major fp32, emit bf16 hi/lo
__global__ void k_convert(const float* __restrict__ Y, int O, int base,
                          const float* __restrict__ gamma, const float* __restrict__ beta,
                          __nv_bfloat16* __restrict__ H, __nv_bfloat16* __restrict__ L) {
    int i = blockIdx.x * 256 + threadIdx.x;
    if (i >= P_ * O) return;
    int o = i & (O - 1);
    float a, b;
    bn_ab(o, base, (float)g_okcnt, gamma, beta, a, b);
    float y = a * Y[i] + b;
    y = (y >= 0.f) ? y : 0.2f * y;
    __nv_bfloat16 h = __float2bfloat16(y);
    H[i] = h;
    L[i] = __float2bfloat16(y - __bfloat162float(h));
}

// ---------------- scalar GEMM (blk0 cpart) ----------------
__global__ __launch_bounds__(256)
void gemm_pt3(const float* __restrict__ X, const float* __restrict__ W,
              int O, int C, float* __restrict__ Y) {
    const int tid = threadIdx.x, tx = tid & 15, ty = tid >> 4;
    const int p0 = blockIdx.x * 64;
    __shared__ float sW[128 * 17];
    __shared__ float sX[16 * 64];
    float acc[8][4];
    #pragma unroll
    for (int r = 0; r < 8; r++)
        #pragma unroll
        for (int j = 0; j < 4; j++) acc[r][j] = 0.f;

    for (int c0 = 0; c0 < C; c0 += 16) {
        #pragma unroll
        for (int e = tid; e < 128 * 16; e += 256) {
            int ol = e >> 4, cc = e & 15;
            int c = c0 + cc;
            sW[ol * 17 + cc] = (ol < O && c < C) ? W[ol * C + c] : 0.f;
        }
        #pragma unroll
        for (int e = tid; e < 16 * 64; e += 256) {
            int col = e >> 4, cc = e & 15;
            int c = c0 + cc;
            sX[cc * 64 + col] = (c < C) ? X[(p0 + col) * C + c] : 0.f;
        }
        __syncthreads();
        #pragma unroll
        for (int cc = 0; cc < 16; cc++) {
            float fv[4], wv[8];
            #pragma unroll
            for (int j = 0; j < 4; j++) fv[j] = sX[cc * 64 + tx + 16 * j];
            #pragma unroll
            for (int r = 0; r < 8; r++) wv[r] = sW[(ty + 16 * r) * 17 + cc];
            #pragma unroll
            for (int r = 0; r < 8; r++)
                #pragma unroll
                for (int j = 0; j < 4; j++) acc[r][j] += wv[r] * fv[j];
        }
        __syncthreads();
    }
    #pragma unroll
    for (int r = 0; r < 8; r++) {
        int o = ty + 16 * r;
        if (o >= O) break;
        #pragma unroll
        for (int j = 0; j < 4; j++)
            Y[(p0 + tx + 16 * j) * 256 + o] = acc[r][j];
    }
}

// ---------------- final out GEMM: fused input-BN, transposed output ----------------
__global__ __launch_bounds__(256)
void k_gemm_out(const float* __restrict__ X, const float* __restrict__ W,
                const float* __restrict__ bias, int base,
                const float* __restrict__ gamma, const float* __restrict__ beta,
                float* __restrict__ Y) {
    const int O = 32, C = 128;
    const int tid = threadIdx.x, tx = tid & 15, ty = tid >> 4;
    const int p0 = blockIdx.x * 64;
    __shared__ float sW[32 * 17];
    __shared__ float sX[16 * 64];
    float acc[2][4];
    #pragma unroll
    for (int r = 0; r < 2; r++)
        #pragma unroll
        for (int j = 0; j < 4; j++) acc[r][j] = 0.f;

    const float cnt = (float)g_okcnt;
    for (int c0 = 0; c0 < C; c0 += 16) {
        for (int e = tid; e < 32 * 16; e += 256) {
            int ol = e >> 4, cc = e & 15;
            sW[ol * 17 + cc] = W[ol * C + c0 + cc];
        }
        #pragma unroll
        for (int e = tid; e < 16 * 64; e += 256) {
            int col = e >> 4, cc = e & 15;
            int c = c0 + cc;
            float a, b;
            bn_ab(c, base, cnt, gamma, beta, a, b);
            float y = a * X[(p0 + col) * C + c] + b;
            sX[cc * 64 + col] = (y >= 0.f) ? y : 0.2f * y;
        }
        __syncthreads();
        #pragma unroll
        for (int cc = 0; cc < 16; cc++) {
            float fv[4], wv[2];
            #pragma unroll
            for (int j = 0; j < 4; j++) fv[j] = sX[cc * 64 + tx + 16 * j];
            #pragma unroll
            for (int r = 0; r < 2; r++) wv[r] = sW[(ty + 16 * r) * 17 + cc];
            #pragma unroll
            for (int r = 0; r < 2; r++)
                #pragma unroll
                for (int j = 0; j < 4; j++) acc[r][j] += wv[r] * fv[j];
        }
        __syncthreads();
    }
    #pragma unroll
    for (int r = 0; r < 2; r++) {
        int o = ty + 16 * r;
        float bs = bias[o];
        #pragma unroll
        for (int j = 0; j < 4; j++) {
            int p = p0 + tx + 16 * j;
            int b = p >> 11, n = p & (N_ - 1);
            Y[(b * O + o) * N_ + n] = acc[r][j] + bs;
        }
    }
}

// ---------------- scalar gather edge GEMM (blk0, C=3) ----------------
__global__ __launch_bounds__(256)
void edge_gemm0(const int* __restrict__ idx, const void* __restrict__ valid) {
    const int C = 3, O = 64;
    const int tid = threadIdx.x, tx = tid & 15, ty = tid >> 4;
    const int p0 = blockIdx.x * 4;
    __shared__ float sW[64 * 17];
    __shared__ float sF[16 * 80];
    __shared__ int sSrc[80];
    __shared__ uint8_t sVal[80];
    __shared__ float sC[4 * 64];

    if (tid < 80) {
        int pt = tid / 20, k = tid - pt * 20;
        int p = p0 + pt, b = p >> 11;
        sSrc[tid] = (b << 11) + idx[p * K_ + k];
        sVal[tid] = (uint8_t)valid_at(valid, p * K_ + k);
    }
    if (tid < 256) {
        int pt = tid >> 6, ol = tid & 63;
        sC[tid] = g_cpart[(p0 + pt) * 256 + ol];
    }
    for (int e = tid; e < 64 * 16; e += 256) {
        int ol = e >> 4, cc = e & 15;
        sW[ol * 17 + cc] = (cc < C) ? g_wd[ol * C + cc] : 0.f;
    }
    __syncthreads();
    for (int e = tid; e < 16 * 80; e += 256) {
        int col = e >> 4, cc = e & 15;
        sF[cc * 80 + col] = (cc < C) ? g_xt0[sSrc[col] * 3 + cc] : 0.f;
    }
    __syncthreads();

    float acc[4][5];
    #pragma unroll
    for (int r = 0; r < 4; r++)
        #pragma unroll
        for (int j = 0; j < 5; j++) acc[r][j] = 0.f;
    #pragma unroll
    for (int cc = 0; cc < 3; cc++) {
        float fv[5], wv[4];
        #pragma unroll
        for (int j = 0; j < 5; j++) fv[j] = sF[cc * 80 + tx * 5 + j];
        #pragma unroll
        for (int r = 0; r < 4; r++) wv[r] = sW[(ty + 16 * r) * 17 + cc];
        #pragma unroll
        for (int r = 0; r < 4; r++)
            #pragma unroll
            for (int j = 0; j < 5; j++) acc[r][j] += wv[r] * fv[j];
    }

    const int myPt = tx >> 2;
    const int cbase = tx * 5;
    #pragma unroll
    for (int r = 0; r < 4; r++) {
        int o = ty + 16 * r;
        float cp = sC[myPt * 64 + o];
        float s = 0.f, s2 = 0.f;
        float vmx = -INFINITY, vmn = INFINITY;
        #pragma unroll
        for (int j = 0; j < 5; j++) {
            int col = cbase + j;
            float h = acc[r][j] + cp;
            if (sVal[col]) {
                s += h; s2 += h * h;
                vmx = fmaxf(vmx, h);
                vmn = fminf(vmn, h);
            }
        }
        for (int d = 1; d < 16; d <<= 1) {
            s  += __shfl_xor_sync(0xffffffffu, s,  d);
            s2 += __shfl_xor_sync(0xffffffffu, s2, d);
        }
        for (int d = 1; d < 4; d <<= 1) {
            vmx = fmaxf(vmx, __shfl_xor_sync(0xffffffffu, vmx, d));
            vmn = fminf(vmn, __shfl_xor_sync(0xffffffffu, vmn, d));
        }
        if (tx == 0) {
            atomicAdd(&g_sum[o], s);
            atomicAdd(&g_sumsq[o], s2);
        }
        if ((tx & 3) == 0) {
            int p = p0 + myPt;
            g_mx[p * O + o] = vmx;
            g_mn[p * O + o] = vmn;
        }
    }
}

// ---------------- warp-MMA dense GEMM, MT-templated (M tile = MT*32) ----------------
template<bool STATS, int MT>
__global__ __launch_bounds__(256, 1)
void tgemm_tail(const __nv_bfloat16* __restrict__ Xhi, const __nv_bfloat16* __restrict__ Xlo,
                const __nv_bfloat16* __restrict__ Wh, const __nv_bfloat16* __restrict__ Wl,
                int ldx, int xoff, int C, int ldout, int base,
                const float* __restrict__ bias, float* __restrict__ Y) {
    extern __shared__ __align__(1024) unsigned char dsm[];
    __shared__ uint8_t sOk[128];
    const int tid = threadIdx.x, lane = tid & 31, wid = tid >> 5;
    const int wm = wid >> 2, wn = wid & 3;
    const int MTILE = MT * 32;
    const uint32_t OFF_WL = MT * 4096u, OFF_XH = MT * 8192u, OFF_XL = MT * 8192u + 16384u;
    const uint32_t BUF = MT * 8192u + 32768u;
    const int p0 = blockIdx.x * 128, o0 = blockIdx.y * MTILE;
    const uint32_t sb = s2u(dsm);
    if (STATS && tid < 128) sOk[tid] = g_ok[p0 + tid];

    const int lr = lane & 7, g = lane >> 3;
    const uint32_t xorv = (uint32_t)lr * 16;
    const uint32_t aRow = (uint32_t)(wm * (MT * 16) + (g & 1) * 8 + lr) * 128;
    const uint32_t aSeg = (uint32_t)(g >> 1) * 16;
    const uint32_t bRow = (uint32_t)(wn * 32 + lr) * 128;
    const uint32_t bSeg = (uint32_t)(g & 1) * 16;

    float acc[MT][4][4];
    #pragma unroll
    for (int mi = 0; mi < MT; mi++)
        #pragma unroll
        for (int ni = 0; ni < 4; ni++)
            #pragma unroll
            for (int j = 0; j < 4; j++) acc[mi][ni][j] = 0.f;

    const int nch = C >> 6;
    {
        #pragma unroll
        for (int e = tid; e < MT * 256; e += 256) {
            int row = e >> 3, q = e & 7;
            uint32_t dst = SWZ((uint32_t)(row * 128 + q * 16));
            cpa16(sb + dst,          Wh + (size_t)(o0 + row) * C + q * 8);
            cpa16(sb + OFF_WL + dst, Wl + (size_t)(o0 + row) * C + q * 8);
        }
        #pragma unroll
        for (int e = tid; e < 1024; e += 256) {
            int row = e >> 3, q = e & 7;
            uint32_t dst = SWZ((uint32_t)(row * 128 + q * 16));
            cpa16(sb + OFF_XH + dst, Xhi + (size_t)(p0 + row) * ldx + xoff + q * 8);
            cpa16(sb + OFF_XL + dst, Xlo + (size_t)(p0 + row) * ldx + xoff + q * 8);
        }
        CPA_COMMIT();
    }
    for (int ch = 0; ch < nch; ch++) {
        if (ch + 1 < nch) {
            const int c0 = (ch + 1) << 6;
            const uint32_t bo = (uint32_t)((ch + 1) & 1) * BUF;
            #pragma unroll
            for (int e = tid; e < MT * 256; e += 256) {
                int row = e >> 3, q = e & 7;
                uint32_t dst = bo + SWZ((uint32_t)(row * 128 + q * 16));
                cpa16(sb + dst,          Wh + (size_t)(o0 + row) * C + c0 + q * 8);
                cpa16(sb + OFF_WL + dst, Wl + (size_t)(o0 + row) * C + c0 + q * 8);
            }
            #pragma unroll
            for (int e = tid; e < 1024; e += 256) {
                int row = e >> 3, q = e & 7;
                uint32_t dst = bo + SWZ((uint32_t)(row * 128 + q * 16));
                cpa16(sb + OFF_XH + dst, Xhi + (size_t)(p0 + row) * ldx + xoff + c0 + q * 8);
                cpa16(sb + OFF_XL + dst, Xlo + (size_t)(p0 + row) * ldx + xoff + c0 + q * 8);
            }
            CPA_COMMIT();
            CPA_WAIT1();
        } else {
            CPA_WAIT0();
        }
        __syncthreads();
        const uint32_t bo = (uint32_t)(ch & 1) * BUF;
        #pragma unroll
        for (int s = 0; s < 4; s++) {
            const uint32_t ofsA = bo + (((uint32_t)(s * 32) + aSeg) ^ xorv);
            const uint32_t ofsB = bo + (((uint32_t)(s * 32) + bSeg) ^ xorv);
            uint32_t ah[MT][4], al[MT][4], bh[4][2], bl[4][2];
            #pragma unroll
            for (int mi = 0; mi < MT; mi++) {
                ldsm4(ah[mi], sb + aRow + mi * 2048 + ofsA);
                ldsm4(al[mi], sb + OFF_WL + aRow + mi * 2048 + ofsA);
            }
            #pragma unroll
            for (int ni = 0; ni < 4; ni++) {
                ldsm2(bh[ni], sb + OFF_XH + bRow + ni * 1024 + ofsB);
                ldsm2(bl[ni], sb + OFF_XL + bRow + ni * 1024 + ofsB);
            }
            #pragma unroll
            for (int mi = 0; mi < MT; mi++)
                #pragma unroll
                for (int ni = 0; ni < 4; ni++) {
                    mma16816(acc[mi][ni], ah[mi], bh[ni]);
                    mma16816(acc[mi][ni], ah[mi], bl[ni]);
                    mma16816(acc[mi][ni], al[mi], bh[ni]);
                }
        }
        __syncthreads();
    }

    const int lrow = lane >> 2, lcol2 = (lane & 3) * 2;
    const int STR = MTILE + 4;
    float bias_r[MT][2];
    #pragma unroll
    for (int mi = 0; mi < MT; mi++)
        #pragma unroll
        for (int h = 0; h < 2; h++) {
            int o = o0 + wm * (MT * 16) + mi * 16 + h * 8 + lrow;
            bias_r[mi][h] = (bias != nullptr) ? bias[o] : 0.f;
        }
    float st[MT][2], st2[MT][2];
    #pragma unroll
    for (int mi = 0; mi < MT; mi++)
        #pragma unroll
        for (int h = 0; h < 2; h++) { st[mi][h] = 0.f; st2[mi][h] = 0.f; }

    float* sT = (float*)dsm;
    #pragma unroll
    for (int mi = 0; mi < MT; mi++) {
        const int ro = wm * (MT * 16) + mi * 16 + lrow;
        #pragma unroll
        for (int ni = 0; ni < 4; ni++) {
            const int cp0 = wn * 32 + ni * 8 + lcol2;
            float y00 = acc[mi][ni][0] + bias_r[mi][0];
            float y01 = acc[mi][ni][1] + bias_r[mi][0];
            float y10 = acc[mi][ni][2] + bias_r[mi][1];
            float y11 = acc[mi][ni][3] + bias_r[mi][1];
            if (STATS) {
                if (sOk[cp0])     { st[mi][0] += y00; st2[mi][0] += y00 * y00;
                                    st[mi][1] += y10; st2[mi][1] += y10 * y10; }
                if (sOk[cp0 + 1]) { st[mi][0] += y01; st2[mi][0] += y01 * y01;
                                    st[mi][1] += y11; st2[mi][1] += y11 * y11; }
            }
            sT[cp0 * STR + ro]           = y00;
            sT[(cp0 + 1) * STR + ro]     = y01;
            sT[cp0 * STR + ro + 8]       = y10;
            sT[(cp0 + 1) * STR + ro + 8] = y11;
        }
    }
    if (STATS) {
        #pragma unroll
        for (int mi = 0; mi < MT; mi++)
            #pragma unroll
            for (int h = 0; h < 2; h++) {
                float v = st[mi][h], v2 = st2[mi][h];
                v  += __shfl_xor_sync(0xffffffffu, v, 1);
                v  += __shfl_xor_sync(0xffffffffu, v, 2);
                v2 += __shfl_xor_sync(0xffffffffu, v2, 1);
                v2 += __shfl_xor_sync(0xffffffffu, v2, 2);
                if ((lane & 3) == 0) {
                    int o = o0 + wm * (MT * 16) + mi * 16 + h * 8 + lrow;
                    atomicAdd(&g_sum[base + o], v);
                    atomicAdd(&g_sumsq[base + o], v2);
                }
            }
    }
    __syncthreads();
    {
        int p = tid >> 1, hf = tid & 1;
        const float4* src = (const float4*)(sT + p * STR + hf * (MT * 16));
        float4* dst = (float4*)(Y + (size_t)(p0 + p) * ldout + o0 + hf * (MT * 16));
        #pragma unroll
        for (int i = 0; i < MT * 4; i++) dst[i] = src[i];
    }
}

// ---------------- warp-MMA edge GEMM, MT-templated: M tile x 160 cols (8 pts x 20 k) ----------------
template<int MT>
__global__ __launch_bounds__(256, 1)
void tgemm_edge(int xoff, int C, int O, int base,
                const __nv_bfloat16* __restrict__ Wh, const __nv_bfloat16* __restrict__ Wl,
                const int* __restrict__ idx, const void* __restrict__ valid) {
    extern __shared__ __align__(1024) unsigned char dsm[];
    __shared__ int sSrc[160];
    __shared__ uint8_t sVal[160];
    const int tid = threadIdx.x, lane = tid & 31, wid = tid >> 5;
    const int wm = wid >> 2, wn = wid & 3;
    const int MTILE = MT * 32;
    const uint32_t OFF_WL = MT * 4096u, OFF_BH = MT * 8192u, OFF_BL = MT * 8192u + 20480u;
    const uint32_t BUF = MT * 8192u + 40960u;
    const int p0 = blockIdx.x * 8, o0 = blockIdx.y * MTILE;
    const uint32_t sb = s2u(dsm);

    if (tid < 160) {
        int p = p0 + tid / 20, k = tid % 20;
        int b = p >> 11;
        sSrc[tid] = (b << 11) + idx[p * K_ + k];
        sVal[tid] = (uint8_t)valid_at(valid, p * K_ + k);
    }
    __syncthreads();

    const int lr = lane & 7, g = lane >> 3;
    const uint32_t xorv = (uint32_t)lr * 16;
    const uint32_t aRow = (uint32_t)(wm * (MT * 16) + (g & 1) * 8 + lr) * 128;
    const uint32_t aSeg = (uint32_t)(g >> 1) * 16;
    const uint32_t bRow = (uint32_t)(wn * 40 + lr) * 128;
    const uint32_t bSeg = (uint32_t)(g & 1) * 16;

    float acc[MT][5][4];
    #pragma unroll
    for (int mi = 0; mi < MT; mi++)
        #pragma unroll
        for (int ni = 0; ni < 5; ni++)
            #pragma unroll
            for (int j = 0; j < 4; j++) acc[mi][ni][j] = 0.f;

    const int nch = C >> 6;
    {
        #pragma unroll
        for (int e = tid; e < MT * 256; e += 256) {
            int row = e >> 3, q = e & 7;
            uint32_t dst = SWZ((uint32_t)(row * 128 + q * 16));
            cpa16(sb + dst,          Wh + (size_t)(o0 + row) * C + q * 8);
            cpa16(sb + OFF_WL + dst, Wl + (size_t)(o0 + row) * C + q * 8);
        }
        for (int e = tid; e < 1280; e += 256) {
            int row = e >> 3, q = e & 7;
            uint32_t dst = SWZ((uint32_t)(row * 128 + q * 16));
            size_t src = (size_t)sSrc[row] * 512 + xoff + q * 8;
            cpa16(sb + OFF_BH + dst, g_xch + src);
            cpa16(sb + OFF_BL + dst, g_xcl + src);
        }
        CPA_COMMIT();
    }
    for (int ch = 0; ch < nch; ch++) {
        if (ch + 1 < nch) {
            const int c0 = (ch + 1) << 6;
            const uint32_t bo = (uint32_t)((ch + 1) & 1) * BUF;
            #pragma unroll
            for (int e = tid; e < MT * 256; e += 256) {
                int row = e >> 3, q = e & 7;
                uint32_t dst = bo + SWZ((uint32_t)(row * 128 + q * 16));
                cpa16(sb + dst,          Wh + (size_t)(o0 + row) * C + c0 + q * 8);
                cpa16(sb + OFF_WL + dst, Wl + (size_t)(o0 + row) * C + c0 + q * 8);
            }
            for (int e = tid; e < 1280; e += 256) {
                int row = e >> 3, q = e & 7;
                uint32_t dst = bo + SWZ((uint32_t)(row * 128 + q * 16));
                size_t src = (size_t)sSrc[row] * 512 + xoff + c0 + q * 8;
                cpa16(sb + OFF_BH + dst, g_xch + src);
                cpa16(sb + OFF_BL + dst, g_xcl + src);
            }
            CPA_COMMIT();
            CPA_WAIT1();
        } else {
            CPA_WAIT0();
        }
        __syncthreads();
        const uint32_t bo = (uint32_t)(ch & 1) * BUF;
        #pragma unroll
        for (int s = 0; s < 4; s++) {
            const uint32_t ofsA = bo + (((uint32_t)(s * 32) + aSeg) ^ xorv);
            const uint32_t ofsB = bo + (((uint32_t)(s * 32) + bSeg) ^ xorv);
            uint32_t ah[MT][4], al[MT][4];
            #pragma unroll
            for (int mi = 0; mi < MT; mi++) {
                ldsm4(ah[mi], sb + aRow + mi * 2048 + ofsA);
                ldsm4(al[mi], sb + OFF_WL + aRow + mi * 2048 + ofsA);
            }
            #pragma unroll
            for (int ni = 0; ni < 5; ni++) {
                uint32_t bh[2], bl[2];
                ldsm2(bh, sb + OFF_BH + bRow + ni * 1024 + ofsB);
                ldsm2(bl, sb + OFF_BL + bRow + ni * 1024 + ofsB);
                #pragma unroll
                for (int mi = 0; mi < MT; mi++) {
                    mma16816(acc[mi][ni], ah[mi], bh);
                    mma16816(acc[mi][ni], ah[mi], bl);
                    mma16816(acc[mi][ni], al[mi], bh);
                }
            }
        }
        __syncthreads();
    }

    const int lrow = lane >> 2, lcol2 = (lane & 3) * 2;
    float cp[MT][2][2];
    #pragma unroll
    for (int mi = 0; mi < MT; mi++)
        #pragma unroll
        for (int h = 0; h < 2; h++)
            #pragma unroll
            for (int pt = 0; pt < 2; pt++) {
                int o = o0 + wm * (MT * 16) + mi * 16 + h * 8 + lrow;
                cp[mi][h][pt] = g_cpart[(size_t)(p0 + wn * 2 + pt) * 256 + o];
            }
    float st[MT][2], st2[MT][2];
    float mxv[MT][2][2], mnv[MT][2][2];
    #pragma unroll
    for (int mi = 0; mi < MT; mi++)
        #pragma unroll
        for (int h = 0; h < 2; h++) {
            st[mi][h] = 0.f; st2[mi][h] = 0.f;
            #pragma unroll
            for (int pt = 0; pt < 2; pt++) { mxv[mi][h][pt] = -INFINITY; mnv[mi][h][pt] = INFINITY; }
        }
    #pragma unroll
    for (int ni = 0; ni < 5; ni++) {
        const int cl = ni * 8 + lcol2;
        const int pt = (cl >= 20) ? 1 : 0;
        const int col = wn * 40 + cl;
        const bool v0 = sVal[col] != 0, v1 = sVal[col + 1] != 0;
        #pragma unroll
        for (int mi = 0; mi < MT; mi++) {
            float h00 = acc[mi][ni][0] + cp[mi][0][pt];
            float h01 = acc[mi][ni][1] + cp[mi][0][pt];
            float h10 = acc[mi][ni][2] + cp[mi][1][pt];
            float h11 = acc[mi][ni][3] + cp[mi][1][pt];
            if (v0) {
                st[mi][0] += h00; st2[mi][0] += h00 * h00;
                st[mi][1] += h10; st2[mi][1] += h10 * h10;
                mxv[mi][0][pt] = fmaxf(mxv[mi][0][pt], h00);
                mnv[mi][0][pt] = fminf(mnv[mi][0][pt], h00);
                mxv[mi][1][pt] = fmaxf(mxv[mi][1][pt], h10);
                mnv[mi][1][pt] = fminf(mnv[mi][1][pt], h10);
            }
            if (v1) {
                st[mi][0] += h01; st2[mi][0] += h01 * h01;
                st[mi][1] += h11; st2[mi][1] += h11 * h11;
                mxv[mi][0][pt] = fmaxf(mxv[mi][0][pt], h01);
                mnv[mi][0][pt] = fminf(mnv[mi][0][pt], h01);
                mxv[mi][1][pt] = fmaxf(mxv[mi][1][pt], h11);
                mnv[mi][1][pt] = fminf(mnv[mi][1][pt], h11);
            }
        }
    }
    #pragma unroll
    for (int mi = 0; mi < MT; mi++)
        #pragma unroll
        for (int h = 0; h < 2; h++) {
            float v = st[mi][h], v2 = st2[mi][h];
            v  += __shfl_xor_sync(0xffffffffu, v, 1);
            v  += __shfl_xor_sync(0xffffffffu, v, 2);
            v2 += __shfl_xor_sync(0xffffffffu, v2, 1);
            v2 += __shfl_xor_sync(0xffffffffu, v2, 2);
            float mxr[2], mnr[2];
            #pragma unroll
            for (int pt = 0; pt < 2; pt++) {
                float a = mxv[mi][h][pt], b = mnv[mi][h][pt];
                a = fmaxf(a, __shfl_xor_sync(0xffffffffu, a, 1));
                a = fmaxf(a, __shfl_xor_sync(0xffffffffu, a, 2));
                b = fminf(b, __shfl_xor_sync(0xffffffffu, b, 1));
                b = fminf(b, __shfl_xor_sync(0xffffffffu, b, 2));
                mxr[pt] = a; mnr[pt] = b;
            }
            if ((lane & 3) == 0) {
                int o = o0 + wm * (MT * 16) + mi * 16 + h * 8 + lrow;
                atomicAdd(&g_sum[base + o], v);
                atomicAdd(&g_sumsq[base + o], v2);
                #pragma unroll
                for (int pt = 0; pt < 2; pt++) {
                    int p = p0 + wn * 2 + pt;
                    g_mx[(size_t)p * O + o] = mxr[pt];
                    g_mn[(size_t)p * O + o] = mnr[pt];
                }
            }
        }
}

// ---------------- host orchestration ----------------
extern "C" void kernel_launch(void* const* d_in, const int* in_sizes, int n_in,
                              void* d_out, int out_size) {
    const float*   x      = (const float*)d_in[0];
    const int*     idx    = (const int*)d_in[1];
    const void*    valid  = (const void*)d_in[2];
    const float* enc_w1   = (const float*)d_in[3];
    const float* enc_g1   = (const float*)d_in[4];
    const float* enc_b1   = (const float*)d_in[5];
    const float* enc_w2   = (const float*)d_in[6];
    const float* enc_g2   = (const float*)d_in[7];
    const float* enc_b2   = (const float*)d_in[8];
    const float* enc_w3   = (const float*)d_in[9];
    const float* enc_g3   = (const float*)d_in[10];
    const float* enc_b3   = (const float*)d_in[11];
    const float* enc_w4   = (const float*)d_in[12];
    const float* enc_g4   = (const float*)d_in[13];
    const float* enc_b4   = (const float*)d_in[14];
    const float* last_w   = (const float*)d_in[15];
    const float* last_g   = (const float*)d_in[16];
    const float* last_b   = (const float*)d_in[17];
    const float* emb_w1   = (const float*)d_in[18];
    const float* emb_bias1= (const float*)d_in[19];
    const float* emb_g1   = (const float*)d_in[20];
    const float* emb_b1   = (const float*)d_in[21];
    const float* emb_w2   = (const float*)d_in[22];
    const float* emb_bias2= (const float*)d_in[23];
    const float* emb_g2   = (const float*)d_in[24];
    const float* emb_b2   = (const float*)d_in[25];
    const float* out_w    = (const float*)d_in[26];
    const float* out_bias = (const float*)d_in[27];

    cudaFuncSetAttribute(tgemm_tail<false, 2>, cudaFuncAttributeMaxDynamicSharedMemorySize, 98304);
    cudaFuncSetAttribute(tgemm_tail<false, 4>, cudaFuncAttributeMaxDynamicSharedMemorySize, 131072);
    cudaFuncSetAttribute(tgemm_tail<true, 4>,  cudaFuncAttributeMaxDynamicSharedMemorySize, 131072);
    cudaFuncSetAttribute(tgemm_edge<2>, cudaFuncAttributeMaxDynamicSharedMemorySize, 114688);
    cudaFuncSetAttribute(tgemm_edge<4>, cudaFuncAttributeMaxDynamicSharedMemorySize, 147456);

    float *xt0p, *cpartp, *y1p, *y2p, *y3p, *w2p;
    __nv_bfloat16 *xchp, *xclp, *y1hp, *y1lp, *y2hp, *y2lp, *ewh, *ewl, *twh, *twl;
    cudaGetSymbolAddress((void**)&xt0p,  g_xt0);
    cudaGetSymbolAddress((void**)&cpartp,g_cpart);
    cudaGetSymbolAddress((void**)&y1p,   g_y1);
    cudaGetSymbolAddress((void**)&y2p,   g_y2);
    cudaGetSymbolAddress((void**)&y3p,   g_y3);
    cudaGetSymbolAddress((void**)&w2p,   g_w2);
    cudaGetSymbolAddress((void**)&xchp,  g_xch);
    cudaGetSymbolAddress((void**)&xclp,  g_xcl);
    cudaGetSymbolAddress((void**)&y1hp,  g_y1h);
    cudaGetSymbolAddress((void**)&y1lp,  g_y1l);
    cudaGetSymbolAddress((void**)&y2hp,  g_y2h);
    cudaGetSymbolAddress((void**)&y2lp,  g_y2l);
    cudaGetSymbolAddress((void**)&ewh,   g_ewh);
    cudaGetSymbolAddress((void**)&ewl,   g_ewl);
    cudaGetSymbolAddress((void**)&twh,   g_twh);
    cudaGetSymbolAddress((void**)&twl,   g_twl);

    k_megaprep<<<(MEGAN + 255) / 256, 256>>>(enc_w2, enc_w3, enc_w4, last_w,
                                             emb_w1, emb_w2, enc_w1);
    k_detect<<<1, 1024>>>(valid);
    k_count<<<P_ / 256, 256>>>(valid);
    k_transpose<<<P_ / 256, 256>>>(x);

    // blk0 (scalar, C=3, O=64)
    gemm_pt3<<<P_ / 64, 256>>>(xt0p, w2p, 64, 3, cpartp);
    edge_gemm0<<<P_ / 4, 256>>>(idx, valid);
    k_edge_pass2<<<(P_ * 64 + 255) / 256, 256>>>(64, 0, 0, enc_g1, enc_b1);

    // blk1 (O=64, C=64) — MT=2 exact tiles
    tgemm_tail<false, 2><<<dim3(P_ / 128, 1), 256, 98304>>>(
        xchp, xclp, ewh + EW1C, ewl + EW1C, 512, 0, 64, 256, 0, nullptr, cpartp);
    tgemm_edge<2><<<dim3(P_ / 8, 1), 256, 114688>>>(
        0, 64, 64, 1024, ewh + EW1D, ewl + EW1D, idx, valid);
    k_edge_pass2<<<(P_ * 64 + 255) / 256, 256>>>(64, 64, 1024, enc_g2, enc_b2);

    // blk2 (O=128, C=64)
    tgemm_tail<false, 4><<<dim3(P_ / 128, 1), 256, 131072>>>(
        xchp, xclp, ewh + EW2C, ewl + EW2C, 512, 64, 64, 256, 0, nullptr, cpartp);
    tgemm_edge<4><<<dim3(P_ / 8, 1), 256, 147456>>>(
        64, 64, 128, 2048, ewh + EW2D, ewl + EW2D, idx, valid);
    k_edge_pass2<<<(P_ * 128 + 255) / 256, 256>>>(128, 128, 2048, enc_g3, enc_b3);

    // blk3 (O=256, C=128)
    tgemm_tail<false, 4><<<dim3(P_ / 128, 2), 256, 131072>>>(
        xchp, xclp, ewh + EW3C, ewl + EW3C, 512, 128, 128, 256, 0, nullptr, cpartp);
    tgemm_edge<4><<<dim3(P_ / 8, 2), 256, 147456>>>(
        128, 128, 256, 3072, ewh + EW3D, ewl + EW3D, idx, valid);
    k_edge_pass2<<<(P_ * 256 + 255) / 256, 256>>>(256, 256, 3072, enc_g4, enc_b4);

    // tail
    tgemm_tail<true, 4><<<dim3(P_ / 128, 8), 256, 131072>>>(
        xchp, xclp, twh + TL, twl + TL, 512, 0, 512, 1024, 4096, nullptr, y1p);
    k_convert<<<(P_ * 1024 + 255) / 256, 256>>>(y1p, 1024, 4096, last_g, last_b, y1hp, y1lp);

    tgemm_tail<true, 4><<<dim3(P_ / 128, 4), 256, 131072>>>(
        y1hp, y1lp, twh + TE1, twl + TE1, 1024, 0, 1024, 512, 5120, emb_bias1, y2p);
    k_convert<<<(P_ * 512 + 255) / 256, 256>>>(y2p, 512, 5120, emb_g1, emb_b1, y2hp, y2lp);

    tgemm_tail<true, 4><<<dim3(P_ / 128, 1), 256, 131072>>>(
        y2hp, y2lp, twh + TE2, twl + TE2, 512, 0, 512, 128, 6144, emb_bias2, y3p);

    // out: fused input-BN scalar GEMM, transposed output
    k_gemm_out<<<P_ / 64, 256>>>(y3p, out_w, out_bias, 6144, emb_g2, emb_b2, (float*)d_out);
}

// round 7
// speedup vs baseline: 2.7389x; 1.0740x over previous
#include <cuda_runtime.h>
#include <cuda_bf16.h>
#include <cstdint>

#define B_ 8
#define N_ 2048
#define K_ 20
#define P_ (B_*N_)      // 16384
#define EPS 1e-5f

// ---------------- scratch (device globals; no runtime allocation) ----------------
__device__ __align__(128) float g_xt0 [P_*3];
__device__ __align__(128) float g_xcat[P_*512];
__device__ __align__(128) __nv_bfloat16 g_xch[P_*512];
__device__ __align__(128) __nv_bfloat16 g_xcl[P_*512];
__device__ __align__(128) float g_cpart[P_*256];        // stride 256 per point
__device__ __align__(128) float g_mx[P_*256];
__device__ __align__(128) float g_mn[P_*256];
__device__ __align__(128) float g_y1[P_*1024];
__device__ __align__(128) float g_y2[P_*512];
__device__ __align__(128) float g_y3[P_*128];
__device__ __align__(128) __nv_bfloat16 g_y1h[P_*1024];
__device__ __align__(128) __nv_bfloat16 g_y1l[P_*1024];
__device__ __align__(128) __nv_bfloat16 g_y2h[P_*512];
__device__ __align__(128) __nv_bfloat16 g_y2l[P_*512];
// weight arenas
#define EW1D 0
#define EW1C 4096
#define EW2D 8192
#define EW2C 16384
#define EW3D 24576
#define EW3C 57344
#define EW_TOT 90112
#define TL  0
#define TE1 524288
#define TE2 1048576
#define TW_TOT 1114112
__device__ __align__(128) __nv_bfloat16 g_ewh[EW_TOT];
__device__ __align__(128) __nv_bfloat16 g_ewl[EW_TOT];
__device__ __align__(128) __nv_bfloat16 g_twh[TW_TOT];
__device__ __align__(128) __nv_bfloat16 g_twl[TW_TOT];
__device__ float g_wd[192];     // blk0 fp32
__device__ float g_w2[192];
__device__ float g_sum[7168];
__device__ float g_sumsq[7168];
__device__ int     g_cnt[P_];
__device__ uint8_t g_ok[P_];
__device__ int g_totvalid;
__device__ int g_okcnt;
__device__ int g_vmode;   // 0=int32, 1=uint8, 2=float32

// ---------------- helpers ----------------
#define SWZ(x) ((x) ^ (((x) >> 3) & 0x70))
__device__ __forceinline__ uint32_t s2u(const void* p) {
    uint32_t a;
    asm("{ .reg .u64 t; cvta.to.shared.u64 t, %1; cvt.u32.u64 %0, t; }" : "=r"(a) : "l"(p));
    return a;
}
__device__ __forceinline__ void ldsm4(uint32_t* r, uint32_t a) {
    asm volatile("ldmatrix.sync.aligned.m8n8.x4.shared.b16 {%0,%1,%2,%3}, [%4];"
                 : "=r"(r[0]), "=r"(r[1]), "=r"(r[2]), "=r"(r[3]) : "r"(a));
}
__device__ __forceinline__ void ldsm2(uint32_t* r, uint32_t a) {
    asm volatile("ldmatrix.sync.aligned.m8n8.x2.shared.b16 {%0,%1}, [%2];"
                 : "=r"(r[0]), "=r"(r[1]) : "r"(a));
}
__device__ __forceinline__ void mma16816(float* c, const uint32_t* a, const uint32_t* b) {
    asm volatile("mma.sync.aligned.m16n8k16.row.col.f32.bf16.bf16.f32 "
                 "{%0,%1,%2,%3},{%4,%5,%6,%7},{%8,%9},{%0,%1,%2,%3};"
                 : "+f"(c[0]), "+f"(c[1]), "+f"(c[2]), "+f"(c[3])
                 : "r"(a[0]), "r"(a[1]), "r"(a[2]), "r"(a[3]), "r"(b[0]), "r"(b[1]));
}
__device__ __forceinline__ void cpa16(uint32_t dst, const void* src) {
    asm volatile("cp.async.cg.shared.global [%0], [%1], 16;" :: "r"(dst), "l"(src));
}
#define CPA_COMMIT() asm volatile("cp.async.commit_group;" ::: "memory")
#define CPA_WAIT1()  asm volatile("cp.async.wait_group 1;" ::: "memory")
#define CPA_WAIT0()  asm volatile("cp.async.wait_group 0;" ::: "memory")

// inline BN params from raw stats
__device__ __forceinline__ void bn_ab(int o, int base, float cnt,
                                      const float* __restrict__ gamma,
                                      const float* __restrict__ beta,
                                      float& a, float& b) {
    float n = fmaxf(cnt, 1.f);
    float s = g_sum[base + o];
    float mean = s / n;
    float var = (g_sumsq[base + o] - 2.f * mean * s + mean * mean * cnt) / n;
    a = gamma[o] * rsqrtf(fmaxf(var, 0.f) + EPS);
    b = beta[o] - mean * a;
}

// ---------------- mega-prep: all weight splits + stat zeroing in ONE launch ----------------
__global__ void k_megaprep(const float* __restrict__ w2_, const float* __restrict__ w3_,
                           const float* __restrict__ w4_, const float* __restrict__ lw,
                           const float* __restrict__ e1, const float* __restrict__ e2,
                           const float* __restrict__ w1_) {
    int i = blockIdx.x * 256 + threadIdx.x;
    if (i < EW_TOT) {
        float v;
        if (i < 4096)        { int o = i >> 6, c = i & 63; v = w2_[o * 128 + c]; }
        else if (i < 8192)   { int j = i - 4096, o = j >> 6, c = j & 63;
                               v = w2_[o * 128 + 64 + c] - w2_[o * 128 + c]; }
        else if (i < 16384)  { int j = i - 8192, o = j >> 6, c = j & 63; v = w3_[o * 128 + c]; }
        else if (i < 24576)  { int j = i - 16384, o = j >> 6, c = j & 63;
                               v = w3_[o * 128 + 64 + c] - w3_[o * 128 + c]; }
        else if (i < 57344)  { int j = i - 24576, o = j >> 7, c = j & 127; v = w4_[o * 256 + c]; }
        else                 { int j = i - 57344, o = j >> 7, c = j & 127;
                               v = w4_[o * 256 + 128 + c] - w4_[o * 256 + c]; }
        __nv_bfloat16 h = __float2bfloat16(v);
        g_ewh[i] = h;
        g_ewl[i] = __float2bfloat16(v - __bfloat162float(h));
        return;
    }
    i -= EW_TOT;
    if (i < TW_TOT) {
        float v = (i < TE1) ? lw[i] : ((i < TE2) ? e1[i - TE1] : e2[i - TE2]);
        __nv_bfloat16 h = __float2bfloat16(v);
        g_twh[i] = h;
        g_twl[i] = __float2bfloat16(v - __bfloat162float(h));
        return;
    }
    i -= TW_TOT;
    if (i < 192) {
        int o = i / 3, c = i - o * 3;
        float wd = w1_[o * 6 + c];
        g_wd[i] = wd;
        g_w2[i] = w1_[o * 6 + 3 + c] - wd;
        return;
    }
    i -= 192;
    if (i < 7168) { g_sum[i] = 0.f; g_sumsq[i] = 0.f; }
}
#define MEGAN (EW_TOT + TW_TOT + 192 + 7168)

// ---------------- valid dtype detection + accessor ----------------
__global__ void k_detect(const void* v) {
    const int nwords = (P_ * K_) / 4;
    const unsigned int* w = (const unsigned int*)v;
    __shared__ int s_not01, s_f32;
    if (threadIdx.x == 0) { s_not01 = 0; s_f32 = 0; }
    __syncthreads();
    int not01 = 0, f32 = 0;
    for (int i = threadIdx.x; i < nwords; i += blockDim.x) {
        unsigned int u = w[i];
        if (u > 1u) not01 = 1;
        if (u == 0x3F800000u) f32 = 1;
    }
    if (not01) atomicOr(&s_not01, 1);
    if (f32)   atomicOr(&s_f32, 1);
    __syncthreads();
    if (threadIdx.x == 0) {
        g_vmode = (!s_not01) ? 0 : (s_f32 ? 2 : 1);
        g_totvalid = 0;
        g_okcnt = 0;
    }
}
__device__ __forceinline__ int valid_at(const void* v, int i) {
    int m = g_vmode;
    if (m == 0) return ((const int*)v)[i] != 0;
    if (m == 1) return ((const uint8_t*)v)[i] != 0;
    return ((const float*)v)[i] != 0.0f;
}

// count valid + ok flags + transpose x, one launch
__global__ void k_count_transpose(const void* __restrict__ valid, const float* __restrict__ x) {
    int p = blockIdx.x * 256 + threadIdx.x;
    int c = 0;
    #pragma unroll
    for (int k = 0; k < K_; k++) c += valid_at(valid, p * K_ + k);
    g_cnt[p] = c;
    int okf = (c >= 1) ? 1 : 0;
    g_ok[p] = (uint8_t)okf;
    int tot = c, okc = okf;
    for (int d = 16; d; d >>= 1) {
        tot += __shfl_xor_sync(0xffffffffu, tot, d);
        okc += __shfl_xor_sync(0xffffffffu, okc, d);
    }
    if ((threadIdx.x & 31) == 0) {
        atomicAdd(&g_totvalid, tot);
        atomicAdd(&g_okcnt, okc);
    }
    int b = p >> 11, n = p & (N_ - 1);
    #pragma unroll
    for (int cc = 0; cc < 3; cc++)
        g_xt0[p * 3 + cc] = x[(b * 3 + cc) * N_ + n];
}

// BN(+lrelu) via pre-BN max/min, ok-gated, BN params inline; writes concat slabs
__global__ void k_edge_pass2(int O, int off, int base,
                             const float* __restrict__ gamma, const float* __restrict__ beta) {
    int i = blockIdx.x * 256 + threadIdx.x;
    if (i >= P_ * O) return;
    int p = i / O, o = i - p * O;
    float a, b;
    bn_ab(o, base, (float)g_totvalid, gamma, beta, a, b);
    float v = (a >= 0.f) ? g_mx[i] : g_mn[i];
    float h = a * v + b;
    h = (h >= 0.f) ? h : 0.2f * h;
    if (g_cnt[p] < 1) h = 0.f;
    int di = p * 512 + off + o;
    g_xcat[di] = h;
    __nv_bfloat16 hh = __float2bfloat16(h);
    g_xch[di] = hh;
    g_xcl[di] = __float2bfloat16(h - __bfloat162float(hh));
}

// BN+lrelu (params inline, ok-count) on point-major fp32, emit bf16 hi/lo
__global__ void k_convert(const float* __restrict__ Y, int O, int base,
                          const float* __restrict__ gamma, const float* __restrict__ beta,
                          __nv_bfloat16* __restrict__ H, __nv_bfloat16* __restrict__ L) {
    int i = blockIdx.x * 256 + threadIdx.x;
    if (i >= P_ * O) return;
    int o = i & (O - 1);
    float a, b;
    bn_ab(o, base, (float)g_okcnt, gamma, beta, a, b);
    float y = a * Y[i] + b;
    y = (y >= 0.f) ? y : 0.2f * y;
    __nv_bfloat16 h = __float2bfloat16(y);
    H[i] = h;
    L[i] = __float2bfloat16(y - __bfloat162float(h));
}

// ---------------- scalar GEMM (blk0 cpart) ----------------
__global__ __launch_bounds__(256)
void gemm_pt3(const float* __restrict__ X, const float* __restrict__ W,
              int O, int C, float* __restrict__ Y) {
    const int tid = threadIdx.x, tx = tid & 15, ty = tid >> 4;
    const int p0 = blockIdx.x * 64;
    __shared__ float sW[128 * 17];
    __shared__ float sX[16 * 64];
    float acc[8][4];
    #pragma unroll
    for (int r = 0; r < 8; r++)
        #pragma unroll
        for (int j = 0; j < 4; j++) acc[r][j] = 0.f;

    for (int c0 = 0; c0 < C; c0 += 16) {
        #pragma unroll
        for (int e = tid; e < 128 * 16; e += 256) {
            int ol = e >> 4, cc = e & 15;
            int c = c0 + cc;
            sW[ol * 17 + cc] = (ol < O && c < C) ? W[ol * C + c] : 0.f;
        }
        #pragma unroll
        for (int e = tid; e < 16 * 64; e += 256) {
            int col = e >> 4, cc = e & 15;
            int c = c0 + cc;
            sX[cc * 64 + col] = (c < C) ? X[(p0 + col) * C + c] : 0.f;
        }
        __syncthreads();
        #pragma unroll
        for (int cc = 0; cc < 16; cc++) {
            float fv[4], wv[8];
            #pragma unroll
            for (int j = 0; j < 4; j++) fv[j] = sX[cc * 64 + tx + 16 * j];
            #pragma unroll
            for (int r = 0; r < 8; r++) wv[r] = sW[(ty + 16 * r) * 17 + cc];
            #pragma unroll
            for (int r = 0; r < 8; r++)
                #pragma unroll
                for (int j = 0; j < 4; j++) acc[r][j] += wv[r] * fv[j];
        }
        __syncthreads();
    }
    #pragma unroll
    for (int r = 0; r < 8; r++) {
        int o = ty + 16 * r;
        if (o >= O) break;
        #pragma unroll
        for (int j = 0; j < 4; j++)
            Y[(p0 + tx + 16 * j) * 256 + o] = acc[r][j];
    }
}

// ---------------- final out GEMM: fused input-BN, transposed output ----------------
__global__ __launch_bounds__(256)
void k_gemm_out(const float* __restrict__ X, const float* __restrict__ W,
                const float* __restrict__ bias, int base,
                const float* __restrict__ gamma, const float* __restrict__ beta,
                float* __restrict__ Y) {
    const int O = 32, C = 128;
    const int tid = threadIdx.x, tx = tid & 15, ty = tid >> 4;
    const int p0 = blockIdx.x * 64;
    __shared__ float sW[32 * 17];
    __shared__ float sX[16 * 64];
    float acc[2][4];
    #pragma unroll
    for (int r = 0; r < 2; r++)
        #pragma unroll
        for (int j = 0; j < 4; j++) acc[r][j] = 0.f;

    const float cnt = (float)g_okcnt;
    for (int c0 = 0; c0 < C; c0 += 16) {
        for (int e = tid; e < 32 * 16; e += 256) {
            int ol = e >> 4, cc = e & 15;
            sW[ol * 17 + cc] = W[ol * C + c0 + cc];
        }
        #pragma unroll
        for (int e = tid; e < 16 * 64; e += 256) {
            int col = e >> 4, cc = e & 15;
            int c = c0 + cc;
            float a, b;
            bn_ab(c, base, cnt, gamma, beta, a, b);
            float y = a * X[(p0 + col) * C + c] + b;
            sX[cc * 64 + col] = (y >= 0.f) ? y : 0.2f * y;
        }
        __syncthreads();
        #pragma unroll
        for (int cc = 0; cc < 16; cc++) {
            float fv[4], wv[2];
            #pragma unroll
            for (int j = 0; j < 4; j++) fv[j] = sX[cc * 64 + tx + 16 * j];
            #pragma unroll
            for (int r = 0; r < 2; r++) wv[r] = sW[(ty + 16 * r) * 17 + cc];
            #pragma unroll
            for (int r = 0; r < 2; r++)
                #pragma unroll
                for (int j = 0; j < 4; j++) acc[r][j] += wv[r] * fv[j];
        }
        __syncthreads();
    }
    #pragma unroll
    for (int r = 0; r < 2; r++) {
        int o = ty + 16 * r;
        float bs = bias[o];
        #pragma unroll
        for (int j = 0; j < 4; j++) {
            int p = p0 + tx + 16 * j;
            int b = p >> 11, n = p & (N_ - 1);
            Y[(b * O + o) * N_ + n] = acc[r][j] + bs;
        }
    }
}

// ---------------- scalar gather edge GEMM (blk0, C=3) ----------------
__global__ __launch_bounds__(256)
void edge_gemm0(const int* __restrict__ idx, const void* __restrict__ valid) {
    const int C = 3, O = 64;
    const int tid = threadIdx.x, tx = tid & 15, ty = tid >> 4;
    const int p0 = blockIdx.x * 4;
    __shared__ float sW[64 * 17];
    __shared__ float sF[16 * 80];
    __shared__ int sSrc[80];
    __shared__ uint8_t sVal[80];
    __shared__ float sC[4 * 64];

    if (tid < 80) {
        int pt = tid / 20, k = tid - pt * 20;
        int p = p0 + pt, b = p >> 11;
        sSrc[tid] = (b << 11) + idx[p * K_ + k];
        sVal[tid] = (uint8_t)valid_at(valid, p * K_ + k);
    }
    if (tid < 256) {
        int pt = tid >> 6, ol = tid & 63;
        sC[tid] = g_cpart[(p0 + pt) * 256 + ol];
    }
    for (int e = tid; e < 64 * 16; e += 256) {
        int ol = e >> 4, cc = e & 15;
        sW[ol * 17 + cc] = (cc < C) ? g_wd[ol * C + cc] : 0.f;
    }
    __syncthreads();
    for (int e = tid; e < 16 * 80; e += 256) {
        int col = e >> 4, cc = e & 15;
        sF[cc * 80 + col] = (cc < C) ? g_xt0[sSrc[col] * 3 + cc] : 0.f;
    }
    __syncthreads();

    float acc[4][5];
    #pragma unroll
    for (int r = 0; r < 4; r++)
        #pragma unroll
        for (int j = 0; j < 5; j++) acc[r][j] = 0.f;
    #pragma unroll
    for (int cc = 0; cc < 3; cc++) {
        float fv[5], wv[4];
        #pragma unroll
        for (int j = 0; j < 5; j++) fv[j] = sF[cc * 80 + tx * 5 + j];
        #pragma unroll
        for (int r = 0; r < 4; r++) wv[r] = sW[(ty + 16 * r) * 17 + cc];
        #pragma unroll
        for (int r = 0; r < 4; r++)
            #pragma unroll
            for (int j = 0; j < 5; j++) acc[r][j] += wv[r] * fv[j];
    }

    const int myPt = tx >> 2;
    const int cbase = tx * 5;
    #pragma unroll
    for (int r = 0; r < 4; r++) {
        int o = ty + 16 * r;
        float cp = sC[myPt * 64 + o];
        float s = 0.f, s2 = 0.f;
        float vmx = -INFINITY, vmn = INFINITY;
        #pragma unroll
        for (int j = 0; j < 5; j++) {
            int col = cbase + j;
            float h = acc[r][j] + cp;
            if (sVal[col]) {
                s += h; s2 += h * h;
                vmx = fmaxf(vmx, h);
                vmn = fminf(vmn, h);
            }
        }
        for (int d = 1; d < 16; d <<= 1) {
            s  += __shfl_xor_sync(0xffffffffu, s,  d);
            s2 += __shfl_xor_sync(0xffffffffu, s2, d);
        }
        for (int d = 1; d < 4; d <<= 1) {
            vmx = fmaxf(vmx, __shfl_xor_sync(0xffffffffu, vmx, d));
            vmn = fminf(vmn, __shfl_xor_sync(0xffffffffu, vmn, d));
        }
        if (tx == 0) {
            atomicAdd(&g_sum[o], s);
            atomicAdd(&g_sumsq[o], s2);
        }
        if ((tx & 3) == 0) {
            int p = p0 + myPt;
            g_mx[p * O + o] = vmx;
            g_mn[p * O + o] = vmn;
        }
    }
}

// ---------------- warp-MMA dense GEMM, MT=2 (64-row o-tile), double-buffered ----------------
template<bool STATS>
__global__ __launch_bounds__(256, 2)
void tgemm_tail(const __nv_bfloat16* __restrict__ Xhi, const __nv_bfloat16* __restrict__ Xlo,
                const __nv_bfloat16* __restrict__ Wh, const __nv_bfloat16* __restrict__ Wl,
                int ldx, int xoff, int C, int ldout, int base,
                const float* __restrict__ bias, float* __restrict__ Y) {
    const int MT = 2;
    extern __shared__ __align__(1024) unsigned char dsm[];
    __shared__ uint8_t sOk[128];
    const int tid = threadIdx.x, lane = tid & 31, wid = tid >> 5;
    const int wm = wid >> 2, wn = wid & 3;
    const uint32_t OFF_WL = 8192u, OFF_XH = 16384u, OFF_XL = 32768u;
    const uint32_t BUF = 49152u;
    const int p0 = blockIdx.x * 128, o0 = blockIdx.y * 64;
    const uint32_t sb = s2u(dsm);
    if (STATS && tid < 128) sOk[tid] = g_ok[p0 + tid];

    const int lr = lane & 7, g = lane >> 3;
    const uint32_t xorv = (uint32_t)lr * 16;
    const uint32_t aRow = (uint32_t)(wm * 32 + (g & 1) * 8 + lr) * 128;
    const uint32_t aSeg = (uint32_t)(g >> 1) * 16;
    const uint32_t bRow = (uint32_t)(wn * 32 + lr) * 128;
    const uint32_t bSeg = (uint32_t)(g & 1) * 16;

    float acc[MT][4][4];
    #pragma unroll
    for (int mi = 0; mi < MT; mi++)
        #pragma unroll
        for (int ni = 0; ni < 4; ni++)
            #pragma unroll
            for (int j = 0; j < 4; j++) acc[mi][ni][j] = 0.f;

    const int nch = C >> 6;
    {
        #pragma unroll
        for (int e = tid; e < 512; e += 256) {
            int row = e >> 3, q = e & 7;
            uint32_t dst = SWZ((uint32_t)(row * 128 + q * 16));
            cpa16(sb + dst,          Wh + (size_t)(o0 + row) * C + q * 8);
            cpa16(sb + OFF_WL + dst, Wl + (size_t)(o0 + row) * C + q * 8);
        }
        #pragma unroll
        for (int e = tid; e < 1024; e += 256) {
            int row = e >> 3, q = e & 7;
            uint32_t dst = SWZ((uint32_t)(row * 128 + q * 16));
            cpa16(sb + OFF_XH + dst, Xhi + (size_t)(p0 + row) * ldx + xoff + q * 8);
            cpa16(sb + OFF_XL + dst, Xlo + (size_t)(p0 + row) * ldx + xoff + q * 8);
        }
        CPA_COMMIT();
    }
    for (int ch = 0; ch < nch; ch++) {
        if (ch + 1 < nch) {
            const int c0 = (ch + 1) << 6;
            const uint32_t bo = (uint32_t)((ch + 1) & 1) * BUF;
            #pragma unroll
            for (int e = tid; e < 512; e += 256) {
                int row = e >> 3, q = e & 7;
                uint32_t dst = bo + SWZ((uint32_t)(row * 128 + q * 16));
                cpa16(sb + dst,          Wh + (size_t)(o0 + row) * C + c0 + q * 8);
                cpa16(sb + OFF_WL + dst, Wl + (size_t)(o0 + row) * C + c0 + q * 8);
            }
            #pragma unroll
            for (int e = tid; e < 1024; e += 256) {
                int row = e >> 3, q = e & 7;
                uint32_t dst = bo + SWZ((uint32_t)(row * 128 + q * 16));
                cpa16(sb + OFF_XH + dst, Xhi + (size_t)(p0 + row) * ldx + xoff + c0 + q * 8);
                cpa16(sb + OFF_XL + dst, Xlo + (size_t)(p0 + row) * ldx + xoff + c0 + q * 8);
            }
            CPA_COMMIT();
            CPA_WAIT1();
        } else {
            CPA_WAIT0();
        }
        __syncthreads();
        const uint32_t bo = (uint32_t)(ch & 1) * BUF;
        #pragma unroll
        for (int s = 0; s < 4; s++) {
            const uint32_t ofsA = bo + (((uint32_t)(s * 32) + aSeg) ^ xorv);
            const uint32_t ofsB = bo + (((uint32_t)(s * 32) + bSeg) ^ xorv);
            uint32_t ah[MT][4], al[MT][4], bh[4][2], bl[4][2];
            #pragma unroll
            for (int mi = 0; mi < MT; mi++) {
                ldsm4(ah[mi], sb + aRow + mi * 2048 + ofsA);
                ldsm4(al[mi], sb + OFF_WL + aRow + mi * 2048 + ofsA);
            }
            #pragma unroll
            for (int ni = 0; ni < 4; ni++) {
                ldsm2(bh[ni], sb + OFF_XH + bRow + ni * 1024 + ofsB);
                ldsm2(bl[ni], sb + OFF_XL + bRow + ni * 1024 + ofsB);
            }
            #pragma unroll
            for (int mi = 0; mi < MT; mi++)
                #pragma unroll
                for (int ni = 0; ni < 4; ni++) {
                    mma16816(acc[mi][ni], ah[mi], bh[ni]);
                    mma16816(acc[mi][ni], ah[mi], bl[ni]);
                    mma16816(acc[mi][ni], al[mi], bh[ni]);
                }
        }
        __syncthreads();
    }

    const int lrow = lane >> 2, lcol2 = (lane & 3) * 2;
    const int STR = 68;
    float bias_r[MT][2];
    #pragma unroll
    for (int mi = 0; mi < MT; mi++)
        #pragma unroll
        for (int h = 0; h < 2; h++) {
            int o = o0 + wm * 32 + mi * 16 + h * 8 + lrow;
            bias_r[mi][h] = (bias != nullptr) ? bias[o] : 0.f;
        }
    float st[MT][2], st2[MT][2];
    #pragma unroll
    for (int mi = 0; mi < MT; mi++)
        #pragma unroll
        for (int h = 0; h < 2; h++) { st[mi][h] = 0.f; st2[mi][h] = 0.f; }

    float* sT = (float*)dsm;
    #pragma unroll
    for (int mi = 0; mi < MT; mi++) {
        const int ro = wm * 32 + mi * 16 + lrow;
        #pragma unroll
        for (int ni = 0; ni < 4; ni++) {
            const int cp0 = wn * 32 + ni * 8 + lcol2;
            float y00 = acc[mi][ni][0] + bias_r[mi][0];
            float y01 = acc[mi][ni][1] + bias_r[mi][0];
            float y10 = acc[mi][ni][2] + bias_r[mi][1];
            float y11 = acc[mi][ni][3] + bias_r[mi][1];
            if (STATS) {
                if (sOk[cp0])     { st[mi][0] += y00; st2[mi][0] += y00 * y00;
                                    st[mi][1] += y10; st2[mi][1] += y10 * y10; }
                if (sOk[cp0 + 1]) { st[mi][0] += y01; st2[mi][0] += y01 * y01;
                                    st[mi][1] += y11; st2[mi][1] += y11 * y11; }
            }
            sT[cp0 * STR + ro]           = y00;
            sT[(cp0 + 1) * STR + ro]     = y01;
            sT[cp0 * STR + ro + 8]       = y10;
            sT[(cp0 + 1) * STR + ro + 8] = y11;
        }
    }
    if (STATS) {
        #pragma unroll
        for (int mi = 0; mi < MT; mi++)
            #pragma unroll
            for (int h = 0; h < 2; h++) {
                float v = st[mi][h], v2 = st2[mi][h];
                v  += __shfl_xor_sync(0xffffffffu, v, 1);
                v  += __shfl_xor_sync(0xffffffffu, v, 2);
                v2 += __shfl_xor_sync(0xffffffffu, v2, 1);
                v2 += __shfl_xor_sync(0xffffffffu, v2, 2);
                if ((lane & 3) == 0) {
                    int o = o0 + wm * 32 + mi * 16 + h * 8 + lrow;
                    atomicAdd(&g_sum[base + o], v);
                    atomicAdd(&g_sumsq[base + o], v2);
                }
            }
    }
    __syncthreads();
    {
        int p = tid >> 1, hf = tid & 1;
        const float4* src = (const float4*)(sT + p * STR + hf * 32);
        float4* dst = (float4*)(Y + (size_t)(p0 + p) * ldout + o0 + hf * 32);
        #pragma unroll
        for (int i = 0; i < 8; i++) dst[i] = src[i];
    }
}

// ---------------- warp-MMA edge GEMM, MT=2, single-buffer, NCH chunks ----------------
// smem 57344: WH[0,8K) WL[8K,16K) BH[16K,36.5K) BL[36.5K,56.5K)
template<int NCH>
__global__ __launch_bounds__(256, 2)
void tgemm_edge(int xoff, int O, int base,
                const __nv_bfloat16* __restrict__ Wh, const __nv_bfloat16* __restrict__ Wl,
                const int* __restrict__ idx, const void* __restrict__ valid) {
    const int MT = 2;
    extern __shared__ __align__(1024) unsigned char dsm[];
    __shared__ int sSrc[160];
    __shared__ uint8_t sVal[160];
    const int tid = threadIdx.x, lane = tid & 31, wid = tid >> 5;
    const int wm = wid >> 2, wn = wid & 3;
    const uint32_t OFF_WL = 8192u, OFF_BH = 16384u, OFF_BL = 36864u;
    const int C = NCH * 64;
    const int p0 = blockIdx.x * 8, o0 = blockIdx.y * 64;
    const uint32_t sb = s2u(dsm);

    if (tid < 160) {
        int p = p0 + tid / 20, k = tid % 20;
        int b = p >> 11;
        sSrc[tid] = (b << 11) + idx[p * K_ + k];
        sVal[tid] = (uint8_t)valid_at(valid, p * K_ + k);
    }
    __syncthreads();

    const int lr = lane & 7, g = lane >> 3;
    const uint32_t xorv = (uint32_t)lr * 16;
    const uint32_t aRow = (uint32_t)(wm * 32 + (g & 1) * 8 + lr) * 128;
    const uint32_t aSeg = (uint32_t)(g >> 1) * 16;
    const uint32_t bRow = (uint32_t)(wn * 40 + lr) * 128;
    const uint32_t bSeg = (uint32_t)(g & 1) * 16;

    float acc[MT][5][4];
    #pragma unroll
    for (int mi = 0; mi < MT; mi++)
        #pragma unroll
        for (int ni = 0; ni < 5; ni++)
            #pragma unroll
            for (int j = 0; j < 4; j++) acc[mi][ni][j] = 0.f;

    // prefetch chunk 0
    {
        #pragma unroll
        for (int e = tid; e < 512; e += 256) {
            int row = e >> 3, q = e & 7;
            uint32_t dst = SWZ((uint32_t)(row * 128 + q * 16));
            cpa16(sb + dst,          Wh + (size_t)(o0 + row) * C + q * 8);
            cpa16(sb + OFF_WL + dst, Wl + (size_t)(o0 + row) * C + q * 8);
        }
        for (int e = tid; e < 1280; e += 256) {
            int row = e >> 3, q = e & 7;
            uint32_t dst = SWZ((uint32_t)(row * 128 + q * 16));
            size_t src = (size_t)sSrc[row] * 512 + xoff + q * 8;
            cpa16(sb + OFF_BH + dst, g_xch + src);
            cpa16(sb + OFF_BL + dst, g_xcl + src);
        }
        CPA_COMMIT();
    }
    #pragma unroll
    for (int ch = 0; ch < NCH; ch++) {
        CPA_WAIT0();
        __syncthreads();
        #pragma unroll
        for (int s = 0; s < 4; s++) {
            const uint32_t ofsA = ((uint32_t)(s * 32) + aSeg) ^ xorv;
            const uint32_t ofsB = ((uint32_t)(s * 32) + bSeg) ^ xorv;
            uint32_t ah[MT][4], al[MT][4];
            #pragma unroll
            for (int mi = 0; mi < MT; mi++) {
                ldsm4(ah[mi], sb + aRow + mi * 2048 + ofsA);
                ldsm4(al[mi], sb + OFF_WL + aRow + mi * 2048 + ofsA);
            }
            #pragma unroll
            for (int ni = 0; ni < 5; ni++) {
                uint32_t bh[2], bl[2];
                ldsm2(bh, sb + OFF_BH + bRow + ni * 1024 + ofsB);
                ldsm2(bl, sb + OFF_BL + bRow + ni * 1024 + ofsB);
                #pragma unroll
                for (int mi = 0; mi < MT; mi++) {
                    mma16816(acc[mi][ni], ah[mi], bh);
                    mma16816(acc[mi][ni], ah[mi], bl);
                    mma16816(acc[mi][ni], al[mi], bh);
                }
            }
        }
        __syncthreads();
        if (ch + 1 < NCH) {
            const int c0 = (ch + 1) << 6;
            #pragma unroll
            for (int e = tid; e < 512; e += 256) {
                int row = e >> 3, q = e & 7;
                uint32_t dst = SWZ((uint32_t)(row * 128 + q * 16));
                cpa16(sb + dst,          Wh + (size_t)(o0 + row) * C + c0 + q * 8);
                cpa16(sb + OFF_WL + dst, Wl + (size_t)(o0 + row) * C + c0 + q * 8);
            }
            for (int e = tid; e < 1280; e += 256) {
                int row = e >> 3, q = e & 7;
                uint32_t dst = SWZ((uint32_t)(row * 128 + q * 16));
                size_t src = (size_t)sSrc[row] * 512 + xoff + c0 + q * 8;
                cpa16(sb + OFF_BH + dst, g_xch + src);
                cpa16(sb + OFF_BL + dst, g_xcl + src);
            }
            CPA_COMMIT();
        }
    }

    const int lrow = lane >> 2, lcol2 = (lane & 3) * 2;
    float cp[MT][2][2];
    #pragma unroll
    for (int mi = 0; mi < MT; mi++)
        #pragma unroll
        for (int h = 0; h < 2; h++)
            #pragma unroll
            for (int pt = 0; pt < 2; pt++) {
                int o = o0 + wm * 32 + mi * 16 + h * 8 + lrow;
                cp[mi][h][pt] = g_cpart[(size_t)(p0 + wn * 2 + pt) * 256 + o];
            }
    float st[MT][2], st2[MT][2];
    float mxv[MT][2][2], mnv[MT][2][2];
    #pragma unroll
    for (int mi = 0; mi < MT; mi++)
        #pragma unroll
        for (int h = 0; h < 2; h++) {
            st[mi][h] = 0.f; st2[mi][h] = 0.f;
            #pragma unroll
            for (int pt = 0; pt < 2; pt++) { mxv[mi][h][pt] = -INFINITY; mnv[mi][h][pt] = INFINITY; }
        }
    #pragma unroll
    for (int ni = 0; ni < 5; ni++) {
        const int cl = ni * 8 + lcol2;
        const int pt = (cl >= 20) ? 1 : 0;
        const int col = wn * 40 + cl;
        const bool v0 = sVal[col] != 0, v1 = sVal[col + 1] != 0;
        #pragma unroll
        for (int mi = 0; mi < MT; mi++) {
            float h00 = acc[mi][ni][0] + cp[mi][0][pt];
            float h01 = acc[mi][ni][1] + cp[mi][0][pt];
            float h10 = acc[mi][ni][2] + cp[mi][1][pt];
            float h11 = acc[mi][ni][3] + cp[mi][1][pt];
            if (v0) {
                st[mi][0] += h00; st2[mi][0] += h00 * h00;
                st[mi][1] += h10; st2[mi][1] += h10 * h10;
                mxv[mi][0][pt] = fmaxf(mxv[mi][0][pt], h00);
                mnv[mi][0][pt] = fminf(mnv[mi][0][pt], h00);
                mxv[mi][1][pt] = fmaxf(mxv[mi][1][pt], h10);
                mnv[mi][1][pt] = fminf(mnv[mi][1][pt], h10);
            }
            if (v1) {
                st[mi][0] += h01; st2[mi][0] += h01 * h01;
                st[mi][1] += h11; st2[mi][1] += h11 * h11;
                mxv[mi][0][pt] = fmaxf(mxv[mi][0][pt], h01);
                mnv[mi][0][pt] = fminf(mnv[mi][0][pt], h01);
                mxv[mi][1][pt] = fmaxf(mxv[mi][1][pt], h11);
                mnv[mi][1][pt] = fminf(mnv[mi][1][pt], h11);
            }
        }
    }
    #pragma unroll
    for (int mi = 0; mi < MT; mi++)
        #pragma unroll
        for (int h = 0; h < 2; h++) {
            float v = st[mi][h], v2 = st2[mi][h];
            v  += __shfl_xor_sync(0xffffffffu, v, 1);
            v  += __shfl_xor_sync(0xffffffffu, v, 2);
            v2 += __shfl_xor_sync(0xffffffffu, v2, 1);
            v2 += __shfl_xor_sync(0xffffffffu, v2, 2);
            float mxr[2], mnr[2];
            #pragma unroll
            for (int pt = 0; pt < 2; pt++) {
                float a = mxv[mi][h][pt], b = mnv[mi][h][pt];
                a = fmaxf(a, __shfl_xor_sync(0xffffffffu, a, 1));
                a = fmaxf(a, __shfl_xor_sync(0xffffffffu, a, 2));
                b = fminf(b, __shfl_xor_sync(0xffffffffu, b, 1));
                b = fminf(b, __shfl_xor_sync(0xffffffffu, b, 2));
                mxr[pt] = a; mnr[pt] = b;
            }
            if ((lane & 3) == 0) {
                int o = o0 + wm * 32 + mi * 16 + h * 8 + lrow;
                atomicAdd(&g_sum[base + o], v);
                atomicAdd(&g_sumsq[base + o], v2);
                #pragma unroll
                for (int pt = 0; pt < 2; pt++) {
                    int p = p0 + wn * 2 + pt;
                    g_mx[(size_t)p * O + o] = mxr[pt];
                    g_mn[(size_t)p * O + o] = mnr[pt];
                }
            }
        }
}

// ---------------- host orchestration ----------------
extern "C" void kernel_launch(void* const* d_in, const int* in_sizes, int n_in,
                              void* d_out, int out_size) {
    const float*   x      = (const float*)d_in[0];
    const int*     idx    = (const int*)d_in[1];
    const void*    valid  = (const void*)d_in[2];
    const float* enc_w1   = (const float*)d_in[3];
    const float* enc_g1   = (const float*)d_in[4];
    const float* enc_b1   = (const float*)d_in[5];
    const float* enc_w2   = (const float*)d_in[6];
    const float* enc_g2   = (const float*)d_in[7];
    const float* enc_b2   = (const float*)d_in[8];
    const float* enc_w3   = (const float*)d_in[9];
    const float* enc_g3   = (const float*)d_in[10];
    const float* enc_b3   = (const float*)d_in[11];
    const float* enc_w4   = (const float*)d_in[12];
    const float* enc_g4   = (const float*)d_in[13];
    const float* enc_b4   = (const float*)d_in[14];
    const float* last_w   = (const float*)d_in[15];
    const float* last_g   = (const float*)d_in[16];
    const float* last_b   = (const float*)d_in[17];
    const float* emb_w1   = (const float*)d_in[18];
    const float* emb_bias1= (const float*)d_in[19];
    const float* emb_g1   = (const float*)d_in[20];
    const float* emb_b1   = (const float*)d_in[21];
    const float* emb_w2   = (const float*)d_in[22];
    const float* emb_bias2= (const float*)d_in[23];
    const float* emb_g2   = (const float*)d_in[24];
    const float* emb_b2   = (const float*)d_in[25];
    const float* out_w    = (const float*)d_in[26];
    const float* out_bias = (const float*)d_in[27];

    cudaFuncSetAttribute(tgemm_tail<false>, cudaFuncAttributeMaxDynamicSharedMemorySize, 98304);
    cudaFuncSetAttribute(tgemm_tail<true>,  cudaFuncAttributeMaxDynamicSharedMemorySize, 98304);
    cudaFuncSetAttribute(tgemm_edge<1>, cudaFuncAttributeMaxDynamicSharedMemorySize, 57344);
    cudaFuncSetAttribute(tgemm_edge<2>, cudaFuncAttributeMaxDynamicSharedMemorySize, 57344);

    float *xt0p, *cpartp, *y1p, *y2p, *y3p, *w2p;
    __nv_bfloat16 *xchp, *xclp, *y1hp, *y1lp, *y2hp, *y2lp, *ewh, *ewl, *twh, *twl;
    cudaGetSymbolAddress((void**)&xt0p,  g_xt0);
    cudaGetSymbolAddress((void**)&cpartp,g_cpart);
    cudaGetSymbolAddress((void**)&y1p,   g_y1);
    cudaGetSymbolAddress((void**)&y2p,   g_y2);
    cudaGetSymbolAddress((void**)&y3p,   g_y3);
    cudaGetSymbolAddress((void**)&w2p,   g_w2);
    cudaGetSymbolAddress((void**)&xchp,  g_xch);
    cudaGetSymbolAddress((void**)&xclp,  g_xcl);
    cudaGetSymbolAddress((void**)&y1hp,  g_y1h);
    cudaGetSymbolAddress((void**)&y1lp,  g_y1l);
    cudaGetSymbolAddress((void**)&y2hp,  g_y2h);
    cudaGetSymbolAddress((void**)&y2lp,  g_y2l);
    cudaGetSymbolAddress((void**)&ewh,   g_ewh);
    cudaGetSymbolAddress((void**)&ewl,   g_ewl);
    cudaGetSymbolAddress((void**)&twh,   g_twh);
    cudaGetSymbolAddress((void**)&twl,   g_twl);

    k_megaprep<<<(MEGAN + 255) / 256, 256>>>(enc_w2, enc_w3, enc_w4, last_w,
                                             emb_w1, emb_w2, enc_w1);
    k_detect<<<1, 1024>>>(valid);
    k_count_transpose<<<P_ / 256, 256>>>(valid, x);

    // blk0 (scalar, C=3, O=64)
    gemm_pt3<<<P_ / 64, 256>>>(xt0p, w2p, 64, 3, cpartp);
    edge_gemm0<<<P_ / 4, 256>>>(idx, valid);
    k_edge_pass2<<<(P_ * 64 + 255) / 256, 256>>>(64, 0, 0, enc_g1, enc_b1);

    // blk1 (O=64, C=64)
    tgemm_tail<false><<<dim3(P_ / 128, 1), 256, 98304>>>(
        xchp, xclp, ewh + EW1C, ewl + EW1C, 512, 0, 64, 256, 0, nullptr, cpartp);
    tgemm_edge<1><<<dim3(P_ / 8, 1), 256, 57344>>>(
        0, 64, 1024, ewh + EW1D, ewl + EW1D, idx, valid);
    k_edge_pass2<<<(P_ * 64 + 255) / 256, 256>>>(64, 64, 1024, enc_g2, enc_b2);

    // blk2 (O=128, C=64)
    tgemm_tail<false><<<dim3(P_ / 128, 2), 256, 98304>>>(
        xchp, xclp, ewh + EW2C, ewl + EW2C, 512, 64, 64, 256, 0, nullptr, cpartp);
    tgemm_edge<1><<<dim3(P_ / 8, 2), 256, 57344>>>(
        64, 128, 2048, ewh + EW2D, ewl + EW2D, idx, valid);
    k_edge_pass2<<<(P_ * 128 + 255) / 256, 256>>>(128, 128, 2048, enc_g3, enc_b3);

    // blk3 (O=256, C=128)
    tgemm_tail<false><<<dim3(P_ / 128, 4), 256, 98304>>>(
        xchp, xclp, ewh + EW3C, ewl + EW3C, 512, 128, 128, 256, 0, nullptr, cpartp);
    tgemm_edge<2><<<dim3(P_ / 8, 4), 256, 57344>>>(
        128, 256, 3072, ewh + EW3D, ewl + EW3D, idx, valid);
    k_edge_pass2<<<(P_ * 256 + 255) / 256, 256>>>(256, 256, 3072, enc_g4, enc_b4);

    // tail
    tgemm_tail<true><<<dim3(P_ / 128, 16), 256, 98304>>>(
        xchp, xclp, twh + TL, twl + TL, 512, 0, 512, 1024, 4096, nullptr, y1p);
    k_convert<<<(P_ * 1024 + 255) / 256, 256>>>(y1p, 1024, 4096, last_g, last_b, y1hp, y1lp);

    tgemm_tail<true><<<dim3(P_ / 128, 8), 256, 98304>>>(
        y1hp, y1lp, twh + TE1, twl + TE1, 1024, 0, 1024, 512, 5120, emb_bias1, y2p);
    k_convert<<<(P_ * 512 + 255) / 256, 256>>>(y2p, 512, 5120, emb_g1, emb_b1, y2hp, y2lp);

    tgemm_tail<true><<<dim3(P_ / 128, 2), 256, 98304>>>(
        y2hp, y2lp, twh + TE2, twl + TE2, 512, 0, 512, 128, 6144, emb_bias2, y3p);

    // out: fused input-BN scalar GEMM, transposed output
    k_gemm_out<<<P_ / 64, 256>>>(y3p, out_w, out_bias, 6144, emb_g2, emb_b2, (float*)d_out);
}

// round 8
// speedup vs baseline: 2.9090x; 1.0621x over previous
#include <cuda_runtime.h>
#include <cuda_bf16.h>
#include <cstdint>

#define B_ 8
#define N_ 2048
#define K_ 20
#define P_ (B_*N_)      // 16384
#define EPS 1e-5f

// ---------------- scratch (device globals; no runtime allocation) ----------------
__device__ __align__(128) float g_xt0 [P_*3];
__device__ __align__(128) float g_xcat[P_*512];
__device__ __align__(128) __nv_bfloat16 g_xch[P_*512];
__device__ __align__(128) __nv_bfloat16 g_xcl[P_*512];
__device__ __align__(128) float g_cpart[P_*256];        // stride 256 per point
__device__ __align__(128) float g_mx[P_*256];
__device__ __align__(128) float g_mn[P_*256];
__device__ __align__(128) float g_y1[P_*1024];
__device__ __align__(128) float g_y2[P_*512];
__device__ __align__(128) float g_y3[P_*128];
__device__ __align__(128) __nv_bfloat16 g_y1h[P_*1024];
__device__ __align__(128) __nv_bfloat16 g_y1l[P_*1024];
__device__ __align__(128) __nv_bfloat16 g_y2h[P_*512];
__device__ __align__(128) __nv_bfloat16 g_y2l[P_*512];
// weight arenas
#define EW1D 0
#define EW1C 4096
#define EW2D 8192
#define EW2C 16384
#define EW3D 24576
#define EW3C 57344
#define EW_TOT 90112
#define TL  0
#define TE1 524288
#define TE2 1048576
#define TW_TOT 1114112
__device__ __align__(128) __nv_bfloat16 g_ewh[EW_TOT];
__device__ __align__(128) __nv_bfloat16 g_ewl[EW_TOT];
__device__ __align__(128) __nv_bfloat16 g_twh[TW_TOT];
__device__ __align__(128) __nv_bfloat16 g_twl[TW_TOT];
__device__ float g_wd[192];     // blk0 fp32
__device__ float g_w2[192];
__device__ float g_sum[7168];
__device__ float g_sumsq[7168];
__device__ int     g_cnt[P_];
__device__ uint8_t g_ok[P_];
__device__ int g_totvalid;
__device__ int g_okcnt;
__device__ int g_vmode;   // 0=int32, 1=uint8, 2=float32

// ---------------- helpers ----------------
#define SWZ(x) ((x) ^ (((x) >> 3) & 0x70))
__device__ __forceinline__ uint32_t s2u(const void* p) {
    uint32_t a;
    asm("{ .reg .u64 t; cvta.to.shared.u64 t, %1; cvt.u32.u64 %0, t; }" : "=r"(a) : "l"(p));
    return a;
}
__device__ __forceinline__ void ldsm4(uint32_t* r, uint32_t a) {
    asm volatile("ldmatrix.sync.aligned.m8n8.x4.shared.b16 {%0,%1,%2,%3}, [%4];"
                 : "=r"(r[0]), "=r"(r[1]), "=r"(r[2]), "=r"(r[3]) : "r"(a));
}
__device__ __forceinline__ void ldsm2(uint32_t* r, uint32_t a) {
    asm volatile("ldmatrix.sync.aligned.m8n8.x2.shared.b16 {%0,%1}, [%2];"
                 : "=r"(r[0]), "=r"(r[1]) : "r"(a));
}
__device__ __forceinline__ void mma16816(float* c, const uint32_t* a, const uint32_t* b) {
    asm volatile("mma.sync.aligned.m16n8k16.row.col.f32.bf16.bf16.f32 "
                 "{%0,%1,%2,%3},{%4,%5,%6,%7},{%8,%9},{%0,%1,%2,%3};"
                 : "+f"(c[0]), "+f"(c[1]), "+f"(c[2]), "+f"(c[3])
                 : "r"(a[0]), "r"(a[1]), "r"(a[2]), "r"(a[3]), "r"(b[0]), "r"(b[1]));
}
__device__ __forceinline__ void cpa16(uint32_t dst, const void* src) {
    asm volatile("cp.async.cg.shared.global [%0], [%1], 16;" :: "r"(dst), "l"(src));
}
#define CPA_COMMIT() asm volatile("cp.async.commit_group;" ::: "memory")
#define CPA_WAIT0()  asm volatile("cp.async.wait_group 0;" ::: "memory")

// inline BN params from raw stats
__device__ __forceinline__ void bn_ab(int o, int base, float cnt,
                                      const float* __restrict__ gamma,
                                      const float* __restrict__ beta,
                                      float& a, float& b) {
    float n = fmaxf(cnt, 1.f);
    float s = g_sum[base + o];
    float mean = s / n;
    float var = (g_sumsq[base + o] - 2.f * mean * s + mean * mean * cnt) / n;
    a = gamma[o] * rsqrtf(fmaxf(var, 0.f) + EPS);
    b = beta[o] - mean * a;
}
// vectorized: 4 consecutive channels
__device__ __forceinline__ void bn_ab4(int o, int base, float cnt,
                                       const float* __restrict__ gamma,
                                       const float* __restrict__ beta,
                                       float* a, float* b) {
    float n = fmaxf(cnt, 1.f);
    float4 s4  = *(const float4*)(g_sum + base + o);
    float4 q4  = *(const float4*)(g_sumsq + base + o);
    float4 gm4 = *(const float4*)(gamma + o);
    float4 bt4 = *(const float4*)(beta + o);
    float ss[4] = {s4.x, s4.y, s4.z, s4.w};
    float qq[4] = {q4.x, q4.y, q4.z, q4.w};
    float gg[4] = {gm4.x, gm4.y, gm4.z, gm4.w};
    float bb[4] = {bt4.x, bt4.y, bt4.z, bt4.w};
    #pragma unroll
    for (int j = 0; j < 4; j++) {
        float mean = ss[j] / n;
        float var = (qq[j] - 2.f * mean * ss[j] + mean * mean * cnt) / n;
        a[j] = gg[j] * rsqrtf(fmaxf(var, 0.f) + EPS);
        b[j] = bb[j] - mean * a[j];
    }
}

// ---------------- mega-prep: all weight splits + stat zeroing in ONE launch ----------------
__global__ void k_megaprep(const float* __restrict__ w2_, const float* __restrict__ w3_,
                           const float* __restrict__ w4_, const float* __restrict__ lw,
                           const float* __restrict__ e1, const float* __restrict__ e2,
                           const float* __restrict__ w1_) {
    int i = blockIdx.x * 256 + threadIdx.x;
    if (i < EW_TOT) {
        float v;
        if (i < 4096)        { int o = i >> 6, c = i & 63; v = w2_[o * 128 + c]; }
        else if (i < 8192)   { int j = i - 4096, o = j >> 6, c = j & 63;
                               v = w2_[o * 128 + 64 + c] - w2_[o * 128 + c]; }
        else if (i < 16384)  { int j = i - 8192, o = j >> 6, c = j & 63; v = w3_[o * 128 + c]; }
        else if (i < 24576)  { int j = i - 16384, o = j >> 6, c = j & 63;
                               v = w3_[o * 128 + 64 + c] - w3_[o * 128 + c]; }
        else if (i < 57344)  { int j = i - 24576, o = j >> 7, c = j & 127; v = w4_[o * 256 + c]; }
        else                 { int j = i - 57344, o = j >> 7, c = j & 127;
                               v = w4_[o * 256 + 128 + c] - w4_[o * 256 + c]; }
        __nv_bfloat16 h = __float2bfloat16(v);
        g_ewh[i] = h;
        g_ewl[i] = __float2bfloat16(v - __bfloat162float(h));
        return;
    }
    i -= EW_TOT;
    if (i < TW_TOT) {
        float v = (i < TE1) ? lw[i] : ((i < TE2) ? e1[i - TE1] : e2[i - TE2]);
        __nv_bfloat16 h = __float2bfloat16(v);
        g_twh[i] = h;
        g_twl[i] = __float2bfloat16(v - __bfloat162float(h));
        return;
    }
    i -= TW_TOT;
    if (i < 192) {
        int o = i / 3, c = i - o * 3;
        float wd = w1_[o * 6 + c];
        g_wd[i] = wd;
        g_w2[i] = w1_[o * 6 + 3 + c] - wd;
        return;
    }
    i -= 192;
    if (i < 7168) { g_sum[i] = 0.f; g_sumsq[i] = 0.f; }
}
#define MEGAN (EW_TOT + TW_TOT + 192 + 7168)

// ---------------- valid dtype detection + accessor ----------------
__global__ void k_detect(const void* v) {
    const int nwords = (P_ * K_) / 4;
    const unsigned int* w = (const unsigned int*)v;
    __shared__ int s_not01, s_f32;
    if (threadIdx.x == 0) { s_not01 = 0; s_f32 = 0; }
    __syncthreads();
    int not01 = 0, f32 = 0;
    for (int i = threadIdx.x; i < nwords; i += blockDim.x) {
        unsigned int u = w[i];
        if (u > 1u) not01 = 1;
        if (u == 0x3F800000u) f32 = 1;
    }
    if (not01) atomicOr(&s_not01, 1);
    if (f32)   atomicOr(&s_f32, 1);
    __syncthreads();
    if (threadIdx.x == 0) {
        g_vmode = (!s_not01) ? 0 : (s_f32 ? 2 : 1);
        g_totvalid = 0;
        g_okcnt = 0;
    }
}
__device__ __forceinline__ int valid_at(const void* v, int i) {
    int m = g_vmode;
    if (m == 0) return ((const int*)v)[i] != 0;
    if (m == 1) return ((const uint8_t*)v)[i] != 0;
    return ((const float*)v)[i] != 0.0f;
}

// count valid + ok flags + transpose x, one launch
__global__ void k_count_transpose(const void* __restrict__ valid, const float* __restrict__ x) {
    int p = blockIdx.x * 256 + threadIdx.x;
    int c = 0;
    #pragma unroll
    for (int k = 0; k < K_; k++) c += valid_at(valid, p * K_ + k);
    g_cnt[p] = c;
    int okf = (c >= 1) ? 1 : 0;
    g_ok[p] = (uint8_t)okf;
    int tot = c, okc = okf;
    for (int d = 16; d; d >>= 1) {
        tot += __shfl_xor_sync(0xffffffffu, tot, d);
        okc += __shfl_xor_sync(0xffffffffu, okc, d);
    }
    if ((threadIdx.x & 31) == 0) {
        atomicAdd(&g_totvalid, tot);
        atomicAdd(&g_okcnt, okc);
    }
    int b = p >> 11, n = p & (N_ - 1);
    #pragma unroll
    for (int cc = 0; cc < 3; cc++)
        g_xt0[p * 3 + cc] = x[(b * 3 + cc) * N_ + n];
}

// BN(+lrelu) via pre-BN max/min, ok-gated, BN params inline; vectorized x4
__global__ void k_edge_pass2(int O, int off, int base,
                             const float* __restrict__ gamma, const float* __restrict__ beta) {
    int i4 = (blockIdx.x * 256 + threadIdx.x) * 4;
    if (i4 >= P_ * O) return;
    int p = i4 / O, o = i4 & (O - 1);
    float a[4], b[4];
    bn_ab4(o, base, (float)g_totvalid, gamma, beta, a, b);
    float4 mx4 = *(const float4*)(g_mx + i4);
    float4 mn4 = *(const float4*)(g_mn + i4);
    float mxs[4] = {mx4.x, mx4.y, mx4.z, mx4.w};
    float mns[4] = {mn4.x, mn4.y, mn4.z, mn4.w};
    bool zero = (g_cnt[p] < 1);
    float hv[4];
    __nv_bfloat16 hh[4], ll[4];
    #pragma unroll
    for (int j = 0; j < 4; j++) {
        float v = (a[j] >= 0.f) ? mxs[j] : mns[j];
        float h = a[j] * v + b[j];
        h = (h >= 0.f) ? h : 0.2f * h;
        if (zero) h = 0.f;
        hv[j] = h;
        hh[j] = __float2bfloat16(h);
        ll[j] = __float2bfloat16(h - __bfloat162float(hh[j]));
    }
    int di = p * 512 + off + o;
    *(float4*)(g_xcat + di) = make_float4(hv[0], hv[1], hv[2], hv[3]);
    *(uint2*)(g_xch + di) = *(uint2*)hh;
    *(uint2*)(g_xcl + di) = *(uint2*)ll;
}

// BN+lrelu (params inline, ok-count) on point-major fp32, emit bf16 hi/lo; vectorized x4
__global__ void k_convert(const float* __restrict__ Y, int O, int base,
                          const float* __restrict__ gamma, const float* __restrict__ beta,
                          __nv_bfloat16* __restrict__ H, __nv_bfloat16* __restrict__ L) {
    int i4 = (blockIdx.x * 256 + threadIdx.x) * 4;
    if (i4 >= P_ * O) return;
    int o = i4 & (O - 1);
    float a[4], b[4];
    bn_ab4(o, base, (float)g_okcnt, gamma, beta, a, b);
    float4 y4 = *(const float4*)(Y + i4);
    float ys[4] = {y4.x, y4.y, y4.z, y4.w};
    __nv_bfloat16 hh[4], ll[4];
    #pragma unroll
    for (int j = 0; j < 4; j++) {
        float y = a[j] * ys[j] + b[j];
        y = (y >= 0.f) ? y : 0.2f * y;
        hh[j] = __float2bfloat16(y);
        ll[j] = __float2bfloat16(y - __bfloat162float(hh[j]));
    }
    *(uint2*)(H + i4) = *(uint2*)hh;
    *(uint2*)(L + i4) = *(uint2*)ll;
}

// ---------------- scalar GEMM (blk0 cpart) ----------------
__global__ __launch_bounds__(256)
void gemm_pt3(const float* __restrict__ X, const float* __restrict__ W,
              int O, int C, float* __restrict__ Y) {
    const int tid = threadIdx.x, tx = tid & 15, ty = tid >> 4;
    const int p0 = blockIdx.x * 64;
    __shared__ float sW[128 * 17];
    __shared__ float sX[16 * 64];
    float acc[8][4];
    #pragma unroll
    for (int r = 0; r < 8; r++)
        #pragma unroll
        for (int j = 0; j < 4; j++) acc[r][j] = 0.f;

    for (int c0 = 0; c0 < C; c0 += 16) {
        #pragma unroll
        for (int e = tid; e < 128 * 16; e += 256) {
            int ol = e >> 4, cc = e & 15;
            int c = c0 + cc;
            sW[ol * 17 + cc] = (ol < O && c < C) ? W[ol * C + c] : 0.f;
        }
        #pragma unroll
        for (int e = tid; e < 16 * 64; e += 256) {
            int col = e >> 4, cc = e & 15;
            int c = c0 + cc;
            sX[cc * 64 + col] = (c < C) ? X[(p0 + col) * C + c] : 0.f;
        }
        __syncthreads();
        #pragma unroll
        for (int cc = 0; cc < 16; cc++) {
            float fv[4], wv[8];
            #pragma unroll
            for (int j = 0; j < 4; j++) fv[j] = sX[cc * 64 + tx + 16 * j];
            #pragma unroll
            for (int r = 0; r < 8; r++) wv[r] = sW[(ty + 16 * r) * 17 + cc];
            #pragma unroll
            for (int r = 0; r < 8; r++)
                #pragma unroll
                for (int j = 0; j < 4; j++) acc[r][j] += wv[r] * fv[j];
        }
        __syncthreads();
    }
    #pragma unroll
    for (int r = 0; r < 8; r++) {
        int o = ty + 16 * r;
        if (o >= O) break;
        #pragma unroll
        for (int j = 0; j < 4; j++)
            Y[(p0 + tx + 16 * j) * 256 + o] = acc[r][j];
    }
}

// ---------------- final out GEMM: fused input-BN, transposed output ----------------
__global__ __launch_bounds__(256)
void k_gemm_out(const float* __restrict__ X, const float* __restrict__ W,
                const float* __restrict__ bias, int base,
                const float* __restrict__ gamma, const float* __restrict__ beta,
                float* __restrict__ Y) {
    const int O = 32, C = 128;
    const int tid = threadIdx.x, tx = tid & 15, ty = tid >> 4;
    const int p0 = blockIdx.x * 64;
    __shared__ float sW[32 * 17];
    __shared__ float sX[16 * 64];
    float acc[2][4];
    #pragma unroll
    for (int r = 0; r < 2; r++)
        #pragma unroll
        for (int j = 0; j < 4; j++) acc[r][j] = 0.f;

    const float cnt = (float)g_okcnt;
    for (int c0 = 0; c0 < C; c0 += 16) {
        for (int e = tid; e < 32 * 16; e += 256) {
            int ol = e >> 4, cc = e & 15;
            sW[ol * 17 + cc] = W[ol * C + c0 + cc];
        }
        #pragma unroll
        for (int e = tid; e < 16 * 64; e += 256) {
            int col = e >> 4, cc = e & 15;
            int c = c0 + cc;
            float a, b;
            bn_ab(c, base, cnt, gamma, beta, a, b);
            float y = a * X[(p0 + col) * C + c] + b;
            sX[cc * 64 + col] = (y >= 0.f) ? y : 0.2f * y;
        }
        __syncthreads();
        #pragma unroll
        for (int cc = 0; cc < 16; cc++) {
            float fv[4], wv[2];
            #pragma unroll
            for (int j = 0; j < 4; j++) fv[j] = sX[cc * 64 + tx + 16 * j];
            #pragma unroll
            for (int r = 0; r < 2; r++) wv[r] = sW[(ty + 16 * r) * 17 + cc];
            #pragma unroll
            for (int r = 0; r < 2; r++)
                #pragma unroll
                for (int j = 0; j < 4; j++) acc[r][j] += wv[r] * fv[j];
        }
        __syncthreads();
    }
    #pragma unroll
    for (int r = 0; r < 2; r++) {
        int o = ty + 16 * r;
        float bs = bias[o];
        #pragma unroll
        for (int j = 0; j < 4; j++) {
            int p = p0 + tx + 16 * j;
            int b = p >> 11, n = p & (N_ - 1);
            Y[(b * O + o) * N_ + n] = acc[r][j] + bs;
        }
    }
}

// ---------------- scalar gather edge GEMM (blk0, C=3) ----------------
__global__ __launch_bounds__(256)
void edge_gemm0(const int* __restrict__ idx, const void* __restrict__ valid) {
    const int C = 3, O = 64;
    const int tid = threadIdx.x, tx = tid & 15, ty = tid >> 4;
    const int p0 = blockIdx.x * 4;
    __shared__ float sW[64 * 17];
    __shared__ float sF[16 * 80];
    __shared__ int sSrc[80];
    __shared__ uint8_t sVal[80];
    __shared__ float sC[4 * 64];

    if (tid < 80) {
        int pt = tid / 20, k = tid - pt * 20;
        int p = p0 + pt, b = p >> 11;
        sSrc[tid] = (b << 11) + idx[p * K_ + k];
        sVal[tid] = (uint8_t)valid_at(valid, p * K_ + k);
    }
    if (tid < 256) {
        int pt = tid >> 6, ol = tid & 63;
        sC[tid] = g_cpart[(p0 + pt) * 256 + ol];
    }
    for (int e = tid; e < 64 * 16; e += 256) {
        int ol = e >> 4, cc = e & 15;
        sW[ol * 17 + cc] = (cc < C) ? g_wd[ol * C + cc] : 0.f;
    }
    __syncthreads();
    for (int e = tid; e < 16 * 80; e += 256) {
        int col = e >> 4, cc = e & 15;
        sF[cc * 80 + col] = (cc < C) ? g_xt0[sSrc[col] * 3 + cc] : 0.f;
    }
    __syncthreads();

    float acc[4][5];
    #pragma unroll
    for (int r = 0; r < 4; r++)
        #pragma unroll
        for (int j = 0; j < 5; j++) acc[r][j] = 0.f;
    #pragma unroll
    for (int cc = 0; cc < 3; cc++) {
        float fv[5], wv[4];
        #pragma unroll
        for (int j = 0; j < 5; j++) fv[j] = sF[cc * 80 + tx * 5 + j];
        #pragma unroll
        for (int r = 0; r < 4; r++) wv[r] = sW[(ty + 16 * r) * 17 + cc];
        #pragma unroll
        for (int r = 0; r < 4; r++)
            #pragma unroll
            for (int j = 0; j < 5; j++) acc[r][j] += wv[r] * fv[j];
    }

    const int myPt = tx >> 2;
    const int cbase = tx * 5;
    #pragma unroll
    for (int r = 0; r < 4; r++) {
        int o = ty + 16 * r;
        float cp = sC[myPt * 64 + o];
        float s = 0.f, s2 = 0.f;
        float vmx = -INFINITY, vmn = INFINITY;
        #pragma unroll
        for (int j = 0; j < 5; j++) {
            int col = cbase + j;
            float h = acc[r][j] + cp;
            if (sVal[col]) {
                s += h; s2 += h * h;
                vmx = fmaxf(vmx, h);
                vmn = fminf(vmn, h);
            }
        }
        for (int d = 1; d < 16; d <<= 1) {
            s  += __shfl_xor_sync(0xffffffffu, s,  d);
            s2 += __shfl_xor_sync(0xffffffffu, s2, d);
        }
        for (int d = 1; d < 4; d <<= 1) {
            vmx = fmaxf(vmx, __shfl_xor_sync(0xffffffffu, vmx, d));
            vmn = fminf(vmn, __shfl_xor_sync(0xffffffffu, vmn, d));
        }
        if (tx == 0) {
            atomicAdd(&g_sum[o], s);
            atomicAdd(&g_sumsq[o], s2);
        }
        if ((tx & 3) == 0) {
            int p = p0 + myPt;
            g_mx[p * O + o] = vmx;
            g_mn[p * O + o] = vmn;
        }
    }
}

// ---------------- warp-MMA dense GEMM, MT in {2,4}, SINGLE buffer, occ 2 ----------------
// smem: WH[0, MT*4K) WL[MT*4K, MT*8K) XH[MT*8K, +16K) XL[+16K, +32K)
template<bool STATS, int MT>
__global__ __launch_bounds__(256, 2)
void tgemm_tail(const __nv_bfloat16* __restrict__ Xhi, const __nv_bfloat16* __restrict__ Xlo,
                const __nv_bfloat16* __restrict__ Wh, const __nv_bfloat16* __restrict__ Wl,
                int ldx, int xoff, int C, int ldout, int base,
                const float* __restrict__ bias, float* __restrict__ Y) {
    extern __shared__ __align__(1024) unsigned char dsm[];
    __shared__ uint8_t sOk[128];
    const int tid = threadIdx.x, lane = tid & 31, wid = tid >> 5;
    const int wm = wid >> 2, wn = wid & 3;
    const uint32_t OFF_WL = MT * 4096u, OFF_XH = MT * 8192u, OFF_XL = MT * 8192u + 16384u;
    const int p0 = blockIdx.x * 128, o0 = blockIdx.y * (MT * 32);
    const uint32_t sb = s2u(dsm);
    if (STATS && tid < 128) sOk[tid] = g_ok[p0 + tid];

    const int lr = lane & 7, g = lane >> 3;
    const uint32_t xorv = (uint32_t)lr * 16;
    const uint32_t aRow = (uint32_t)(wm * (MT * 16) + (g & 1) * 8 + lr) * 128;
    const uint32_t aSeg = (uint32_t)(g >> 1) * 16;
    const uint32_t bRow = (uint32_t)(wn * 32 + lr) * 128;
    const uint32_t bSeg = (uint32_t)(g & 1) * 16;

    float acc[MT][4][4];
    #pragma unroll
    for (int mi = 0; mi < MT; mi++)
        #pragma unroll
        for (int ni = 0; ni < 4; ni++)
            #pragma unroll
            for (int j = 0; j < 4; j++) acc[mi][ni][j] = 0.f;

    const int nch = C >> 6;
    // prefetch chunk 0
    {
        #pragma unroll
        for (int e = tid; e < MT * 256; e += 256) {
            int row = e >> 3, q = e & 7;
            uint32_t dst = SWZ((uint32_t)(row * 128 + q * 16));
            cpa16(sb + dst,          Wh + (size_t)(o0 + row) * C + q * 8);
            cpa16(sb + OFF_WL + dst, Wl + (size_t)(o0 + row) * C + q * 8);
        }
        #pragma unroll
        for (int e = tid; e < 1024; e += 256) {
            int row = e >> 3, q = e & 7;
            uint32_t dst = SWZ((uint32_t)(row * 128 + q * 16));
            cpa16(sb + OFF_XH + dst, Xhi + (size_t)(p0 + row) * ldx + xoff + q * 8);
            cpa16(sb + OFF_XL + dst, Xlo + (size_t)(p0 + row) * ldx + xoff + q * 8);
        }
        CPA_COMMIT();
    }
    for (int ch = 0; ch < nch; ch++) {
        CPA_WAIT0();
        __syncthreads();
        #pragma unroll
        for (int s = 0; s < 4; s++) {
            const uint32_t ofsA = ((uint32_t)(s * 32) + aSeg) ^ xorv;
            const uint32_t ofsB = ((uint32_t)(s * 32) + bSeg) ^ xorv;
            uint32_t ah[MT][4], al[MT][4];
            #pragma unroll
            for (int mi = 0; mi < MT; mi++) {
                ldsm4(ah[mi], sb + aRow + mi * 2048 + ofsA);
                ldsm4(al[mi], sb + OFF_WL + aRow + mi * 2048 + ofsA);
            }
            #pragma unroll
            for (int ni = 0; ni < 4; ni++) {
                uint32_t bh[2], bl[2];
                ldsm2(bh, sb + OFF_XH + bRow + ni * 1024 + ofsB);
                ldsm2(bl, sb + OFF_XL + bRow + ni * 1024 + ofsB);
                #pragma unroll
                for (int mi = 0; mi < MT; mi++) {
                    mma16816(acc[mi][ni], ah[mi], bh);
                    mma16816(acc[mi][ni], ah[mi], bl);
                    mma16816(acc[mi][ni], al[mi], bh);
                }
            }
        }
        __syncthreads();
        if (ch + 1 < nch) {
            const int c0 = (ch + 1) << 6;
            #pragma unroll
            for (int e = tid; e < MT * 256; e += 256) {
                int row = e >> 3, q = e & 7;
                uint32_t dst = SWZ((uint32_t)(row * 128 + q * 16));
                cpa16(sb + dst,          Wh + (size_t)(o0 + row) * C + c0 + q * 8);
                cpa16(sb + OFF_WL + dst, Wl + (size_t)(o0 + row) * C + c0 + q * 8);
            }
            #pragma unroll
            for (int e = tid; e < 1024; e += 256) {
                int row = e >> 3, q = e & 7;
                uint32_t dst = SWZ((uint32_t)(row * 128 + q * 16));
                cpa16(sb + OFF_XH + dst, Xhi + (size_t)(p0 + row) * ldx + xoff + c0 + q * 8);
                cpa16(sb + OFF_XL + dst, Xlo + (size_t)(p0 + row) * ldx + xoff + c0 + q * 8);
            }
            CPA_COMMIT();
        }
    }

    // epilogue: bias + (masked stats) + transpose (in point-slabs) + coalesced store
    const int lrow = lane >> 2, lcol2 = (lane & 3) * 2;
    const int STR = MT * 32 + 4;
    const int NSLAB = (MT == 4) ? 2 : 1;
    const int PPS = 128 / NSLAB;
    float bias_r[MT][2];
    #pragma unroll
    for (int mi = 0; mi < MT; mi++)
        #pragma unroll
        for (int h = 0; h < 2; h++) {
            int o = o0 + wm * (MT * 16) + mi * 16 + h * 8 + lrow;
            bias_r[mi][h] = (bias != nullptr) ? bias[o] : 0.f;
        }
    float st[MT][2], st2[MT][2];
    #pragma unroll
    for (int mi = 0; mi < MT; mi++)
        #pragma unroll
        for (int h = 0; h < 2; h++) { st[mi][h] = 0.f; st2[mi][h] = 0.f; }

    float* sT = (float*)dsm;
    #pragma unroll
    for (int sl = 0; sl < NSLAB; sl++) {
        __syncthreads();
        #pragma unroll
        for (int mi = 0; mi < MT; mi++) {
            const int ro = wm * (MT * 16) + mi * 16 + lrow;
            #pragma unroll
            for (int ni = 0; ni < 4; ni++) {
                const int cp0 = wn * 32 + ni * 8 + lcol2;
                if (cp0 < sl * PPS || cp0 >= (sl + 1) * PPS) continue;
                float y00 = acc[mi][ni][0] + bias_r[mi][0];
                float y01 = acc[mi][ni][1] + bias_r[mi][0];
                float y10 = acc[mi][ni][2] + bias_r[mi][1];
                float y11 = acc[mi][ni][3] + bias_r[mi][1];
                if (STATS) {
                    if (sOk[cp0])     { st[mi][0] += y00; st2[mi][0] += y00 * y00;
                                        st[mi][1] += y10; st2[mi][1] += y10 * y10; }
                    if (sOk[cp0 + 1]) { st[mi][0] += y01; st2[mi][0] += y01 * y01;
                                        st[mi][1] += y11; st2[mi][1] += y11 * y11; }
                }
                int lp = cp0 - sl * PPS;
                sT[lp * STR + ro]           = y00;
                sT[(lp + 1) * STR + ro]     = y01;
                sT[lp * STR + ro + 8]       = y10;
                sT[(lp + 1) * STR + ro + 8] = y11;
            }
        }
        __syncthreads();
        // copy slab out: PPS points x MT*32 o
        const int F4PP = MT * 8;   // float4 per point
        #pragma unroll
        for (int v = 0; v < PPS * F4PP / 256; v++) {
            int f4 = tid + v * 256;
            int p = f4 / F4PP, sg = f4 % F4PP;
            float4 val = *(const float4*)(sT + p * STR + sg * 4);
            *(float4*)(Y + (size_t)(p0 + sl * PPS + p) * ldout + o0 + sg * 4) = val;
        }
    }
    if (STATS) {
        #pragma unroll
        for (int mi = 0; mi < MT; mi++)
            #pragma unroll
            for (int h = 0; h < 2; h++) {
                float v = st[mi][h], v2 = st2[mi][h];
                v  += __shfl_xor_sync(0xffffffffu, v, 1);
                v  += __shfl_xor_sync(0xffffffffu, v, 2);
                v2 += __shfl_xor_sync(0xffffffffu, v2, 1);
                v2 += __shfl_xor_sync(0xffffffffu, v2, 2);
                if ((lane & 3) == 0) {
                    int o = o0 + wm * (MT * 16) + mi * 16 + h * 8 + lrow;
                    atomicAdd(&g_sum[base + o], v);
                    atomicAdd(&g_sumsq[base + o], v2);
                }
            }
    }
}

// ---------------- warp-MMA edge GEMM, MT=2, single-buffer, NCH chunks ----------------
// smem 57344: WH[0,8K) WL[8K,16K) BH[16K,36.5K) BL[36.5K,56.5K)
template<int NCH>
__global__ __launch_bounds__(256, 2)
void tgemm_edge(int xoff, int O, int base,
                const __nv_bfloat16* __restrict__ Wh, const __nv_bfloat16* __restrict__ Wl,
                const int* __restrict__ idx, const void* __restrict__ valid) {
    const int MT = 2;
    extern __shared__ __align__(1024) unsigned char dsm[];
    __shared__ int sSrc[160];
    __shared__ uint8_t sVal[160];
    const int tid = threadIdx.x, lane = tid & 31, wid = tid >> 5;
    const int wm = wid >> 2, wn = wid & 3;
    const uint32_t OFF_WL = 8192u, OFF_BH = 16384u, OFF_BL = 36864u;
    const int C = NCH * 64;
    const int p0 = blockIdx.x * 8, o0 = blockIdx.y * 64;
    const uint32_t sb = s2u(dsm);

    if (tid < 160) {
        int p = p0 + tid / 20, k = tid % 20;
        int b = p >> 11;
        sSrc[tid] = (b << 11) + idx[p * K_ + k];
        sVal[tid] = (uint8_t)valid_at(valid, p * K_ + k);
    }
    __syncthreads();

    const int lr = lane & 7, g = lane >> 3;
    const uint32_t xorv = (uint32_t)lr * 16;
    const uint32_t aRow = (uint32_t)(wm * 32 + (g & 1) * 8 + lr) * 128;
    const uint32_t aSeg = (uint32_t)(g >> 1) * 16;
    const uint32_t bRow = (uint32_t)(wn * 40 + lr) * 128;
    const uint32_t bSeg = (uint32_t)(g & 1) * 16;

    float acc[MT][5][4];
    #pragma unroll
    for (int mi = 0; mi < MT; mi++)
        #pragma unroll
        for (int ni = 0; ni < 5; ni++)
            #pragma unroll
            for (int j = 0; j < 4; j++) acc[mi][ni][j] = 0.f;

    {
        #pragma unroll
        for (int e = tid; e < 512; e += 256) {
            int row = e >> 3, q = e & 7;
            uint32_t dst = SWZ((uint32_t)(row * 128 + q * 16));
            cpa16(sb + dst,          Wh + (size_t)(o0 + row) * C + q * 8);
            cpa16(sb + OFF_WL + dst, Wl + (size_t)(o0 + row) * C + q * 8);
        }
        for (int e = tid; e < 1280; e += 256) {
            int row = e >> 3, q = e & 7;
            uint32_t dst = SWZ((uint32_t)(row * 128 + q * 16));
            size_t src = (size_t)sSrc[row] * 512 + xoff + q * 8;
            cpa16(sb + OFF_BH + dst, g_xch + src);
            cpa16(sb + OFF_BL + dst, g_xcl + src);
        }
        CPA_COMMIT();
    }
    #pragma unroll
    for (int ch = 0; ch < NCH; ch++) {
        CPA_WAIT0();
        __syncthreads();
        #pragma unroll
        for (int s = 0; s < 4; s++) {
            const uint32_t ofsA = ((uint32_t)(s * 32) + aSeg) ^ xorv;
            const uint32_t ofsB = ((uint32_t)(s * 32) + bSeg) ^ xorv;
            uint32_t ah[MT][4], al[MT][4];
            #pragma unroll
            for (int mi = 0; mi < MT; mi++) {
                ldsm4(ah[mi], sb + aRow + mi * 2048 + ofsA);
                ldsm4(al[mi], sb + OFF_WL + aRow + mi * 2048 + ofsA);
            }
            #pragma unroll
            for (int ni = 0; ni < 5; ni++) {
                uint32_t bh[2], bl[2];
                ldsm2(bh, sb + OFF_BH + bRow + ni * 1024 + ofsB);
                ldsm2(bl, sb + OFF_BL + bRow + ni * 1024 + ofsB);
                #pragma unroll
                for (int mi = 0; mi < MT; mi++) {
                    mma16816(acc[mi][ni], ah[mi], bh);
                    mma16816(acc[mi][ni], ah[mi], bl);
                    mma16816(acc[mi][ni], al[mi], bh);
                }
            }
        }
        __syncthreads();
        if (ch + 1 < NCH) {
            const int c0 = (ch + 1) << 6;
            #pragma unroll
            for (int e = tid; e < 512; e += 256) {
                int row = e >> 3, q = e & 7;
                uint32_t dst = SWZ((uint32_t)(row * 128 + q * 16));
                cpa16(sb + dst,          Wh + (size_t)(o0 + row) * C + c0 + q * 8);
                cpa16(sb + OFF_WL + dst, Wl + (size_t)(o0 + row) * C + c0 + q * 8);
            }
            for (int e = tid; e < 1280; e += 256) {
                int row = e >> 3, q = e & 7;
                uint32_t dst = SWZ((uint32_t)(row * 128 + q * 16));
                size_t src = (size_t)sSrc[row] * 512 + xoff + c0 + q * 8;
                cpa16(sb + OFF_BH + dst, g_xch + src);
                cpa16(sb + OFF_BL + dst, g_xcl + src);
            }
            CPA_COMMIT();
        }
    }

    const int lrow = lane >> 2, lcol2 = (lane & 3) * 2;
    float cp[MT][2][2];
    #pragma unroll
    for (int mi = 0; mi < MT; mi++)
        #pragma unroll
        for (int h = 0; h < 2; h++)
            #pragma unroll
            for (int pt = 0; pt < 2; pt++) {
                int o = o0 + wm * 32 + mi * 16 + h * 8 + lrow;
                cp[mi][h][pt] = g_cpart[(size_t)(p0 + wn * 2 + pt) * 256 + o];
            }
    float st[MT][2], st2[MT][2];
    float mxv[MT][2][2], mnv[MT][2][2];
    #pragma unroll
    for (int mi = 0; mi < MT; mi++)
        #pragma unroll
        for (int h = 0; h < 2; h++) {
            st[mi][h] = 0.f; st2[mi][h] = 0.f;
            #pragma unroll
            for (int pt = 0; pt < 2; pt++) { mxv[mi][h][pt] = -INFINITY; mnv[mi][h][pt] = INFINITY; }
        }
    #pragma unroll
    for (int ni = 0; ni < 5; ni++) {
        const int cl = ni * 8 + lcol2;
        const int pt = (cl >= 20) ? 1 : 0;
        const int col = wn * 40 + cl;
        const bool v0 = sVal[col] != 0, v1 = sVal[col + 1] != 0;
        #pragma unroll
        for (int mi = 0; mi < MT; mi++) {
            float h00 = acc[mi][ni][0] + cp[mi][0][pt];
            float h01 = acc[mi][ni][1] + cp[mi][0][pt];
            float h10 = acc[mi][ni][2] + cp[mi][1][pt];
            float h11 = acc[mi][ni][3] + cp[mi][1][pt];
            if (v0) {
                st[mi][0] += h00; st2[mi][0] += h00 * h00;
                st[mi][1] += h10; st2[mi][1] += h10 * h10;
                mxv[mi][0][pt] = fmaxf(mxv[mi][0][pt], h00);
                mnv[mi][0][pt] = fminf(mnv[mi][0][pt], h00);
                mxv[mi][1][pt] = fmaxf(mxv[mi][1][pt], h10);
                mnv[mi][1][pt] = fminf(mnv[mi][1][pt], h10);
            }
            if (v1) {
                st[mi][0] += h01; st2[mi][0] += h01 * h01;
                st[mi][1] += h11; st2[mi][1] += h11 * h11;
                mxv[mi][0][pt] = fmaxf(mxv[mi][0][pt], h01);
                mnv[mi][0][pt] = fminf(mnv[mi][0][pt], h01);
                mxv[mi][1][pt] = fmaxf(mxv[mi][1][pt], h11);
                mnv[mi][1][pt] = fminf(mnv[mi][1][pt], h11);
            }
        }
    }
    #pragma unroll
    for (int mi = 0; mi < MT; mi++)
        #pragma unroll
        for (int h = 0; h < 2; h++) {
            float v = st[mi][h], v2 = st2[mi][h];
            v  += __shfl_xor_sync(0xffffffffu, v, 1);
            v  += __shfl_xor_sync(0xffffffffu, v, 2);
            v2 += __shfl_xor_sync(0xffffffffu, v2, 1);
            v2 += __shfl_xor_sync(0xffffffffu, v2, 2);
            float mxr[2], mnr[2];
            #pragma unroll
            for (int pt = 0; pt < 2; pt++) {
                float a = mxv[mi][h][pt], b = mnv[mi][h][pt];
                a = fmaxf(a, __shfl_xor_sync(0xffffffffu, a, 1));
                a = fmaxf(a, __shfl_xor_sync(0xffffffffu, a, 2));
                b = fminf(b, __shfl_xor_sync(0xffffffffu, b, 1));
                b = fminf(b, __shfl_xor_sync(0xffffffffu, b, 2));
                mxr[pt] = a; mnr[pt] = b;
            }
            if ((lane & 3) == 0) {
                int o = o0 + wm * 32 + mi * 16 + h * 8 + lrow;
                atomicAdd(&g_sum[base + o], v);
                atomicAdd(&g_sumsq[base + o], v2);
                #pragma unroll
                for (int pt = 0; pt < 2; pt++) {
                    int p = p0 + wn * 2 + pt;
                    g_mx[(size_t)p * O + o] = mxr[pt];
                    g_mn[(size_t)p * O + o] = mnr[pt];
                }
            }
        }
}

// ---------------- host orchestration ----------------
extern "C" void kernel_launch(void* const* d_in, const int* in_sizes, int n_in,
                              void* d_out, int out_size) {
    const float*   x      = (const float*)d_in[0];
    const int*     idx    = (const int*)d_in[1];
    const void*    valid  = (const void*)d_in[2];
    const float* enc_w1   = (const float*)d_in[3];
    const float* enc_g1   = (const float*)d_in[4];
    const float* enc_b1   = (const float*)d_in[5];
    const float* enc_w2   = (const float*)d_in[6];
    const float* enc_g2   = (const float*)d_in[7];
    const float* enc_b2   = (const float*)d_in[8];
    const float* enc_w3   = (const float*)d_in[9];
    const float* enc_g3   = (const float*)d_in[10];
    const float* enc_b3   = (const float*)d_in[11];
    const float* enc_w4   = (const float*)d_in[12];
    const float* enc_g4   = (const float*)d_in[13];
    const float* enc_b4   = (const float*)d_in[14];
    const float* last_w   = (const float*)d_in[15];
    const float* last_g   = (const float*)d_in[16];
    const float* last_b   = (const float*)d_in[17];
    const float* emb_w1   = (const float*)d_in[18];
    const float* emb_bias1= (const float*)d_in[19];
    const float* emb_g1   = (const float*)d_in[20];
    const float* emb_b1   = (const float*)d_in[21];
    const float* emb_w2   = (const float*)d_in[22];
    const float* emb_bias2= (const float*)d_in[23];
    const float* emb_g2   = (const float*)d_in[24];
    const float* emb_b2   = (const float*)d_in[25];
    const float* out_w    = (const float*)d_in[26];
    const float* out_bias = (const float*)d_in[27];

    cudaFuncSetAttribute(tgemm_tail<false, 2>, cudaFuncAttributeMaxDynamicSharedMemorySize, 49152);
    cudaFuncSetAttribute(tgemm_tail<false, 4>, cudaFuncAttributeMaxDynamicSharedMemorySize, 65536);
    cudaFuncSetAttribute(tgemm_tail<true, 4>,  cudaFuncAttributeMaxDynamicSharedMemorySize, 65536);
    cudaFuncSetAttribute(tgemm_edge<1>, cudaFuncAttributeMaxDynamicSharedMemorySize, 57344);
    cudaFuncSetAttribute(tgemm_edge<2>, cudaFuncAttributeMaxDynamicSharedMemorySize, 57344);

    float *xt0p, *cpartp, *y1p, *y2p, *y3p, *w2p;
    __nv_bfloat16 *xchp, *xclp, *y1hp, *y1lp, *y2hp, *y2lp, *ewh, *ewl, *twh, *twl;
    cudaGetSymbolAddress((void**)&xt0p,  g_xt0);
    cudaGetSymbolAddress((void**)&cpartp,g_cpart);
    cudaGetSymbolAddress((void**)&y1p,   g_y1);
    cudaGetSymbolAddress((void**)&y2p,   g_y2);
    cudaGetSymbolAddress((void**)&y3p,   g_y3);
    cudaGetSymbolAddress((void**)&w2p,   g_w2);
    cudaGetSymbolAddress((void**)&xchp,  g_xch);
    cudaGetSymbolAddress((void**)&xclp,  g_xcl);
    cudaGetSymbolAddress((void**)&y1hp,  g_y1h);
    cudaGetSymbolAddress((void**)&y1lp,  g_y1l);
    cudaGetSymbolAddress((void**)&y2hp,  g_y2h);
    cudaGetSymbolAddress((void**)&y2lp,  g_y2l);
    cudaGetSymbolAddress((void**)&ewh,   g_ewh);
    cudaGetSymbolAddress((void**)&ewl,   g_ewl);
    cudaGetSymbolAddress((void**)&twh,   g_twh);
    cudaGetSymbolAddress((void**)&twl,   g_twl);

    k_megaprep<<<(MEGAN + 255) / 256, 256>>>(enc_w2, enc_w3, enc_w4, last_w,
                                             emb_w1, emb_w2, enc_w1);
    k_detect<<<1, 1024>>>(valid);
    k_count_transpose<<<P_ / 256, 256>>>(valid, x);

    // blk0 (scalar, C=3, O=64)
    gemm_pt3<<<P_ / 64, 256>>>(xt0p, w2p, 64, 3, cpartp);
    edge_gemm0<<<P_ / 4, 256>>>(idx, valid);
    k_edge_pass2<<<(P_ * 64 / 4 + 255) / 256, 256>>>(64, 0, 0, enc_g1, enc_b1);

    // blk1 (O=64, C=64)
    tgemm_tail<false, 2><<<dim3(P_ / 128, 1), 256, 49152>>>(
        xchp, xclp, ewh + EW1C, ewl + EW1C, 512, 0, 64, 256, 0, nullptr, cpartp);
    tgemm_edge<1><<<dim3(P_ / 8, 1), 256, 57344>>>(
        0, 64, 1024, ewh + EW1D, ewl + EW1D, idx, valid);
    k_edge_pass2<<<(P_ * 64 / 4 + 255) / 256, 256>>>(64, 64, 1024, enc_g2, enc_b2);

    // blk2 (O=128, C=64)
    tgemm_tail<false, 4><<<dim3(P_ / 128, 1), 256, 65536>>>(
        xchp, xclp, ewh + EW2C, ewl + EW2C, 512, 64, 64, 256, 0, nullptr, cpartp);
    tgemm_edge<1><<<dim3(P_ / 8, 2), 256, 57344>>>(
        64, 128, 2048, ewh + EW2D, ewl + EW2D, idx, valid);
    k_edge_pass2<<<(P_ * 128 / 4 + 255) / 256, 256>>>(128, 128, 2048, enc_g3, enc_b3);

    // blk3 (O=256, C=128)
    tgemm_tail<false, 4><<<dim3(P_ / 128, 2), 256, 65536>>>(
        xchp, xclp, ewh + EW3C, ewl + EW3C, 512, 128, 128, 256, 0, nullptr, cpartp);
    tgemm_edge<2><<<dim3(P_ / 8, 4), 256, 57344>>>(
        128, 256, 3072, ewh + EW3D, ewl + EW3D, idx, valid);
    k_edge_pass2<<<(P_ * 256 / 4 + 255) / 256, 256>>>(256, 256, 3072, enc_g4, enc_b4);

    // tail
    tgemm_tail<true, 4><<<dim3(P_ / 128, 8), 256, 65536>>>(
        xchp, xclp, twh + TL, twl + TL, 512, 0, 512, 1024, 4096, nullptr, y1p);
    k_convert<<<(P_ * 1024 / 4 + 255) / 256, 256>>>(y1p, 1024, 4096, last_g, last_b, y1hp, y1lp);

    tgemm_tail<true, 4><<<dim3(P_ / 128, 4), 256, 65536>>>(
        y1hp, y1lp, twh + TE1, twl + TE1, 1024, 0, 1024, 512, 5120, emb_bias1, y2p);
    k_convert<<<(P_ * 512 / 4 + 255) / 256, 256>>>(y2p, 512, 5120, emb_g1, emb_b1, y2hp, y2lp);

    tgemm_tail<true, 4><<<dim3(P_ / 128, 1), 256, 65536>>>(
        y2hp, y2lp, twh + TE2, twl + TE2, 512, 0, 512, 128, 6144, emb_bias2, y3p);

    // out: fused input-BN scalar GEMM, transposed output
    k_gemm_out<<<P_ / 64, 256>>>(y3p, out_w, out_bias, 6144, emb_g2, emb_b2, (float*)d_out);
}